// round 9
// baseline (speedup 1.0000x reference)
#include <cuda_runtime.h>
#include <math.h>
#include <stdint.h>

#define SEQ 2048
#define HID 2048
#define NH 16
#define NKV 4
#define HD 128
#define QD (NH*HD)    /* 2048 */
#define KVD (NKV*HD)  /* 512  */

// Scratch (device globals: no allocations allowed)
__device__ float    g_q[SEQ*QD];
__device__ float    g_k[SEQ*KVD];            // fp32 K (pre-normrope)
__device__ uint32_t g_kt[SEQ*KVD];           // tf32 K (post-normrope)
__device__ uint32_t g_vt[KVD*SEQ];           // tf32 V, transposed [kvd][seq]
__device__ uint32_t g_o[SEQ*QD];             // attention output as tf32 bits
__device__ float2   g_rope[SEQ*64];          // (cos, sin) per (pos, freq)
// Pre-converted tf32-bit operands (prepass)
__device__ uint32_t g_xmu[SEQ*2*HID];        // [x | mu]  2048 x 4096
__device__ uint32_t g_wqc[QD*2*HID];         // [wq | wmq] 2048 x 4096
__device__ uint32_t g_wkc[KVD*2*HID];        // [wk | wmk]  512 x 4096
__device__ uint32_t g_wvc[KVD*2*HID];        // [wv | wmv]  512 x 4096
__device__ uint32_t g_wot[HID*QD];           // wo         2048 x 2048

// ---------------------------------------------------------------------------
// tf32 helpers (plain sm_80+ PTX — no sm_103a-gated instructions)
// ---------------------------------------------------------------------------
__device__ __forceinline__ uint32_t f2tf32(float x) {
    uint32_t r;
    asm("cvt.rna.tf32.f32 %0, %1;" : "=r"(r) : "f"(x));
    return r;
}

__device__ __forceinline__ void mma_tf32(float d[4], const uint32_t a[4], const uint32_t b[2]) {
    asm volatile(
        "mma.sync.aligned.m16n8k8.row.col.f32.tf32.tf32.f32 "
        "{%0,%1,%2,%3}, {%4,%5,%6,%7}, {%8,%9}, {%0,%1,%2,%3};"
        : "+f"(d[0]), "+f"(d[1]), "+f"(d[2]), "+f"(d[3])
        : "r"(a[0]), "r"(a[1]), "r"(a[2]), "r"(a[3]), "r"(b[0]), "r"(b[1]));
}

__device__ __forceinline__ void mma_tf32_2(float d[4], const uint32_t a[4],
                                           uint32_t b0, uint32_t b1) {
    asm volatile(
        "mma.sync.aligned.m16n8k8.row.col.f32.tf32.tf32.f32 "
        "{%0,%1,%2,%3}, {%4,%5,%6,%7}, {%8,%9}, {%0,%1,%2,%3};"
        : "+f"(d[0]), "+f"(d[1]), "+f"(d[2]), "+f"(d[3])
        : "r"(a[0]), "r"(a[1]), "r"(a[2]), "r"(a[3]), "r"(b0), "r"(b1));
}

#define CP_ASYNC_CG(dst_u32, src_ptr) \
    asm volatile("cp.async.cg.shared.global [%0], [%1], 16;" :: "r"(dst_u32), "l"(src_ptr) : "memory")
#define CP_COMMIT() asm volatile("cp.async.commit_group;" ::: "memory")
#define CP_WAIT1()  asm volatile("cp.async.wait_group 1;"  ::: "memory")
#define CP_WAIT0()  asm volatile("cp.async.wait_group 0;"  ::: "memory")

__device__ __forceinline__ uint32_t smem_u32(const void* p) {
    uint32_t a;
    asm("{ .reg .u64 t; cvta.to.shared.u64 t, %1; cvt.u32.u64 %0, t; }" : "=r"(a) : "l"(p));
    return a;
}

// ---------------------------------------------------------------------------
// Fused prepass: all fp32 -> tf32 conversions (+K-concat) in ONE kernel.
// Word segments: xmu[0,8M) wqc[8M,16M) wkc[16M,18M) wvc[18M,20M) wot[20M,24M)
// All cat segments have K=2048, K2=4096. Blocks never straddle segments.
// ---------------------------------------------------------------------------
__global__ __launch_bounds__(256) void cvt_all(
    uint32_t* __restrict__ xmu, uint32_t* __restrict__ wqc,
    uint32_t* __restrict__ wkc, uint32_t* __restrict__ wvc,
    uint32_t* __restrict__ wot,
    const float* __restrict__ x,  const float* __restrict__ mu,
    const float* __restrict__ wq, const float* __restrict__ wmq,
    const float* __restrict__ wk, const float* __restrict__ wmk,
    const float* __restrict__ wv, const float* __restrict__ wmv,
    const float* __restrict__ wo)
{
    long e = ((long)blockIdx.x * 256 + threadIdx.x) * 4;
    const float *A, *B; uint32_t* D; long off; bool cat = true;
    if (e < 8388608L)       { D = xmu; A = x;  B = mu;  off = e; }
    else if (e < 16777216L) { D = wqc; A = wq; B = wmq; off = e - 8388608L; }
    else if (e < 18874368L) { D = wkc; A = wk; B = wmk; off = e - 16777216L; }
    else if (e < 20971520L) { D = wvc; A = wv; B = wmv; off = e - 18874368L; }
    else                    { D = wot; A = wo; B = wo;  off = e - 20971520L; cat = false; }

    float4 v;
    if (cat) {
        int r = (int)(off >> 12);
        int c = (int)(off & 4095);
        const float* src = (c < 2048) ? (A + (size_t)r * 2048 + c)
                                      : (B + (size_t)r * 2048 + (c - 2048));
        v = *(const float4*)src;
    } else {
        v = *(const float4*)(A + off);
    }
    *(uint4*)(D + off) = make_uint4(f2tf32(v.x), f2tf32(v.y), f2tf32(v.z), f2tf32(v.w));
}

// RoPE (cos,sin) table: only 2048 x 64 unique angles exist.
__global__ __launch_bounds__(64) void rope_table(float2* __restrict__ tab)
{
    const int pos = blockIdx.x;
    const int f = threadIdx.x;
    float ang = (float)pos * powf(10000.0f, -(float)f * (1.0f / 64.0f));
    float sn, cs;
    sincosf(ang, &sn, &cs);
    tab[pos * 64 + f] = make_float2(cs, sn);
}

// ---------------------------------------------------------------------------
// cp.async 3-stage tf32 GEMM core (XOR swizzle). TRANSV epilogue writes tf32
// bits transposed into Ct[(col0g+cc)*SEQ + row0g + r].
// ---------------------------------------------------------------------------
#define STG_WORDS 4096            /* 128*32 */
#define STAGE_WORDS (2*STG_WORDS) /* A+B */

template<bool TRANSV>
__device__ __forceinline__ void gemm_core_async(
    const uint32_t* __restrict__ Ablk, const uint32_t* __restrict__ Bblk,
    float* __restrict__ Cblk, int ldc,
    uint32_t* __restrict__ Ct, int row0g, int col0g,
    int K, uint32_t* s)
{
    const uint32_t sbyte = smem_u32(s);
    const int tid = threadIdx.x;
    const int wid = tid >> 5, lane = tid & 31;
    const int g = lane >> 2, t = lane & 3;
    const int m0 = (wid >> 2) * 64;
    const int n0 = (wid & 3) * 32;

    const int lr = tid >> 3;
    const int ch = tid & 7;

    float acc[4][4][4];
#pragma unroll
    for (int i = 0; i < 4; ++i)
#pragma unroll
        for (int j = 0; j < 4; ++j)
#pragma unroll
            for (int q = 0; q < 4; ++q) acc[i][j][q] = 0.0f;

    const int nch = K >> 5;
    const int chsw = ch ^ (lr & 7);

    auto issue = [&](int st, int cc) {
        const uint32_t sa0 = sbyte + (uint32_t)(st * STAGE_WORDS) * 4u;
        const uint32_t sb0 = sa0 + STG_WORDS * 4u;
        const int kk = cc << 5;
#pragma unroll
        for (int i = 0; i < 4; ++i) {
            int r = lr + i * 32;
            uint32_t so = (uint32_t)(r * 32 + chsw * 4) * 4u;
            CP_ASYNC_CG(sa0 + so, Ablk + (size_t)r * K + kk + ch * 4);
            CP_ASYNC_CG(sb0 + so, Bblk + (size_t)r * K + kk + ch * 4);
        }
    };

    issue(0, 0); CP_COMMIT();
    issue(1, 1); CP_COMMIT();

    for (int c = 0; c < nch; ++c) {
        CP_WAIT1();
        __syncthreads();
        if (c + 2 < nch) issue((c + 2) % 3, c + 2);
        CP_COMMIT();

        const uint32_t* sA = s + (c % 3) * STAGE_WORDS;
        const uint32_t* sB = sA + STG_WORDS;
#pragma unroll
        for (int ks = 0; ks < 4; ++ks) {
            const int e1 = (((2 * ks) ^ g) << 2) + t;
            const int e2 = (((2 * ks) ^ g ^ 1) << 2) + t;
            uint32_t af[4][4], bf[4][2];
#pragma unroll
            for (int mt = 0; mt < 4; ++mt) {
                int mr = m0 + mt * 16 + g;
                af[mt][0] = sA[mr * 32 + e1];
                af[mt][1] = sA[(mr + 8) * 32 + e1];
                af[mt][2] = sA[mr * 32 + e2];
                af[mt][3] = sA[(mr + 8) * 32 + e2];
            }
#pragma unroll
            for (int nt = 0; nt < 4; ++nt) {
                int nr = n0 + nt * 8 + g;
                bf[nt][0] = sB[nr * 32 + e1];
                bf[nt][1] = sB[nr * 32 + e2];
            }
#pragma unroll
            for (int mt = 0; mt < 4; ++mt)
#pragma unroll
                for (int nt = 0; nt < 4; ++nt)
                    mma_tf32(acc[mt][nt], af[mt], bf[nt]);
        }
    }

#pragma unroll
    for (int mt = 0; mt < 4; ++mt) {
        int r0 = m0 + mt * 16 + g;
#pragma unroll
        for (int nt = 0; nt < 4; ++nt) {
            int cc = n0 + nt * 8 + 2 * t;
            if (TRANSV) {
                Ct[(size_t)(col0g + cc)     * SEQ + row0g + r0]     = f2tf32(acc[mt][nt][0]);
                Ct[(size_t)(col0g + cc + 1) * SEQ + row0g + r0]     = f2tf32(acc[mt][nt][1]);
                Ct[(size_t)(col0g + cc)     * SEQ + row0g + r0 + 8] = f2tf32(acc[mt][nt][2]);
                Ct[(size_t)(col0g + cc + 1) * SEQ + row0g + r0 + 8] = f2tf32(acc[mt][nt][3]);
            } else {
                *(float2*)(Cblk + (size_t)r0 * ldc + cc)       = make_float2(acc[mt][nt][0], acc[mt][nt][1]);
                *(float2*)(Cblk + (size_t)(r0 + 8) * ldc + cc) = make_float2(acc[mt][nt][2], acc[mt][nt][3]);
            }
        }
    }
}

// Fused QKV: grid (24,16). cb 0..15 -> Q (fp32), 16..19 -> K (fp32),
// 20..23 -> V (tf32 bits, transposed into g_vt).
__global__ __launch_bounds__(256, 2) void qkv_mma(
    const uint32_t* __restrict__ xmu,
    const uint32_t* __restrict__ wqc, const uint32_t* __restrict__ wkc,
    const uint32_t* __restrict__ wvc,
    float* __restrict__ pq, float* __restrict__ pk, uint32_t* __restrict__ pvt)
{
    extern __shared__ uint32_t smem[];
    const int cb = blockIdx.x;
    const int row0 = blockIdx.y * 128;

    if (cb < 20) {
        const uint32_t* B; float* C; int ldc, ccol;
        if (cb < 16) { B = wqc; C = pq; ldc = QD;  ccol = cb * 128; }
        else         { B = wkc; C = pk; ldc = KVD; ccol = (cb - 16) * 128; }
        gemm_core_async<false>(xmu + (size_t)row0 * (2 * HID), B + (size_t)ccol * (2 * HID),
                               C + (size_t)row0 * ldc + ccol, ldc, nullptr, 0, 0, 2 * HID, smem);
    } else {
        const int ccol = (cb - 20) * 128;
        gemm_core_async<true>(xmu + (size_t)row0 * (2 * HID), wvc + (size_t)ccol * (2 * HID),
                              nullptr, 0, pvt, row0, ccol, 2 * HID, smem);
    }
}

// Output projection: grid = (16, 16)
__global__ __launch_bounds__(256, 2) void oproj_mma(
    const uint32_t* __restrict__ A, const uint32_t* __restrict__ B, float* __restrict__ C)
{
    extern __shared__ uint32_t smem[];
    const int row0 = blockIdx.y * 128;
    const int ccol = blockIdx.x * 128;
    gemm_core_async<false>(A + (size_t)row0 * QD, B + (size_t)ccol * QD,
                           C + (size_t)row0 * QD + ccol, QD, nullptr, 0, 0, QD, smem);
}

// ---------------------------------------------------------------------------
// Per-head RMSNorm + RoPE (table-based). Q in place (fp32); K -> tf32 bits.
// grid=(SEQ, NH+NKV), 128 thr
// ---------------------------------------------------------------------------
__global__ __launch_bounds__(128) void normrope_kernel(
    float* __restrict__ qb, const float* __restrict__ kb, uint32_t* __restrict__ kt,
    const float* __restrict__ qw, const float* __restrict__ kw,
    const float2* __restrict__ rope)
{
    const int pos = blockIdx.x;
    const int hh = blockIdx.y;
    const int d = threadIdx.x;

    const bool isq = (hh < NH);
    int stride = isq ? QD : KVD;
    int col0 = isq ? hh * HD : (hh - NH) * HD;
    const float* w = isq ? qw : kw;
    const size_t idx = (size_t)pos * stride + col0 + d;

    float x = isq ? qb[idx] : kb[idx];

    float ss = x * x;
#pragma unroll
    for (int off = 16; off; off >>= 1) ss += __shfl_xor_sync(0xffffffffu, ss, off);

    __shared__ float red[4];
    __shared__ float xs[128];
    if ((d & 31) == 0) red[d >> 5] = ss;
    __syncthreads();
    ss = red[0] + red[1] + red[2] + red[3];

    float xn = x * rsqrtf(ss * (1.0f / 128.0f) + 1e-6f) * w[d];
    xs[d] = xn;
    __syncthreads();
    float rot = (d < 64) ? -xs[d + 64] : xs[d - 64];

    float2 cs = rope[pos * 64 + (d & 63)];
    float r = xn * cs.x + rot * cs.y;
    if (isq) qb[idx] = r;
    else     kt[idx] = f2tf32(r);
}

// ---------------------------------------------------------------------------
// Tensor-core causal flash attention (tf32 mma), cp.async double-buffered K/V.
// Q-tile 128 rows, KV-tile 64. 8 warps. grid = (SEQ/128, NH), reversed qt.
// Fully-masked 8-col mma chunks are skipped (warp-uniform branches).
// ---------------------------------------------------------------------------
#define ATTN_SMEM_WORDS 41984

__global__ __launch_bounds__(256, 1) void attn_mma(
    const float* __restrict__ q, const uint32_t* __restrict__ kt,
    const uint32_t* __restrict__ vt, uint32_t* __restrict__ o)
{
    extern __shared__ uint32_t sw[];
    uint32_t* sP = sw + 32768;    // [128][72]
    uint32_t* sQ = sw + 16384;    // staging [128][136]
    const uint32_t sbyte = smem_u32(sw);

    const int qt = gridDim.x - 1 - blockIdx.x;   // heavy tiles first
    const int h = blockIdx.y;
    const int kvh = h >> 2;
    const int qrow0 = qt * 128;
    const int tid = threadIdx.x;
    const int w = tid >> 5, lane = tid & 31;
    const int gg = lane >> 2, t = lane & 3;
    const int m0 = w * 16;
    const int jmax = 2 * qt + 2;
    const int rmax = qrow0 + m0 + 15;            // warp's max query row

    // issue cp.async for KV tile jt into buffer b
    auto issueKV = [&](int b, int jt) {
        const uint32_t kb0 = sbyte + (uint32_t)(b ? 16384 : 0) * 4u;
        const uint32_t vb0 = kb0 + 8192u * 4u;
#pragma unroll
        for (int i = 0; i < 8; ++i) {      // K: 64 rows x 32 chunks
            int id = tid + i * 256;
            int r = id >> 5, c = id & 31;
            int cs = (c & 24) | ((c & 7) ^ (r & 7));
            CP_ASYNC_CG(kb0 + (uint32_t)(r * 128 + cs * 4) * 4u,
                        kt + (size_t)(jt * 64 + r) * KVD + kvh * HD + c * 4);
        }
#pragma unroll
        for (int i = 0; i < 8; ++i) {      // V: 128 rows x 16 chunks
            int id = tid + i * 256;
            int r = id >> 4, c = id & 15;
            int cs = (c & 8) | ((c & 7) ^ (r & 7));
            CP_ASYNC_CG(vb0 + (uint32_t)(r * 64 + cs * 4) * 4u,
                        vt + (size_t)(kvh * HD + r) * SEQ + jt * 64 + c * 4);
        }
    };

    // tile 0 copy overlaps Q staging (buf0 does not alias sQ)
    issueKV(0, 0); CP_COMMIT();

    // ---- stage Q tile into permuted smem (coalesced) ----
#pragma unroll
    for (int i = 0; i < 16; ++i) {
        int id = tid + i * 256;
        int r = id >> 5, c4 = id & 31, c = c4 * 4;
        float4 val = *(const float4*)(q + (size_t)(qrow0 + r) * QD + h * HD + c);
        uint32_t base = (uint32_t)(r * 136 + (c >> 3) * 8 + ((c >> 2) & 1));
        sQ[base + 0] = f2tf32(val.x);
        sQ[base + 2] = f2tf32(val.y);
        sQ[base + 4] = f2tf32(val.z);
        sQ[base + 6] = f2tf32(val.w);
    }
    __syncthreads();

    // ---- load Q fragments into registers ----
    uint32_t qf[16][4];
#pragma unroll
    for (int ks = 0; ks < 16; ++ks) {
        uint2 q0 = *(const uint2*)&sQ[(m0 + gg) * 136 + ks * 8 + 2 * t];
        uint2 q1 = *(const uint2*)&sQ[(m0 + gg + 8) * 136 + ks * 8 + 2 * t];
        qf[ks][0] = q0.x; qf[ks][1] = q1.x; qf[ks][2] = q0.y; qf[ks][3] = q1.y;
    }

    float oacc[16][4];
#pragma unroll
    for (int i = 0; i < 16; ++i)
#pragma unroll
        for (int j = 0; j < 4; ++j) oacc[i][j] = 0.0f;
    float mrow0 = -1e30f, mrow1 = -1e30f, lrow0 = 0.0f, lrow1 = 0.0f;

    const float scale = 0.08838834764831845f;  // 1/sqrt(128)

    for (int jt = 0; jt < jmax; ++jt) {
        CP_WAIT0();
        __syncthreads();   // tile jt visible to all; all warps done with prev compute
        if (jt + 1 < jmax) { issueKV((jt + 1) & 1, jt + 1); CP_COMMIT(); }

        const uint32_t* sK = sw + ((jt & 1) ? 16384 : 0);
        const uint32_t* sV = sK + 8192;

        const bool active = (jt * 64 <= rmax);
        if (active) {
            // ---- S = Q @ K^T (skip fully-masked 8-col chunks) ----
            float sacc[8][4];
#pragma unroll
            for (int i = 0; i < 8; ++i)
#pragma unroll
                for (int j = 0; j < 4; ++j) sacc[i][j] = 0.0f;

#pragma unroll
            for (int nt = 0; nt < 8; ++nt) {
                if (jt * 64 + nt * 8 <= rmax) {
                    const int nr = nt * 8 + gg;
#pragma unroll
                    for (int ks = 0; ks < 16; ++ks) {
                        const int c0 = ((2 * ks) & 24) | (((2 * ks) & 7) ^ gg);
                        const int c1 = ((2 * ks) & 24) | ((((2 * ks) & 7) ^ 1) ^ gg);
                        mma_tf32_2(sacc[nt], qf[ks],
                                   sK[nr * 128 + c0 * 4 + t], sK[nr * 128 + c1 * 4 + t]);
                    }
                }
            }

            // ---- scale + mask + online softmax ----
            const int r0 = qrow0 + m0 + gg;
            const int r1 = r0 + 8;
            const bool edge = (jt >= 2 * qt);
            float rm0 = -1e30f, rm1 = -1e30f;
#pragma unroll
            for (int nt = 0; nt < 8; ++nt) {
                float c0 = sacc[nt][0] * scale, c1 = sacc[nt][1] * scale;
                float c2 = sacc[nt][2] * scale, c3 = sacc[nt][3] * scale;
                if (edge) {
                    int colb = jt * 64 + nt * 8 + 2 * t;
                    if (colb     > r0) c0 = -1e30f;
                    if (colb + 1 > r0) c1 = -1e30f;
                    if (colb     > r1) c2 = -1e30f;
                    if (colb + 1 > r1) c3 = -1e30f;
                }
                sacc[nt][0] = c0; sacc[nt][1] = c1; sacc[nt][2] = c2; sacc[nt][3] = c3;
                rm0 = fmaxf(rm0, fmaxf(c0, c1));
                rm1 = fmaxf(rm1, fmaxf(c2, c3));
            }
            rm0 = fmaxf(rm0, __shfl_xor_sync(0xffffffffu, rm0, 1));
            rm0 = fmaxf(rm0, __shfl_xor_sync(0xffffffffu, rm0, 2));
            rm1 = fmaxf(rm1, __shfl_xor_sync(0xffffffffu, rm1, 1));
            rm1 = fmaxf(rm1, __shfl_xor_sync(0xffffffffu, rm1, 2));

            float mn0 = fmaxf(mrow0, rm0), mn1 = fmaxf(mrow1, rm1);
            float al0 = __expf(mrow0 - mn0), al1 = __expf(mrow1 - mn1);
            mrow0 = mn0; mrow1 = mn1;

            const uint32_t pA = (uint32_t)(((2 * t) & 3) * 2 + ((t >> 1) & 1));
            const uint32_t pb0 = (uint32_t)((m0 + gg) * 72) + pA;
            const uint32_t pb1 = pb0 + 8 * 72;
            float rs0 = 0.0f, rs1 = 0.0f;
#pragma unroll
            for (int nt = 0; nt < 8; ++nt) {
                float p0 = __expf(sacc[nt][0] - mn0);
                float p1 = __expf(sacc[nt][1] - mn0);
                float p2 = __expf(sacc[nt][2] - mn1);
                float p3 = __expf(sacc[nt][3] - mn1);
                rs0 += p0 + p1; rs1 += p2 + p3;
                sP[pb0 + nt * 8]     = f2tf32(p0);
                sP[pb0 + nt * 8 + 2] = f2tf32(p1);
                sP[pb1 + nt * 8]     = f2tf32(p2);
                sP[pb1 + nt * 8 + 2] = f2tf32(p3);
            }
            rs0 += __shfl_xor_sync(0xffffffffu, rs0, 1);
            rs0 += __shfl_xor_sync(0xffffffffu, rs0, 2);
            rs1 += __shfl_xor_sync(0xffffffffu, rs1, 1);
            rs1 += __shfl_xor_sync(0xffffffffu, rs1, 2);
            lrow0 = lrow0 * al0 + rs0;
            lrow1 = lrow1 * al1 + rs1;

#pragma unroll
            for (int nt = 0; nt < 16; ++nt) {
                oacc[nt][0] *= al0; oacc[nt][1] *= al0;
                oacc[nt][2] *= al1; oacc[nt][3] *= al1;
            }
            __syncwarp();

            // ---- O += P @ V (skip k-chunks whose P rows are all masked) ----
#pragma unroll
            for (int ks = 0; ks < 8; ++ks) {
                if (jt * 64 + ks * 8 <= rmax) {
                    const int c0 = ((2 * ks) & 8) | (((2 * ks) & 7) ^ gg);
                    const int c1 = ((2 * ks) & 8) | ((((2 * ks) & 7) ^ 1) ^ gg);
                    uint2 pa0 = *(const uint2*)&sP[(m0 + gg) * 72 + ks * 8 + 2 * t];
                    uint2 pa1 = *(const uint2*)&sP[(m0 + gg + 8) * 72 + ks * 8 + 2 * t];
                    uint32_t a[4] = {pa0.x, pa1.x, pa0.y, pa1.y};
#pragma unroll
                    for (int nt = 0; nt < 16; ++nt) {
                        int nr = nt * 8 + gg;
                        mma_tf32_2(oacc[nt], a,
                                   sV[nr * 64 + c0 * 4 + t], sV[nr * 64 + c1 * 4 + t]);
                    }
                }
            }
        }
    }

    // ---- normalize + write tf32 bits ----
    const float inv0 = 1.0f / lrow0, inv1 = 1.0f / lrow1;
    const int r0 = qrow0 + m0 + gg;
#pragma unroll
    for (int nt = 0; nt < 16; ++nt) {
        int cc = h * HD + nt * 8 + 2 * t;
        *(uint2*)(o + (size_t)r0 * QD + cc) =
            make_uint2(f2tf32(oacc[nt][0] * inv0), f2tf32(oacc[nt][1] * inv0));
        *(uint2*)(o + (size_t)(r0 + 8) * QD + cc) =
            make_uint2(f2tf32(oacc[nt][2] * inv1), f2tf32(oacc[nt][3] * inv1));
    }
}

// ---------------------------------------------------------------------------
extern "C" void kernel_launch(void* const* d_in, const int* in_sizes, int n_in,
                              void* d_out, int out_size)
{
    (void)in_sizes; (void)n_in; (void)out_size;
    const float* x   = (const float*)d_in[0];
    const float* mu  = (const float*)d_in[1];
    const float* wq  = (const float*)d_in[2];
    const float* wk  = (const float*)d_in[3];
    const float* wv  = (const float*)d_in[4];
    const float* wo  = (const float*)d_in[5];
    const float* wmq = (const float*)d_in[6];
    const float* wmk = (const float*)d_in[7];
    const float* wmv = (const float*)d_in[8];
    const float* qw  = (const float*)d_in[9];
    const float* kw  = (const float*)d_in[10];
    float* out = (float*)d_out;

    float *pq, *pk; uint32_t *pkt, *pvt, *po;
    uint32_t *pxmu, *pwqc, *pwkc, *pwvc, *pwot;
    float2 *prope;
    cudaGetSymbolAddress((void**)&pq, g_q);
    cudaGetSymbolAddress((void**)&pk, g_k);
    cudaGetSymbolAddress((void**)&pkt, g_kt);
    cudaGetSymbolAddress((void**)&pvt, g_vt);
    cudaGetSymbolAddress((void**)&po, g_o);
    cudaGetSymbolAddress((void**)&pxmu, g_xmu);
    cudaGetSymbolAddress((void**)&pwqc, g_wqc);
    cudaGetSymbolAddress((void**)&pwkc, g_wkc);
    cudaGetSymbolAddress((void**)&pwvc, g_wvc);
    cudaGetSymbolAddress((void**)&pwot, g_wot);
    cudaGetSymbolAddress((void**)&prope, g_rope);

    // ---- fused prepass: all conversions in one kernel + rope table ----
    rope_table<<<SEQ, 64>>>(prope);
    cvt_all<<<24576, 256>>>(pxmu, pwqc, pwkc, pwvc, pwot,
                            x, mu, wq, wmq, wk, wmk, wv, wmv, wo);

    const int gemm_smem = 3 * STAGE_WORDS * 4;  // 98304 bytes
    cudaFuncSetAttribute(qkv_mma,   cudaFuncAttributeMaxDynamicSharedMemorySize, gemm_smem);
    cudaFuncSetAttribute(oproj_mma, cudaFuncAttributeMaxDynamicSharedMemorySize, gemm_smem);

    // Fused QKV projections (tf32, cp.async pipelined, 2 CTAs/SM)
    qkv_mma<<<dim3(24, 16), 256, gemm_smem>>>(pxmu, pwqc, pwkc, pwvc, pq, pk, pvt);

    // per-head RMSNorm + RoPE (table); K emitted as tf32 bits
    normrope_kernel<<<dim3(SEQ, NH + NKV), 128>>>(pq, pk, pkt, qw, kw, prope);

    // causal GQA attention (tf32, cp.async double-buffered K/V)
    const int attn_smem = ATTN_SMEM_WORDS * 4;  // 167936 bytes
    cudaFuncSetAttribute(attn_mma, cudaFuncAttributeMaxDynamicSharedMemorySize, attn_smem);
    attn_mma<<<dim3(SEQ / 128, NH), 256, attn_smem>>>(pq, pkt, pvt, po);

    // output projection (tf32, cp.async pipelined, 2 CTAs/SM)
    oproj_mma<<<dim3(16, 16), 256, gemm_smem>>>(po, pwot, out);
}

// round 10
// speedup vs baseline: 1.0551x; 1.0551x over previous
#include <cuda_runtime.h>
#include <math.h>
#include <stdint.h>

#define SEQ 2048
#define HID 2048
#define NH 16
#define NKV 4
#define HD 128
#define QD (NH*HD)    /* 2048 */
#define KVD (NKV*HD)  /* 512  */

// Scratch (device globals: no allocations allowed)
__device__ float    g_q[SEQ*QD];
__device__ float    g_k[SEQ*KVD];            // fp32 K (pre-normrope)
__device__ uint32_t g_kt[SEQ*KVD];           // tf32 K (post-normrope)
__device__ uint32_t g_vt[KVD*SEQ];           // tf32 V, transposed [kvd][seq]
__device__ uint32_t g_o[SEQ*QD];             // attention output as tf32 bits
__device__ float2   g_rope[SEQ*64];          // (cos, sin) per (pos, freq)
// Pre-converted tf32-bit operands (prepass)
__device__ uint32_t g_xmu[SEQ*2*HID];        // [x | mu]  2048 x 4096
__device__ uint32_t g_wqc[QD*2*HID];         // [wq | wmq] 2048 x 4096
__device__ uint32_t g_wkc[KVD*2*HID];        // [wk | wmk]  512 x 4096
__device__ uint32_t g_wvc[KVD*2*HID];        // [wv | wmv]  512 x 4096
__device__ uint32_t g_wot[HID*QD];           // wo         2048 x 2048

// ---------------------------------------------------------------------------
// tf32 helpers (plain sm_80+ PTX — no sm_103a-gated instructions)
// ---------------------------------------------------------------------------
__device__ __forceinline__ uint32_t f2tf32(float x) {
    uint32_t r;
    asm("cvt.rna.tf32.f32 %0, %1;" : "=r"(r) : "f"(x));
    return r;
}

__device__ __forceinline__ void mma_tf32(float d[4], const uint32_t a[4], const uint32_t b[2]) {
    asm volatile(
        "mma.sync.aligned.m16n8k8.row.col.f32.tf32.tf32.f32 "
        "{%0,%1,%2,%3}, {%4,%5,%6,%7}, {%8,%9}, {%0,%1,%2,%3};"
        : "+f"(d[0]), "+f"(d[1]), "+f"(d[2]), "+f"(d[3])
        : "r"(a[0]), "r"(a[1]), "r"(a[2]), "r"(a[3]), "r"(b[0]), "r"(b[1]));
}

__device__ __forceinline__ void mma_tf32_2(float d[4], const uint32_t a[4],
                                           uint32_t b0, uint32_t b1) {
    asm volatile(
        "mma.sync.aligned.m16n8k8.row.col.f32.tf32.tf32.f32 "
        "{%0,%1,%2,%3}, {%4,%5,%6,%7}, {%8,%9}, {%0,%1,%2,%3};"
        : "+f"(d[0]), "+f"(d[1]), "+f"(d[2]), "+f"(d[3])
        : "r"(a[0]), "r"(a[1]), "r"(a[2]), "r"(a[3]), "r"(b0), "r"(b1));
}

#define CP_ASYNC_CG(dst_u32, src_ptr) \
    asm volatile("cp.async.cg.shared.global [%0], [%1], 16;" :: "r"(dst_u32), "l"(src_ptr) : "memory")
#define CP_COMMIT() asm volatile("cp.async.commit_group;" ::: "memory")
#define CP_WAIT1()  asm volatile("cp.async.wait_group 1;"  ::: "memory")
#define CP_WAIT0()  asm volatile("cp.async.wait_group 0;"  ::: "memory")

__device__ __forceinline__ uint32_t smem_u32(const void* p) {
    uint32_t a;
    asm("{ .reg .u64 t; cvta.to.shared.u64 t, %1; cvt.u32.u64 %0, t; }" : "=r"(a) : "l"(p));
    return a;
}

// ---------------------------------------------------------------------------
// Fused prepass: all fp32 -> tf32 conversions (+K-concat) in ONE kernel.
// ---------------------------------------------------------------------------
__global__ __launch_bounds__(256) void cvt_all(
    uint32_t* __restrict__ xmu, uint32_t* __restrict__ wqc,
    uint32_t* __restrict__ wkc, uint32_t* __restrict__ wvc,
    uint32_t* __restrict__ wot,
    const float* __restrict__ x,  const float* __restrict__ mu,
    const float* __restrict__ wq, const float* __restrict__ wmq,
    const float* __restrict__ wk, const float* __restrict__ wmk,
    const float* __restrict__ wv, const float* __restrict__ wmv,
    const float* __restrict__ wo)
{
    long e = ((long)blockIdx.x * 256 + threadIdx.x) * 4;
    const float *A, *B; uint32_t* D; long off; bool cat = true;
    if (e < 8388608L)       { D = xmu; A = x;  B = mu;  off = e; }
    else if (e < 16777216L) { D = wqc; A = wq; B = wmq; off = e - 8388608L; }
    else if (e < 18874368L) { D = wkc; A = wk; B = wmk; off = e - 16777216L; }
    else if (e < 20971520L) { D = wvc; A = wv; B = wmv; off = e - 18874368L; }
    else                    { D = wot; A = wo; B = wo;  off = e - 20971520L; cat = false; }

    float4 v;
    if (cat) {
        int r = (int)(off >> 12);
        int c = (int)(off & 4095);
        const float* src = (c < 2048) ? (A + (size_t)r * 2048 + c)
                                      : (B + (size_t)r * 2048 + (c - 2048));
        v = *(const float4*)src;
    } else {
        v = *(const float4*)(A + off);
    }
    *(uint4*)(D + off) = make_uint4(f2tf32(v.x), f2tf32(v.y), f2tf32(v.z), f2tf32(v.w));
}

// RoPE (cos,sin) table: only 2048 x 64 unique angles exist.
__global__ __launch_bounds__(64) void rope_table(float2* __restrict__ tab)
{
    const int pos = blockIdx.x;
    const int f = threadIdx.x;
    float ang = (float)pos * powf(10000.0f, -(float)f * (1.0f / 64.0f));
    float sn, cs;
    sincosf(ang, &sn, &cs);
    tab[pos * 64 + f] = make_float2(cs, sn);
}

// ---------------------------------------------------------------------------
// cp.async 3-stage tf32 GEMM core (XOR swizzle). TRANSV epilogue writes tf32
// bits transposed into Ct[(col0g+cc)*SEQ + row0g + r].
// ---------------------------------------------------------------------------
#define STG_WORDS 4096            /* 128*32 */
#define STAGE_WORDS (2*STG_WORDS) /* A+B */

template<bool TRANSV>
__device__ __forceinline__ void gemm_core_async(
    const uint32_t* __restrict__ Ablk, const uint32_t* __restrict__ Bblk,
    float* __restrict__ Cblk, int ldc,
    uint32_t* __restrict__ Ct, int row0g, int col0g,
    int K, uint32_t* s)
{
    const uint32_t sbyte = smem_u32(s);
    const int tid = threadIdx.x;
    const int wid = tid >> 5, lane = tid & 31;
    const int g = lane >> 2, t = lane & 3;
    const int m0 = (wid >> 2) * 64;
    const int n0 = (wid & 3) * 32;

    const int lr = tid >> 3;
    const int ch = tid & 7;

    float acc[4][4][4];
#pragma unroll
    for (int i = 0; i < 4; ++i)
#pragma unroll
        for (int j = 0; j < 4; ++j)
#pragma unroll
            for (int q = 0; q < 4; ++q) acc[i][j][q] = 0.0f;

    const int nch = K >> 5;
    const int chsw = ch ^ (lr & 7);

    auto issue = [&](int st, int cc) {
        const uint32_t sa0 = sbyte + (uint32_t)(st * STAGE_WORDS) * 4u;
        const uint32_t sb0 = sa0 + STG_WORDS * 4u;
        const int kk = cc << 5;
#pragma unroll
        for (int i = 0; i < 4; ++i) {
            int r = lr + i * 32;
            uint32_t so = (uint32_t)(r * 32 + chsw * 4) * 4u;
            CP_ASYNC_CG(sa0 + so, Ablk + (size_t)r * K + kk + ch * 4);
            CP_ASYNC_CG(sb0 + so, Bblk + (size_t)r * K + kk + ch * 4);
        }
    };

    issue(0, 0); CP_COMMIT();
    issue(1, 1); CP_COMMIT();

    for (int c = 0; c < nch; ++c) {
        CP_WAIT1();
        __syncthreads();
        if (c + 2 < nch) issue((c + 2) % 3, c + 2);
        CP_COMMIT();

        const uint32_t* sA = s + (c % 3) * STAGE_WORDS;
        const uint32_t* sB = sA + STG_WORDS;
#pragma unroll
        for (int ks = 0; ks < 4; ++ks) {
            const int e1 = (((2 * ks) ^ g) << 2) + t;
            const int e2 = (((2 * ks) ^ g ^ 1) << 2) + t;
            uint32_t af[4][4], bf[4][2];
#pragma unroll
            for (int mt = 0; mt < 4; ++mt) {
                int mr = m0 + mt * 16 + g;
                af[mt][0] = sA[mr * 32 + e1];
                af[mt][1] = sA[(mr + 8) * 32 + e1];
                af[mt][2] = sA[mr * 32 + e2];
                af[mt][3] = sA[(mr + 8) * 32 + e2];
            }
#pragma unroll
            for (int nt = 0; nt < 4; ++nt) {
                int nr = n0 + nt * 8 + g;
                bf[nt][0] = sB[nr * 32 + e1];
                bf[nt][1] = sB[nr * 32 + e2];
            }
#pragma unroll
            for (int mt = 0; mt < 4; ++mt)
#pragma unroll
                for (int nt = 0; nt < 4; ++nt)
                    mma_tf32(acc[mt][nt], af[mt], bf[nt]);
        }
    }

#pragma unroll
    for (int mt = 0; mt < 4; ++mt) {
        int r0 = m0 + mt * 16 + g;
#pragma unroll
        for (int nt = 0; nt < 4; ++nt) {
            int cc = n0 + nt * 8 + 2 * t;
            if (TRANSV) {
                Ct[(size_t)(col0g + cc)     * SEQ + row0g + r0]     = f2tf32(acc[mt][nt][0]);
                Ct[(size_t)(col0g + cc + 1) * SEQ + row0g + r0]     = f2tf32(acc[mt][nt][1]);
                Ct[(size_t)(col0g + cc)     * SEQ + row0g + r0 + 8] = f2tf32(acc[mt][nt][2]);
                Ct[(size_t)(col0g + cc + 1) * SEQ + row0g + r0 + 8] = f2tf32(acc[mt][nt][3]);
            } else {
                *(float2*)(Cblk + (size_t)r0 * ldc + cc)       = make_float2(acc[mt][nt][0], acc[mt][nt][1]);
                *(float2*)(Cblk + (size_t)(r0 + 8) * ldc + cc) = make_float2(acc[mt][nt][2], acc[mt][nt][3]);
            }
        }
    }
}

// Fused QKV: grid (24,16). cb 0..15 -> Q (fp32), 16..19 -> K (fp32),
// 20..23 -> V (tf32 bits, transposed into g_vt).
__global__ __launch_bounds__(256, 2) void qkv_mma(
    const uint32_t* __restrict__ xmu,
    const uint32_t* __restrict__ wqc, const uint32_t* __restrict__ wkc,
    const uint32_t* __restrict__ wvc,
    float* __restrict__ pq, float* __restrict__ pk, uint32_t* __restrict__ pvt)
{
    extern __shared__ uint32_t smem[];
    const int cb = blockIdx.x;
    const int row0 = blockIdx.y * 128;

    if (cb < 20) {
        const uint32_t* B; float* C; int ldc, ccol;
        if (cb < 16) { B = wqc; C = pq; ldc = QD;  ccol = cb * 128; }
        else         { B = wkc; C = pk; ldc = KVD; ccol = (cb - 16) * 128; }
        gemm_core_async<false>(xmu + (size_t)row0 * (2 * HID), B + (size_t)ccol * (2 * HID),
                               C + (size_t)row0 * ldc + ccol, ldc, nullptr, 0, 0, 2 * HID, smem);
    } else {
        const int ccol = (cb - 20) * 128;
        gemm_core_async<true>(xmu + (size_t)row0 * (2 * HID), wvc + (size_t)ccol * (2 * HID),
                              nullptr, 0, pvt, row0, ccol, 2 * HID, smem);
    }
}

// Output projection: grid = (16, 16)
__global__ __launch_bounds__(256, 2) void oproj_mma(
    const uint32_t* __restrict__ A, const uint32_t* __restrict__ B, float* __restrict__ C)
{
    extern __shared__ uint32_t smem[];
    const int row0 = blockIdx.y * 128;
    const int ccol = blockIdx.x * 128;
    gemm_core_async<false>(A + (size_t)row0 * QD, B + (size_t)ccol * QD,
                           C + (size_t)row0 * QD + ccol, QD, nullptr, 0, 0, QD, smem);
}

// ---------------------------------------------------------------------------
// Per-head RMSNorm + RoPE (table-based). Q in place (fp32); K -> tf32 bits.
// grid=(SEQ, NH+NKV), 128 thr
// ---------------------------------------------------------------------------
__global__ __launch_bounds__(128) void normrope_kernel(
    float* __restrict__ qb, const float* __restrict__ kb, uint32_t* __restrict__ kt,
    const float* __restrict__ qw, const float* __restrict__ kw,
    const float2* __restrict__ rope)
{
    const int pos = blockIdx.x;
    const int hh = blockIdx.y;
    const int d = threadIdx.x;

    const bool isq = (hh < NH);
    int stride = isq ? QD : KVD;
    int col0 = isq ? hh * HD : (hh - NH) * HD;
    const float* w = isq ? qw : kw;
    const size_t idx = (size_t)pos * stride + col0 + d;

    float x = isq ? qb[idx] : kb[idx];

    float ss = x * x;
#pragma unroll
    for (int off = 16; off; off >>= 1) ss += __shfl_xor_sync(0xffffffffu, ss, off);

    __shared__ float red[4];
    __shared__ float xs[128];
    if ((d & 31) == 0) red[d >> 5] = ss;
    __syncthreads();
    ss = red[0] + red[1] + red[2] + red[3];

    float xn = x * rsqrtf(ss * (1.0f / 128.0f) + 1e-6f) * w[d];
    xs[d] = xn;
    __syncthreads();
    float rot = (d < 64) ? -xs[d + 64] : xs[d - 64];

    float2 cs = rope[pos * 64 + (d & 63)];
    float r = xn * cs.x + rot * cs.y;
    if (isq) qb[idx] = r;
    else     kt[idx] = f2tf32(r);
}

// ---------------------------------------------------------------------------
// Tensor-core causal flash attention (tf32 mma), cp.async double-buffered K/V.
// Q-tile 128 rows, KV-tile 64. 8 warps. grid = (SEQ/128, NH), reversed qt.
// Interior tiles use the branch-free R8 loop; edge tiles (2 per CTA) take a
// duplicated path with warp-uniform per-chunk skips.
// ---------------------------------------------------------------------------
#define ATTN_SMEM_WORDS 41984

__global__ __launch_bounds__(256, 1) void attn_mma(
    const float* __restrict__ q, const uint32_t* __restrict__ kt,
    const uint32_t* __restrict__ vt, uint32_t* __restrict__ o)
{
    extern __shared__ uint32_t sw[];
    uint32_t* sP = sw + 32768;    // [128][72]
    uint32_t* sQ = sw + 16384;    // staging [128][136]
    const uint32_t sbyte = smem_u32(sw);

    const int qt = gridDim.x - 1 - blockIdx.x;   // heavy tiles first
    const int h = blockIdx.y;
    const int kvh = h >> 2;
    const int qrow0 = qt * 128;
    const int tid = threadIdx.x;
    const int w = tid >> 5, lane = tid & 31;
    const int gg = lane >> 2, t = lane & 3;
    const int m0 = w * 16;
    const int jmax = 2 * qt + 2;
    const int rmax = qrow0 + m0 + 15;            // warp's max query row

    // issue cp.async for KV tile jt into buffer b
    auto issueKV = [&](int b, int jt) {
        const uint32_t kb0 = sbyte + (uint32_t)(b ? 16384 : 0) * 4u;
        const uint32_t vb0 = kb0 + 8192u * 4u;
#pragma unroll
        for (int i = 0; i < 8; ++i) {      // K: 64 rows x 32 chunks
            int id = tid + i * 256;
            int r = id >> 5, c = id & 31;
            int cs = (c & 24) | ((c & 7) ^ (r & 7));
            CP_ASYNC_CG(kb0 + (uint32_t)(r * 128 + cs * 4) * 4u,
                        kt + (size_t)(jt * 64 + r) * KVD + kvh * HD + c * 4);
        }
#pragma unroll
        for (int i = 0; i < 8; ++i) {      // V: 128 rows x 16 chunks
            int id = tid + i * 256;
            int r = id >> 4, c = id & 15;
            int cs = (c & 8) | ((c & 7) ^ (r & 7));
            CP_ASYNC_CG(vb0 + (uint32_t)(r * 64 + cs * 4) * 4u,
                        vt + (size_t)(kvh * HD + r) * SEQ + jt * 64 + c * 4);
        }
    };

    // tile 0 copy overlaps Q staging (buf0 does not alias sQ)
    issueKV(0, 0); CP_COMMIT();

    // ---- stage Q tile into permuted smem (coalesced) ----
#pragma unroll
    for (int i = 0; i < 16; ++i) {
        int id = tid + i * 256;
        int r = id >> 5, c4 = id & 31, c = c4 * 4;
        float4 val = *(const float4*)(q + (size_t)(qrow0 + r) * QD + h * HD + c);
        uint32_t base = (uint32_t)(r * 136 + (c >> 3) * 8 + ((c >> 2) & 1));
        sQ[base + 0] = f2tf32(val.x);
        sQ[base + 2] = f2tf32(val.y);
        sQ[base + 4] = f2tf32(val.z);
        sQ[base + 6] = f2tf32(val.w);
    }
    __syncthreads();

    // ---- load Q fragments into registers ----
    uint32_t qf[16][4];
#pragma unroll
    for (int ks = 0; ks < 16; ++ks) {
        uint2 q0 = *(const uint2*)&sQ[(m0 + gg) * 136 + ks * 8 + 2 * t];
        uint2 q1 = *(const uint2*)&sQ[(m0 + gg + 8) * 136 + ks * 8 + 2 * t];
        qf[ks][0] = q0.x; qf[ks][1] = q1.x; qf[ks][2] = q0.y; qf[ks][3] = q1.y;
    }

    float oacc[16][4];
#pragma unroll
    for (int i = 0; i < 16; ++i)
#pragma unroll
        for (int j = 0; j < 4; ++j) oacc[i][j] = 0.0f;
    float mrow0 = -1e30f, mrow1 = -1e30f, lrow0 = 0.0f, lrow1 = 0.0f;

    const float scale = 0.08838834764831845f;  // 1/sqrt(128)

    for (int jt = 0; jt < jmax; ++jt) {
        CP_WAIT0();
        __syncthreads();   // tile jt visible to all; all warps done with prev compute
        if (jt + 1 < jmax) { issueKV((jt + 1) & 1, jt + 1); CP_COMMIT(); }

        const uint32_t* sK = sw + ((jt & 1) ? 16384 : 0);
        const uint32_t* sV = sK + 8192;

        const bool edge = (jt >= 2 * qt);
        const bool active = (jt * 64 <= rmax);
        if (active) {
            // ---- S = Q @ K^T ----
            float sacc[8][4];
#pragma unroll
            for (int i = 0; i < 8; ++i)
#pragma unroll
                for (int j = 0; j < 4; ++j) sacc[i][j] = 0.0f;

            if (!edge) {
                // interior tile: branch-free (R8) loop
#pragma unroll
                for (int ks = 0; ks < 16; ++ks) {
                    const int c0 = ((2 * ks) & 24) | (((2 * ks) & 7) ^ gg);
                    const int c1 = ((2 * ks) & 24) | ((((2 * ks) & 7) ^ 1) ^ gg);
#pragma unroll
                    for (int nt = 0; nt < 8; ++nt) {
                        int nr = nt * 8 + gg;
                        mma_tf32_2(sacc[nt], qf[ks],
                                   sK[nr * 128 + c0 * 4 + t], sK[nr * 128 + c1 * 4 + t]);
                    }
                }
            } else {
                // edge tile (rare): skip fully-masked 8-col chunks
#pragma unroll
                for (int nt = 0; nt < 8; ++nt) {
                    if (jt * 64 + nt * 8 <= rmax) {
                        const int nr = nt * 8 + gg;
#pragma unroll
                        for (int ks = 0; ks < 16; ++ks) {
                            const int c0 = ((2 * ks) & 24) | (((2 * ks) & 7) ^ gg);
                            const int c1 = ((2 * ks) & 24) | ((((2 * ks) & 7) ^ 1) ^ gg);
                            mma_tf32_2(sacc[nt], qf[ks],
                                       sK[nr * 128 + c0 * 4 + t], sK[nr * 128 + c1 * 4 + t]);
                        }
                    }
                }
            }

            // ---- scale + mask + online softmax ----
            const int r0 = qrow0 + m0 + gg;
            const int r1 = r0 + 8;
            float rm0 = -1e30f, rm1 = -1e30f;
#pragma unroll
            for (int nt = 0; nt < 8; ++nt) {
                float c0 = sacc[nt][0] * scale, c1 = sacc[nt][1] * scale;
                float c2 = sacc[nt][2] * scale, c3 = sacc[nt][3] * scale;
                if (edge) {
                    int colb = jt * 64 + nt * 8 + 2 * t;
                    if (colb     > r0) c0 = -1e30f;
                    if (colb + 1 > r0) c1 = -1e30f;
                    if (colb     > r1) c2 = -1e30f;
                    if (colb + 1 > r1) c3 = -1e30f;
                }
                sacc[nt][0] = c0; sacc[nt][1] = c1; sacc[nt][2] = c2; sacc[nt][3] = c3;
                rm0 = fmaxf(rm0, fmaxf(c0, c1));
                rm1 = fmaxf(rm1, fmaxf(c2, c3));
            }
            rm0 = fmaxf(rm0, __shfl_xor_sync(0xffffffffu, rm0, 1));
            rm0 = fmaxf(rm0, __shfl_xor_sync(0xffffffffu, rm0, 2));
            rm1 = fmaxf(rm1, __shfl_xor_sync(0xffffffffu, rm1, 1));
            rm1 = fmaxf(rm1, __shfl_xor_sync(0xffffffffu, rm1, 2));

            float mn0 = fmaxf(mrow0, rm0), mn1 = fmaxf(mrow1, rm1);
            float al0 = __expf(mrow0 - mn0), al1 = __expf(mrow1 - mn1);
            mrow0 = mn0; mrow1 = mn1;

            const uint32_t pA = (uint32_t)(((2 * t) & 3) * 2 + ((t >> 1) & 1));
            const uint32_t pb0 = (uint32_t)((m0 + gg) * 72) + pA;
            const uint32_t pb1 = pb0 + 8 * 72;
            float rs0 = 0.0f, rs1 = 0.0f;
#pragma unroll
            for (int nt = 0; nt < 8; ++nt) {
                float p0 = __expf(sacc[nt][0] - mn0);
                float p1 = __expf(sacc[nt][1] - mn0);
                float p2 = __expf(sacc[nt][2] - mn1);
                float p3 = __expf(sacc[nt][3] - mn1);
                rs0 += p0 + p1; rs1 += p2 + p3;
                sP[pb0 + nt * 8]     = f2tf32(p0);
                sP[pb0 + nt * 8 + 2] = f2tf32(p1);
                sP[pb1 + nt * 8]     = f2tf32(p2);
                sP[pb1 + nt * 8 + 2] = f2tf32(p3);
            }
            rs0 += __shfl_xor_sync(0xffffffffu, rs0, 1);
            rs0 += __shfl_xor_sync(0xffffffffu, rs0, 2);
            rs1 += __shfl_xor_sync(0xffffffffu, rs1, 1);
            rs1 += __shfl_xor_sync(0xffffffffu, rs1, 2);
            lrow0 = lrow0 * al0 + rs0;
            lrow1 = lrow1 * al1 + rs1;

#pragma unroll
            for (int nt = 0; nt < 16; ++nt) {
                oacc[nt][0] *= al0; oacc[nt][1] *= al0;
                oacc[nt][2] *= al1; oacc[nt][3] *= al1;
            }
            __syncwarp();

            // ---- O += P @ V ----
            if (!edge) {
#pragma unroll
                for (int ks = 0; ks < 8; ++ks) {
                    const int c0 = ((2 * ks) & 8) | (((2 * ks) & 7) ^ gg);
                    const int c1 = ((2 * ks) & 8) | ((((2 * ks) & 7) ^ 1) ^ gg);
                    uint2 pa0 = *(const uint2*)&sP[(m0 + gg) * 72 + ks * 8 + 2 * t];
                    uint2 pa1 = *(const uint2*)&sP[(m0 + gg + 8) * 72 + ks * 8 + 2 * t];
                    uint32_t a[4] = {pa0.x, pa1.x, pa0.y, pa1.y};
#pragma unroll
                    for (int nt = 0; nt < 16; ++nt) {
                        int nr = nt * 8 + gg;
                        mma_tf32_2(oacc[nt], a,
                                   sV[nr * 64 + c0 * 4 + t], sV[nr * 64 + c1 * 4 + t]);
                    }
                }
            } else {
#pragma unroll
                for (int ks = 0; ks < 8; ++ks) {
                    if (jt * 64 + ks * 8 <= rmax) {
                        const int c0 = ((2 * ks) & 8) | (((2 * ks) & 7) ^ gg);
                        const int c1 = ((2 * ks) & 8) | ((((2 * ks) & 7) ^ 1) ^ gg);
                        uint2 pa0 = *(const uint2*)&sP[(m0 + gg) * 72 + ks * 8 + 2 * t];
                        uint2 pa1 = *(const uint2*)&sP[(m0 + gg + 8) * 72 + ks * 8 + 2 * t];
                        uint32_t a[4] = {pa0.x, pa1.x, pa0.y, pa1.y};
#pragma unroll
                        for (int nt = 0; nt < 16; ++nt) {
                            int nr = nt * 8 + gg;
                            mma_tf32_2(oacc[nt], a,
                                       sV[nr * 64 + c0 * 4 + t], sV[nr * 64 + c1 * 4 + t]);
                        }
                    }
                }
            }
        }
    }

    // ---- normalize + write tf32 bits ----
    const float inv0 = 1.0f / lrow0, inv1 = 1.0f / lrow1;
    const int r0 = qrow0 + m0 + gg;
#pragma unroll
    for (int nt = 0; nt < 16; ++nt) {
        int cc = h * HD + nt * 8 + 2 * t;
        *(uint2*)(o + (size_t)r0 * QD + cc) =
            make_uint2(f2tf32(oacc[nt][0] * inv0), f2tf32(oacc[nt][1] * inv0));
        *(uint2*)(o + (size_t)(r0 + 8) * QD + cc) =
            make_uint2(f2tf32(oacc[nt][2] * inv1), f2tf32(oacc[nt][3] * inv1));
    }
}

// ---------------------------------------------------------------------------
extern "C" void kernel_launch(void* const* d_in, const int* in_sizes, int n_in,
                              void* d_out, int out_size)
{
    (void)in_sizes; (void)n_in; (void)out_size;
    const float* x   = (const float*)d_in[0];
    const float* mu  = (const float*)d_in[1];
    const float* wq  = (const float*)d_in[2];
    const float* wk  = (const float*)d_in[3];
    const float* wv  = (const float*)d_in[4];
    const float* wo  = (const float*)d_in[5];
    const float* wmq = (const float*)d_in[6];
    const float* wmk = (const float*)d_in[7];
    const float* wmv = (const float*)d_in[8];
    const float* qw  = (const float*)d_in[9];
    const float* kw  = (const float*)d_in[10];
    float* out = (float*)d_out;

    float *pq, *pk; uint32_t *pkt, *pvt, *po;
    uint32_t *pxmu, *pwqc, *pwkc, *pwvc, *pwot;
    float2 *prope;
    cudaGetSymbolAddress((void**)&pq, g_q);
    cudaGetSymbolAddress((void**)&pk, g_k);
    cudaGetSymbolAddress((void**)&pkt, g_kt);
    cudaGetSymbolAddress((void**)&pvt, g_vt);
    cudaGetSymbolAddress((void**)&po, g_o);
    cudaGetSymbolAddress((void**)&pxmu, g_xmu);
    cudaGetSymbolAddress((void**)&pwqc, g_wqc);
    cudaGetSymbolAddress((void**)&pwkc, g_wkc);
    cudaGetSymbolAddress((void**)&pwvc, g_wvc);
    cudaGetSymbolAddress((void**)&pwot, g_wot);
    cudaGetSymbolAddress((void**)&prope, g_rope);

    // ---- fused prepass: all conversions in one kernel + rope table ----
    rope_table<<<SEQ, 64>>>(prope);
    cvt_all<<<24576, 256>>>(pxmu, pwqc, pwkc, pwvc, pwot,
                            x, mu, wq, wmq, wk, wmk, wv, wmv, wo);

    const int gemm_smem = 3 * STAGE_WORDS * 4;  // 98304 bytes
    cudaFuncSetAttribute(qkv_mma,   cudaFuncAttributeMaxDynamicSharedMemorySize, gemm_smem);
    cudaFuncSetAttribute(oproj_mma, cudaFuncAttributeMaxDynamicSharedMemorySize, gemm_smem);

    // Fused QKV projections (tf32, cp.async pipelined, 2 CTAs/SM)
    qkv_mma<<<dim3(24, 16), 256, gemm_smem>>>(pxmu, pwqc, pwkc, pwvc, pq, pk, pvt);

    // per-head RMSNorm + RoPE (table); K emitted as tf32 bits
    normrope_kernel<<<dim3(SEQ, NH + NKV), 128>>>(pq, pk, pkt, qw, kw, prope);

    // causal GQA attention (tf32, cp.async double-buffered K/V)
    const int attn_smem = ATTN_SMEM_WORDS * 4;  // 167936 bytes
    cudaFuncSetAttribute(attn_mma, cudaFuncAttributeMaxDynamicSharedMemorySize, attn_smem);
    attn_mma<<<dim3(SEQ / 128, NH), 256, attn_smem>>>(pq, pkt, pvt, po);

    // output projection (tf32, cp.async pipelined, 2 CTAs/SM)
    oproj_mma<<<dim3(16, 16), 256, gemm_smem>>>(po, pwot, out);
}

// round 11
// speedup vs baseline: 1.0585x; 1.0032x over previous
#include <cuda_runtime.h>
#include <math.h>
#include <stdint.h>

#define SEQ 2048
#define HID 2048
#define NH 16
#define NKV 4
#define HD 128
#define QD (NH*HD)    /* 2048 */
#define KVD (NKV*HD)  /* 512  */

// Scratch (device globals: no allocations allowed)
__device__ float    g_q[SEQ*QD];             // Q half0 (x@Wq), then normed Q
__device__ float    g_q1[SEQ*QD];            // Q half1 (mu@Wmq)
__device__ float    g_k[SEQ*KVD];            // K half0
__device__ float    g_k1[SEQ*KVD];           // K half1
__device__ float    g_v0[KVD*SEQ];           // V half0, fp32 transposed
__device__ float    g_v1[KVD*SEQ];           // V half1, fp32 transposed
__device__ uint32_t g_kt[SEQ*KVD];           // tf32 K (post-normrope)
__device__ uint32_t g_vt[KVD*SEQ];           // tf32 V, transposed [kvd][seq]
__device__ uint32_t g_o[SEQ*QD];             // attention output as tf32 bits
__device__ float2   g_rope[SEQ*64];          // (cos, sin) per (pos, freq)
// Pre-converted tf32-bit operands (prepass)
__device__ uint32_t g_xmu[SEQ*2*HID];        // [x | mu]  2048 x 4096
__device__ uint32_t g_wqc[QD*2*HID];         // [wq | wmq] 2048 x 4096
__device__ uint32_t g_wkc[KVD*2*HID];        // [wk | wmk]  512 x 4096
__device__ uint32_t g_wvc[KVD*2*HID];        // [wv | wmv]  512 x 4096
__device__ uint32_t g_wot[HID*QD];           // wo         2048 x 2048

// ---------------------------------------------------------------------------
// tf32 helpers (plain sm_80+ PTX — no sm_103a-gated instructions)
// ---------------------------------------------------------------------------
__device__ __forceinline__ uint32_t f2tf32(float x) {
    uint32_t r;
    asm("cvt.rna.tf32.f32 %0, %1;" : "=r"(r) : "f"(x));
    return r;
}

__device__ __forceinline__ void mma_tf32(float d[4], const uint32_t a[4], const uint32_t b[2]) {
    asm volatile(
        "mma.sync.aligned.m16n8k8.row.col.f32.tf32.tf32.f32 "
        "{%0,%1,%2,%3}, {%4,%5,%6,%7}, {%8,%9}, {%0,%1,%2,%3};"
        : "+f"(d[0]), "+f"(d[1]), "+f"(d[2]), "+f"(d[3])
        : "r"(a[0]), "r"(a[1]), "r"(a[2]), "r"(a[3]), "r"(b[0]), "r"(b[1]));
}

__device__ __forceinline__ void mma_tf32_2(float d[4], const uint32_t a[4],
                                           uint32_t b0, uint32_t b1) {
    asm volatile(
        "mma.sync.aligned.m16n8k8.row.col.f32.tf32.tf32.f32 "
        "{%0,%1,%2,%3}, {%4,%5,%6,%7}, {%8,%9}, {%0,%1,%2,%3};"
        : "+f"(d[0]), "+f"(d[1]), "+f"(d[2]), "+f"(d[3])
        : "r"(a[0]), "r"(a[1]), "r"(a[2]), "r"(a[3]), "r"(b0), "r"(b1));
}

#define CP_ASYNC_CG(dst_u32, src_ptr) \
    asm volatile("cp.async.cg.shared.global [%0], [%1], 16;" :: "r"(dst_u32), "l"(src_ptr) : "memory")
#define CP_COMMIT() asm volatile("cp.async.commit_group;" ::: "memory")
#define CP_WAIT1()  asm volatile("cp.async.wait_group 1;"  ::: "memory")
#define CP_WAIT0()  asm volatile("cp.async.wait_group 0;"  ::: "memory")

__device__ __forceinline__ uint32_t smem_u32(const void* p) {
    uint32_t a;
    asm("{ .reg .u64 t; cvta.to.shared.u64 t, %1; cvt.u32.u64 %0, t; }" : "=r"(a) : "l"(p));
    return a;
}

// ---------------------------------------------------------------------------
// Fused prepass: all fp32 -> tf32 conversions (+K-concat) in ONE kernel.
// ---------------------------------------------------------------------------
__global__ __launch_bounds__(256) void cvt_all(
    uint32_t* __restrict__ xmu, uint32_t* __restrict__ wqc,
    uint32_t* __restrict__ wkc, uint32_t* __restrict__ wvc,
    uint32_t* __restrict__ wot,
    const float* __restrict__ x,  const float* __restrict__ mu,
    const float* __restrict__ wq, const float* __restrict__ wmq,
    const float* __restrict__ wk, const float* __restrict__ wmk,
    const float* __restrict__ wv, const float* __restrict__ wmv,
    const float* __restrict__ wo)
{
    long e = ((long)blockIdx.x * 256 + threadIdx.x) * 4;
    const float *A, *B; uint32_t* D; long off; bool cat = true;
    if (e < 8388608L)       { D = xmu; A = x;  B = mu;  off = e; }
    else if (e < 16777216L) { D = wqc; A = wq; B = wmq; off = e - 8388608L; }
    else if (e < 18874368L) { D = wkc; A = wk; B = wmk; off = e - 16777216L; }
    else if (e < 20971520L) { D = wvc; A = wv; B = wmv; off = e - 18874368L; }
    else                    { D = wot; A = wo; B = wo;  off = e - 20971520L; cat = false; }

    float4 v;
    if (cat) {
        int r = (int)(off >> 12);
        int c = (int)(off & 4095);
        const float* src = (c < 2048) ? (A + (size_t)r * 2048 + c)
                                      : (B + (size_t)r * 2048 + (c - 2048));
        v = *(const float4*)src;
    } else {
        v = *(const float4*)(A + off);
    }
    *(uint4*)(D + off) = make_uint4(f2tf32(v.x), f2tf32(v.y), f2tf32(v.z), f2tf32(v.w));
}

// RoPE (cos,sin) table: only 2048 x 64 unique angles exist.
__global__ __launch_bounds__(64) void rope_table(float2* __restrict__ tab)
{
    const int pos = blockIdx.x;
    const int f = threadIdx.x;
    float ang = (float)pos * powf(10000.0f, -(float)f * (1.0f / 64.0f));
    float sn, cs;
    sincosf(ang, &sn, &cs);
    tab[pos * 64 + f] = make_float2(cs, sn);
}

// V half-sum: g_vt = tf32(v0 + v1), float4-vectorized
__global__ __launch_bounds__(256) void vsum(
    uint32_t* __restrict__ vt, const float* __restrict__ v0, const float* __restrict__ v1)
{
    long e = ((long)blockIdx.x * 256 + threadIdx.x) * 4;
    float4 a = *(const float4*)(v0 + e);
    float4 b = *(const float4*)(v1 + e);
    *(uint4*)(vt + e) = make_uint4(f2tf32(a.x + b.x), f2tf32(a.y + b.y),
                                   f2tf32(a.z + b.z), f2tf32(a.w + b.w));
}

// ---------------------------------------------------------------------------
// cp.async 3-stage tf32 GEMM core (XOR swizzle). Explicit lda/ldb (row strides
// in words) so halves of concatenated operands can be addressed directly.
// TRANSV epilogue writes fp32 transposed into CtF[(col0g+cc)*SEQ + row0g + r].
// ---------------------------------------------------------------------------
#define STG_WORDS 4096            /* 128*32 */
#define STAGE_WORDS (2*STG_WORDS) /* A+B */

template<bool TRANSV>
__device__ __forceinline__ void gemm_core_async(
    const uint32_t* __restrict__ Ablk, const uint32_t* __restrict__ Bblk,
    float* __restrict__ Cblk, int ldc,
    float* __restrict__ CtF, int row0g, int col0g,
    int K, int lda, int ldb, uint32_t* s)
{
    const uint32_t sbyte = smem_u32(s);
    const int tid = threadIdx.x;
    const int wid = tid >> 5, lane = tid & 31;
    const int g = lane >> 2, t = lane & 3;
    const int m0 = (wid >> 2) * 64;
    const int n0 = (wid & 3) * 32;

    const int lr = tid >> 3;
    const int ch = tid & 7;

    float acc[4][4][4];
#pragma unroll
    for (int i = 0; i < 4; ++i)
#pragma unroll
        for (int j = 0; j < 4; ++j)
#pragma unroll
            for (int q = 0; q < 4; ++q) acc[i][j][q] = 0.0f;

    const int nch = K >> 5;
    const int chsw = ch ^ (lr & 7);

    auto issue = [&](int st, int cc) {
        const uint32_t sa0 = sbyte + (uint32_t)(st * STAGE_WORDS) * 4u;
        const uint32_t sb0 = sa0 + STG_WORDS * 4u;
        const int kk = cc << 5;
#pragma unroll
        for (int i = 0; i < 4; ++i) {
            int r = lr + i * 32;
            uint32_t so = (uint32_t)(r * 32 + chsw * 4) * 4u;
            CP_ASYNC_CG(sa0 + so, Ablk + (size_t)r * lda + kk + ch * 4);
            CP_ASYNC_CG(sb0 + so, Bblk + (size_t)r * ldb + kk + ch * 4);
        }
    };

    issue(0, 0); CP_COMMIT();
    issue(1, 1); CP_COMMIT();

    for (int c = 0; c < nch; ++c) {
        CP_WAIT1();
        __syncthreads();
        if (c + 2 < nch) issue((c + 2) % 3, c + 2);
        CP_COMMIT();

        const uint32_t* sA = s + (c % 3) * STAGE_WORDS;
        const uint32_t* sB = sA + STG_WORDS;
#pragma unroll
        for (int ks = 0; ks < 4; ++ks) {
            const int e1 = (((2 * ks) ^ g) << 2) + t;
            const int e2 = (((2 * ks) ^ g ^ 1) << 2) + t;
            uint32_t af[4][4], bf[4][2];
#pragma unroll
            for (int mt = 0; mt < 4; ++mt) {
                int mr = m0 + mt * 16 + g;
                af[mt][0] = sA[mr * 32 + e1];
                af[mt][1] = sA[(mr + 8) * 32 + e1];
                af[mt][2] = sA[mr * 32 + e2];
                af[mt][3] = sA[(mr + 8) * 32 + e2];
            }
#pragma unroll
            for (int nt = 0; nt < 4; ++nt) {
                int nr = n0 + nt * 8 + g;
                bf[nt][0] = sB[nr * 32 + e1];
                bf[nt][1] = sB[nr * 32 + e2];
            }
#pragma unroll
            for (int mt = 0; mt < 4; ++mt)
#pragma unroll
                for (int nt = 0; nt < 4; ++nt)
                    mma_tf32(acc[mt][nt], af[mt], bf[nt]);
        }
    }

#pragma unroll
    for (int mt = 0; mt < 4; ++mt) {
        int r0 = m0 + mt * 16 + g;
#pragma unroll
        for (int nt = 0; nt < 4; ++nt) {
            int cc = n0 + nt * 8 + 2 * t;
            if (TRANSV) {
                CtF[(size_t)(col0g + cc)     * SEQ + row0g + r0]     = acc[mt][nt][0];
                CtF[(size_t)(col0g + cc + 1) * SEQ + row0g + r0]     = acc[mt][nt][1];
                CtF[(size_t)(col0g + cc)     * SEQ + row0g + r0 + 8] = acc[mt][nt][2];
                CtF[(size_t)(col0g + cc + 1) * SEQ + row0g + r0 + 8] = acc[mt][nt][3];
            } else {
                *(float2*)(Cblk + (size_t)r0 * ldc + cc)       = make_float2(acc[mt][nt][0], acc[mt][nt][1]);
                *(float2*)(Cblk + (size_t)(r0 + 8) * ldc + cc) = make_float2(acc[mt][nt][2], acc[mt][nt][3]);
            }
        }
    }
}

// Fused QKV, split-K by mu-decomposition: grid (48, 16).
// blockIdx.x: cb = x>>1 (column block 0..23), half = x&1 (0: x@W, 1: mu@Wm).
// cb 0..15 -> Q halves (fp32), 16..19 -> K halves (fp32),
// 20..23 -> V halves (fp32, transposed).
__global__ __launch_bounds__(256, 2) void qkv_mma(
    const uint32_t* __restrict__ xmu,
    const uint32_t* __restrict__ wqc, const uint32_t* __restrict__ wkc,
    const uint32_t* __restrict__ wvc,
    float* __restrict__ pq0, float* __restrict__ pq1,
    float* __restrict__ pk0, float* __restrict__ pk1,
    float* __restrict__ pv0, float* __restrict__ pv1)
{
    extern __shared__ uint32_t smem[];
    const int cb = blockIdx.x >> 1;
    const int half = blockIdx.x & 1;
    const int row0 = blockIdx.y * 128;
    const int koff = half * HID;   // offset into concatenated K range

    const uint32_t* A = xmu + (size_t)row0 * (2 * HID) + koff;

    if (cb < 20) {
        const uint32_t* B; float* C; int ldc, ccol;
        if (cb < 16) { B = wqc; C = half ? pq1 : pq0; ldc = QD;  ccol = cb * 128; }
        else         { B = wkc; C = half ? pk1 : pk0; ldc = KVD; ccol = (cb - 16) * 128; }
        gemm_core_async<false>(A, B + (size_t)ccol * (2 * HID) + koff,
                               C + (size_t)row0 * ldc + ccol, ldc,
                               nullptr, 0, 0, HID, 2 * HID, 2 * HID, smem);
    } else {
        const int ccol = (cb - 20) * 128;
        gemm_core_async<true>(A, wvc + (size_t)ccol * (2 * HID) + koff,
                              nullptr, 0, half ? pv1 : pv0, row0, ccol,
                              HID, 2 * HID, 2 * HID, smem);
    }
}

// Output projection: grid = (16, 16)
__global__ __launch_bounds__(256, 2) void oproj_mma(
    const uint32_t* __restrict__ A, const uint32_t* __restrict__ B, float* __restrict__ C)
{
    extern __shared__ uint32_t smem[];
    const int row0 = blockIdx.y * 128;
    const int ccol = blockIdx.x * 128;
    gemm_core_async<false>(A + (size_t)row0 * QD, B + (size_t)ccol * QD,
                           C + (size_t)row0 * QD + ccol, QD,
                           nullptr, 0, 0, QD, QD, QD, smem);
}

// ---------------------------------------------------------------------------
// Per-head RMSNorm + RoPE (table-based), summing the two split-K halves.
// Q: q0+q1 -> normed fp32 back into q0. K: k0+k1 -> tf32 bits.
// grid=(SEQ, NH+NKV), 128 thr
// ---------------------------------------------------------------------------
__global__ __launch_bounds__(128) void normrope_kernel(
    float* __restrict__ qb0, const float* __restrict__ qb1,
    const float* __restrict__ kb0, const float* __restrict__ kb1,
    uint32_t* __restrict__ kt,
    const float* __restrict__ qw, const float* __restrict__ kw,
    const float2* __restrict__ rope)
{
    const int pos = blockIdx.x;
    const int hh = blockIdx.y;
    const int d = threadIdx.x;

    const bool isq = (hh < NH);
    int stride = isq ? QD : KVD;
    int col0 = isq ? hh * HD : (hh - NH) * HD;
    const float* w = isq ? qw : kw;
    const size_t idx = (size_t)pos * stride + col0 + d;

    float x = isq ? (qb0[idx] + qb1[idx]) : (kb0[idx] + kb1[idx]);

    float ss = x * x;
#pragma unroll
    for (int off = 16; off; off >>= 1) ss += __shfl_xor_sync(0xffffffffu, ss, off);

    __shared__ float red[4];
    __shared__ float xs[128];
    if ((d & 31) == 0) red[d >> 5] = ss;
    __syncthreads();
    ss = red[0] + red[1] + red[2] + red[3];

    float xn = x * rsqrtf(ss * (1.0f / 128.0f) + 1e-6f) * w[d];
    xs[d] = xn;
    __syncthreads();
    float rot = (d < 64) ? -xs[d + 64] : xs[d - 64];

    float2 cs = rope[pos * 64 + (d & 63)];
    float r = xn * cs.x + rot * cs.y;
    if (isq) qb0[idx] = r;
    else     kt[idx] = f2tf32(r);
}

// ---------------------------------------------------------------------------
// Tensor-core causal flash attention (tf32 mma), cp.async double-buffered K/V.
// (unchanged from R8/R10 best)
// ---------------------------------------------------------------------------
#define ATTN_SMEM_WORDS 41984

__global__ __launch_bounds__(256, 1) void attn_mma(
    const float* __restrict__ q, const uint32_t* __restrict__ kt,
    const uint32_t* __restrict__ vt, uint32_t* __restrict__ o)
{
    extern __shared__ uint32_t sw[];
    uint32_t* sP = sw + 32768;    // [128][72]
    uint32_t* sQ = sw + 16384;    // staging [128][136]
    const uint32_t sbyte = smem_u32(sw);

    const int qt = gridDim.x - 1 - blockIdx.x;   // heavy tiles first
    const int h = blockIdx.y;
    const int kvh = h >> 2;
    const int qrow0 = qt * 128;
    const int tid = threadIdx.x;
    const int w = tid >> 5, lane = tid & 31;
    const int gg = lane >> 2, t = lane & 3;
    const int m0 = w * 16;
    const int jmax = 2 * qt + 2;
    const int rmax = qrow0 + m0 + 15;

    auto issueKV = [&](int b, int jt) {
        const uint32_t kb0 = sbyte + (uint32_t)(b ? 16384 : 0) * 4u;
        const uint32_t vb0 = kb0 + 8192u * 4u;
#pragma unroll
        for (int i = 0; i < 8; ++i) {
            int id = tid + i * 256;
            int r = id >> 5, c = id & 31;
            int cs = (c & 24) | ((c & 7) ^ (r & 7));
            CP_ASYNC_CG(kb0 + (uint32_t)(r * 128 + cs * 4) * 4u,
                        kt + (size_t)(jt * 64 + r) * KVD + kvh * HD + c * 4);
        }
#pragma unroll
        for (int i = 0; i < 8; ++i) {
            int id = tid + i * 256;
            int r = id >> 4, c = id & 15;
            int cs = (c & 8) | ((c & 7) ^ (r & 7));
            CP_ASYNC_CG(vb0 + (uint32_t)(r * 64 + cs * 4) * 4u,
                        vt + (size_t)(kvh * HD + r) * SEQ + jt * 64 + c * 4);
        }
    };

    issueKV(0, 0); CP_COMMIT();

#pragma unroll
    for (int i = 0; i < 16; ++i) {
        int id = tid + i * 256;
        int r = id >> 5, c4 = id & 31, c = c4 * 4;
        float4 val = *(const float4*)(q + (size_t)(qrow0 + r) * QD + h * HD + c);
        uint32_t base = (uint32_t)(r * 136 + (c >> 3) * 8 + ((c >> 2) & 1));
        sQ[base + 0] = f2tf32(val.x);
        sQ[base + 2] = f2tf32(val.y);
        sQ[base + 4] = f2tf32(val.z);
        sQ[base + 6] = f2tf32(val.w);
    }
    __syncthreads();

    uint32_t qf[16][4];
#pragma unroll
    for (int ks = 0; ks < 16; ++ks) {
        uint2 q0 = *(const uint2*)&sQ[(m0 + gg) * 136 + ks * 8 + 2 * t];
        uint2 q1 = *(const uint2*)&sQ[(m0 + gg + 8) * 136 + ks * 8 + 2 * t];
        qf[ks][0] = q0.x; qf[ks][1] = q1.x; qf[ks][2] = q0.y; qf[ks][3] = q1.y;
    }

    float oacc[16][4];
#pragma unroll
    for (int i = 0; i < 16; ++i)
#pragma unroll
        for (int j = 0; j < 4; ++j) oacc[i][j] = 0.0f;
    float mrow0 = -1e30f, mrow1 = -1e30f, lrow0 = 0.0f, lrow1 = 0.0f;

    const float scale = 0.08838834764831845f;

    for (int jt = 0; jt < jmax; ++jt) {
        CP_WAIT0();
        __syncthreads();
        if (jt + 1 < jmax) { issueKV((jt + 1) & 1, jt + 1); CP_COMMIT(); }

        const uint32_t* sK = sw + ((jt & 1) ? 16384 : 0);
        const uint32_t* sV = sK + 8192;

        const bool edge = (jt >= 2 * qt);
        const bool active = (jt * 64 <= rmax);
        if (active) {
            float sacc[8][4];
#pragma unroll
            for (int i = 0; i < 8; ++i)
#pragma unroll
                for (int j = 0; j < 4; ++j) sacc[i][j] = 0.0f;

            if (!edge) {
#pragma unroll
                for (int ks = 0; ks < 16; ++ks) {
                    const int c0 = ((2 * ks) & 24) | (((2 * ks) & 7) ^ gg);
                    const int c1 = ((2 * ks) & 24) | ((((2 * ks) & 7) ^ 1) ^ gg);
#pragma unroll
                    for (int nt = 0; nt < 8; ++nt) {
                        int nr = nt * 8 + gg;
                        mma_tf32_2(sacc[nt], qf[ks],
                                   sK[nr * 128 + c0 * 4 + t], sK[nr * 128 + c1 * 4 + t]);
                    }
                }
            } else {
#pragma unroll
                for (int nt = 0; nt < 8; ++nt) {
                    if (jt * 64 + nt * 8 <= rmax) {
                        const int nr = nt * 8 + gg;
#pragma unroll
                        for (int ks = 0; ks < 16; ++ks) {
                            const int c0 = ((2 * ks) & 24) | (((2 * ks) & 7) ^ gg);
                            const int c1 = ((2 * ks) & 24) | ((((2 * ks) & 7) ^ 1) ^ gg);
                            mma_tf32_2(sacc[nt], qf[ks],
                                       sK[nr * 128 + c0 * 4 + t], sK[nr * 128 + c1 * 4 + t]);
                        }
                    }
                }
            }

            const int r0 = qrow0 + m0 + gg;
            const int r1 = r0 + 8;
            float rm0 = -1e30f, rm1 = -1e30f;
#pragma unroll
            for (int nt = 0; nt < 8; ++nt) {
                float c0 = sacc[nt][0] * scale, c1 = sacc[nt][1] * scale;
                float c2 = sacc[nt][2] * scale, c3 = sacc[nt][3] * scale;
                if (edge) {
                    int colb = jt * 64 + nt * 8 + 2 * t;
                    if (colb     > r0) c0 = -1e30f;
                    if (colb + 1 > r0) c1 = -1e30f;
                    if (colb     > r1) c2 = -1e30f;
                    if (colb + 1 > r1) c3 = -1e30f;
                }
                sacc[nt][0] = c0; sacc[nt][1] = c1; sacc[nt][2] = c2; sacc[nt][3] = c3;
                rm0 = fmaxf(rm0, fmaxf(c0, c1));
                rm1 = fmaxf(rm1, fmaxf(c2, c3));
            }
            rm0 = fmaxf(rm0, __shfl_xor_sync(0xffffffffu, rm0, 1));
            rm0 = fmaxf(rm0, __shfl_xor_sync(0xffffffffu, rm0, 2));
            rm1 = fmaxf(rm1, __shfl_xor_sync(0xffffffffu, rm1, 1));
            rm1 = fmaxf(rm1, __shfl_xor_sync(0xffffffffu, rm1, 2));

            float mn0 = fmaxf(mrow0, rm0), mn1 = fmaxf(mrow1, rm1);
            float al0 = __expf(mrow0 - mn0), al1 = __expf(mrow1 - mn1);
            mrow0 = mn0; mrow1 = mn1;

            const uint32_t pA = (uint32_t)(((2 * t) & 3) * 2 + ((t >> 1) & 1));
            const uint32_t pb0 = (uint32_t)((m0 + gg) * 72) + pA;
            const uint32_t pb1 = pb0 + 8 * 72;
            float rs0 = 0.0f, rs1 = 0.0f;
#pragma unroll
            for (int nt = 0; nt < 8; ++nt) {
                float p0 = __expf(sacc[nt][0] - mn0);
                float p1 = __expf(sacc[nt][1] - mn0);
                float p2 = __expf(sacc[nt][2] - mn1);
                float p3 = __expf(sacc[nt][3] - mn1);
                rs0 += p0 + p1; rs1 += p2 + p3;
                sP[pb0 + nt * 8]     = f2tf32(p0);
                sP[pb0 + nt * 8 + 2] = f2tf32(p1);
                sP[pb1 + nt * 8]     = f2tf32(p2);
                sP[pb1 + nt * 8 + 2] = f2tf32(p3);
            }
            rs0 += __shfl_xor_sync(0xffffffffu, rs0, 1);
            rs0 += __shfl_xor_sync(0xffffffffu, rs0, 2);
            rs1 += __shfl_xor_sync(0xffffffffu, rs1, 1);
            rs1 += __shfl_xor_sync(0xffffffffu, rs1, 2);
            lrow0 = lrow0 * al0 + rs0;
            lrow1 = lrow1 * al1 + rs1;

#pragma unroll
            for (int nt = 0; nt < 16; ++nt) {
                oacc[nt][0] *= al0; oacc[nt][1] *= al0;
                oacc[nt][2] *= al1; oacc[nt][3] *= al1;
            }
            __syncwarp();

            if (!edge) {
#pragma unroll
                for (int ks = 0; ks < 8; ++ks) {
                    const int c0 = ((2 * ks) & 8) | (((2 * ks) & 7) ^ gg);
                    const int c1 = ((2 * ks) & 8) | ((((2 * ks) & 7) ^ 1) ^ gg);
                    uint2 pa0 = *(const uint2*)&sP[(m0 + gg) * 72 + ks * 8 + 2 * t];
                    uint2 pa1 = *(const uint2*)&sP[(m0 + gg + 8) * 72 + ks * 8 + 2 * t];
                    uint32_t a[4] = {pa0.x, pa1.x, pa0.y, pa1.y};
#pragma unroll
                    for (int nt = 0; nt < 16; ++nt) {
                        int nr = nt * 8 + gg;
                        mma_tf32_2(oacc[nt], a,
                                   sV[nr * 64 + c0 * 4 + t], sV[nr * 64 + c1 * 4 + t]);
                    }
                }
            } else {
#pragma unroll
                for (int ks = 0; ks < 8; ++ks) {
                    if (jt * 64 + ks * 8 <= rmax) {
                        const int c0 = ((2 * ks) & 8) | (((2 * ks) & 7) ^ gg);
                        const int c1 = ((2 * ks) & 8) | ((((2 * ks) & 7) ^ 1) ^ gg);
                        uint2 pa0 = *(const uint2*)&sP[(m0 + gg) * 72 + ks * 8 + 2 * t];
                        uint2 pa1 = *(const uint2*)&sP[(m0 + gg + 8) * 72 + ks * 8 + 2 * t];
                        uint32_t a[4] = {pa0.x, pa1.x, pa0.y, pa1.y};
#pragma unroll
                        for (int nt = 0; nt < 16; ++nt) {
                            int nr = nt * 8 + gg;
                            mma_tf32_2(oacc[nt], a,
                                       sV[nr * 64 + c0 * 4 + t], sV[nr * 64 + c1 * 4 + t]);
                        }
                    }
                }
            }
        }
    }

    const float inv0 = 1.0f / lrow0, inv1 = 1.0f / lrow1;
    const int r0 = qrow0 + m0 + gg;
#pragma unroll
    for (int nt = 0; nt < 16; ++nt) {
        int cc = h * HD + nt * 8 + 2 * t;
        *(uint2*)(o + (size_t)r0 * QD + cc) =
            make_uint2(f2tf32(oacc[nt][0] * inv0), f2tf32(oacc[nt][1] * inv0));
        *(uint2*)(o + (size_t)(r0 + 8) * QD + cc) =
            make_uint2(f2tf32(oacc[nt][2] * inv1), f2tf32(oacc[nt][3] * inv1));
    }
}

// ---------------------------------------------------------------------------
extern "C" void kernel_launch(void* const* d_in, const int* in_sizes, int n_in,
                              void* d_out, int out_size)
{
    (void)in_sizes; (void)n_in; (void)out_size;
    const float* x   = (const float*)d_in[0];
    const float* mu  = (const float*)d_in[1];
    const float* wq  = (const float*)d_in[2];
    const float* wk  = (const float*)d_in[3];
    const float* wv  = (const float*)d_in[4];
    const float* wo  = (const float*)d_in[5];
    const float* wmq = (const float*)d_in[6];
    const float* wmk = (const float*)d_in[7];
    const float* wmv = (const float*)d_in[8];
    const float* qw  = (const float*)d_in[9];
    const float* kw  = (const float*)d_in[10];
    float* out = (float*)d_out;

    float *pq0, *pq1, *pk0, *pk1, *pv0, *pv1;
    uint32_t *pkt, *pvt, *po;
    uint32_t *pxmu, *pwqc, *pwkc, *pwvc, *pwot;
    float2 *prope;
    cudaGetSymbolAddress((void**)&pq0, g_q);
    cudaGetSymbolAddress((void**)&pq1, g_q1);
    cudaGetSymbolAddress((void**)&pk0, g_k);
    cudaGetSymbolAddress((void**)&pk1, g_k1);
    cudaGetSymbolAddress((void**)&pv0, g_v0);
    cudaGetSymbolAddress((void**)&pv1, g_v1);
    cudaGetSymbolAddress((void**)&pkt, g_kt);
    cudaGetSymbolAddress((void**)&pvt, g_vt);
    cudaGetSymbolAddress((void**)&po, g_o);
    cudaGetSymbolAddress((void**)&pxmu, g_xmu);
    cudaGetSymbolAddress((void**)&pwqc, g_wqc);
    cudaGetSymbolAddress((void**)&pwkc, g_wkc);
    cudaGetSymbolAddress((void**)&pwvc, g_wvc);
    cudaGetSymbolAddress((void**)&pwot, g_wot);
    cudaGetSymbolAddress((void**)&prope, g_rope);

    // ---- fused prepass ----
    rope_table<<<SEQ, 64>>>(prope);
    cvt_all<<<24576, 256>>>(pxmu, pwqc, pwkc, pwvc, pwot,
                            x, mu, wq, wmq, wk, wmk, wv, wmv, wo);

    const int gemm_smem = 3 * STAGE_WORDS * 4;  // 98304 bytes
    cudaFuncSetAttribute(qkv_mma,   cudaFuncAttributeMaxDynamicSharedMemorySize, gemm_smem);
    cudaFuncSetAttribute(oproj_mma, cudaFuncAttributeMaxDynamicSharedMemorySize, gemm_smem);

    // Fused QKV projections, split-K (x/mu halves) -> 768 CTAs for wave balance
    qkv_mma<<<dim3(48, 16), 256, gemm_smem>>>(pxmu, pwqc, pwkc, pwvc,
                                              pq0, pq1, pk0, pk1, pv0, pv1);

    // V halves -> tf32 transposed
    vsum<<<(KVD * SEQ) / 1024, 256>>>(pvt, pv0, pv1);

    // per-head RMSNorm + RoPE (table), summing Q/K halves; K emitted as tf32
    normrope_kernel<<<dim3(SEQ, NH + NKV), 128>>>(pq0, pq1, pk0, pk1, pkt, qw, kw, prope);

    // causal GQA attention (tf32, cp.async double-buffered K/V)
    const int attn_smem = ATTN_SMEM_WORDS * 4;  // 167936 bytes
    cudaFuncSetAttribute(attn_mma, cudaFuncAttributeMaxDynamicSharedMemorySize, attn_smem);
    attn_mma<<<dim3(SEQ / 128, NH), 256, attn_smem>>>(pq0, pkt, pvt, po);

    // output projection (tf32, cp.async pipelined, 2 CTAs/SM)
    oproj_mma<<<dim3(16, 16), 256, gemm_smem>>>(po, pwot, out);
}

// round 12
// speedup vs baseline: 1.1151x; 1.0536x over previous
#include <cuda_runtime.h>
#include <math.h>
#include <stdint.h>

#define SEQ 2048
#define HID 2048
#define NH 16
#define NKV 4
#define HD 128
#define QD (NH*HD)    /* 2048 */
#define KVD (NKV*HD)  /* 512  */

// Scratch (device globals: no allocations allowed)
__device__ float    g_q[SEQ*QD];             // Q half0 (x@Wq), then normed Q
__device__ float    g_q1[SEQ*QD];            // Q half1 (mu@Wmq)
__device__ float    g_k[SEQ*KVD];            // K half0
__device__ float    g_k1[SEQ*KVD];           // K half1
__device__ float    g_v0[KVD*SEQ];           // V half0, fp32 transposed
__device__ float    g_v1[KVD*SEQ];           // V half1, fp32 transposed
__device__ uint32_t g_kt[SEQ*KVD];           // tf32 K (post-normrope)
__device__ uint32_t g_vt[KVD*SEQ];           // tf32 V, transposed [kvd][seq]
__device__ uint32_t g_o[SEQ*QD];             // attention output as tf32 bits
__device__ float2   g_rope[SEQ*64];          // (cos, sin) per (pos, freq)
// Pre-converted tf32-bit operands (prepass)
__device__ uint32_t g_xmu[SEQ*2*HID];        // [x | mu]  2048 x 4096
__device__ uint32_t g_wqc[QD*2*HID];         // [wq | wmq] 2048 x 4096
__device__ uint32_t g_wkc[KVD*2*HID];        // [wk | wmk]  512 x 4096
__device__ uint32_t g_wvc[KVD*2*HID];        // [wv | wmv]  512 x 4096
__device__ uint32_t g_wot[HID*QD];           // wo         2048 x 2048

// ---------------------------------------------------------------------------
// tf32 helpers (plain sm_80+ PTX — no sm_103a-gated instructions)
// ---------------------------------------------------------------------------
__device__ __forceinline__ uint32_t f2tf32(float x) {
    uint32_t r;
    asm("cvt.rna.tf32.f32 %0, %1;" : "=r"(r) : "f"(x));
    return r;
}

__device__ __forceinline__ void mma_tf32(float d[4], const uint32_t a[4], const uint32_t b[2]) {
    asm volatile(
        "mma.sync.aligned.m16n8k8.row.col.f32.tf32.tf32.f32 "
        "{%0,%1,%2,%3}, {%4,%5,%6,%7}, {%8,%9}, {%0,%1,%2,%3};"
        : "+f"(d[0]), "+f"(d[1]), "+f"(d[2]), "+f"(d[3])
        : "r"(a[0]), "r"(a[1]), "r"(a[2]), "r"(a[3]), "r"(b[0]), "r"(b[1]));
}

__device__ __forceinline__ void mma_tf32_2(float d[4], const uint32_t a[4],
                                           uint32_t b0, uint32_t b1) {
    asm volatile(
        "mma.sync.aligned.m16n8k8.row.col.f32.tf32.tf32.f32 "
        "{%0,%1,%2,%3}, {%4,%5,%6,%7}, {%8,%9}, {%0,%1,%2,%3};"
        : "+f"(d[0]), "+f"(d[1]), "+f"(d[2]), "+f"(d[3])
        : "r"(a[0]), "r"(a[1]), "r"(a[2]), "r"(a[3]), "r"(b0), "r"(b1));
}

#define CP_ASYNC_CG(dst_u32, src_ptr) \
    asm volatile("cp.async.cg.shared.global [%0], [%1], 16;" :: "r"(dst_u32), "l"(src_ptr) : "memory")
#define CP_COMMIT() asm volatile("cp.async.commit_group;" ::: "memory")
#define CP_WAIT1()  asm volatile("cp.async.wait_group 1;"  ::: "memory")
#define CP_WAIT0()  asm volatile("cp.async.wait_group 0;"  ::: "memory")

__device__ __forceinline__ uint32_t smem_u32(const void* p) {
    uint32_t a;
    asm("{ .reg .u64 t; cvta.to.shared.u64 t, %1; cvt.u32.u64 %0, t; }" : "=r"(a) : "l"(p));
    return a;
}

// ---------------------------------------------------------------------------
// Fused prepass: all fp32 -> tf32 conversions (+K-concat) in ONE kernel.
// ---------------------------------------------------------------------------
__global__ __launch_bounds__(256) void cvt_all(
    uint32_t* __restrict__ xmu, uint32_t* __restrict__ wqc,
    uint32_t* __restrict__ wkc, uint32_t* __restrict__ wvc,
    uint32_t* __restrict__ wot,
    const float* __restrict__ x,  const float* __restrict__ mu,
    const float* __restrict__ wq, const float* __restrict__ wmq,
    const float* __restrict__ wk, const float* __restrict__ wmk,
    const float* __restrict__ wv, const float* __restrict__ wmv,
    const float* __restrict__ wo)
{
    long e = ((long)blockIdx.x * 256 + threadIdx.x) * 4;
    const float *A, *B; uint32_t* D; long off; bool cat = true;
    if (e < 8388608L)       { D = xmu; A = x;  B = mu;  off = e; }
    else if (e < 16777216L) { D = wqc; A = wq; B = wmq; off = e - 8388608L; }
    else if (e < 18874368L) { D = wkc; A = wk; B = wmk; off = e - 16777216L; }
    else if (e < 20971520L) { D = wvc; A = wv; B = wmv; off = e - 18874368L; }
    else                    { D = wot; A = wo; B = wo;  off = e - 20971520L; cat = false; }

    float4 v;
    if (cat) {
        int r = (int)(off >> 12);
        int c = (int)(off & 4095);
        const float* src = (c < 2048) ? (A + (size_t)r * 2048 + c)
                                      : (B + (size_t)r * 2048 + (c - 2048));
        v = *(const float4*)src;
    } else {
        v = *(const float4*)(A + off);
    }
    *(uint4*)(D + off) = make_uint4(f2tf32(v.x), f2tf32(v.y), f2tf32(v.z), f2tf32(v.w));
}

// RoPE (cos,sin) table: only 2048 x 64 unique angles exist.
__global__ __launch_bounds__(64) void rope_table(float2* __restrict__ tab)
{
    const int pos = blockIdx.x;
    const int f = threadIdx.x;
    float ang = (float)pos * powf(10000.0f, -(float)f * (1.0f / 64.0f));
    float sn, cs;
    sincosf(ang, &sn, &cs);
    tab[pos * 64 + f] = make_float2(cs, sn);
}

// V half-sum: g_vt = tf32(v0 + v1), float4-vectorized
__global__ __launch_bounds__(256) void vsum(
    uint32_t* __restrict__ vt, const float* __restrict__ v0, const float* __restrict__ v1)
{
    long e = ((long)blockIdx.x * 256 + threadIdx.x) * 4;
    float4 a = *(const float4*)(v0 + e);
    float4 b = *(const float4*)(v1 + e);
    *(uint4*)(vt + e) = make_uint4(f2tf32(a.x + b.x), f2tf32(a.y + b.y),
                                   f2tf32(a.z + b.z), f2tf32(a.w + b.w));
}

// ---------------------------------------------------------------------------
// cp.async 3-stage tf32 GEMM core (XOR swizzle), 128 threads, warp tile 64x64
// (2x2 warps cover the 128x128 CTA tile). Halves fragment LDS traffic per mma
// vs the 8-warp 64x32 variant (crossbar was the bottleneck).
// ---------------------------------------------------------------------------
#define STG_WORDS 4096            /* 128*32 */
#define STAGE_WORDS (2*STG_WORDS) /* A+B */

template<bool TRANSV>
__device__ __forceinline__ void gemm_core_async(
    const uint32_t* __restrict__ Ablk, const uint32_t* __restrict__ Bblk,
    float* __restrict__ Cblk, int ldc,
    float* __restrict__ CtF, int row0g, int col0g,
    int K, int lda, int ldb, uint32_t* s)
{
    const uint32_t sbyte = smem_u32(s);
    const int tid = threadIdx.x;
    const int wid = tid >> 5, lane = tid & 31;
    const int g = lane >> 2, t = lane & 3;
    const int m0 = (wid >> 1) * 64;
    const int n0 = (wid & 1) * 64;

    const int lr = tid >> 3;          // 0..15: base row
    const int ch = tid & 7;           // 16B chunk 0..7

    float acc[4][8][4];
#pragma unroll
    for (int i = 0; i < 4; ++i)
#pragma unroll
        for (int j = 0; j < 8; ++j)
#pragma unroll
            for (int q = 0; q < 4; ++q) acc[i][j][q] = 0.0f;

    const int nch = K >> 5;
    const int chsw = ch ^ (lr & 7);

    auto issue = [&](int st, int cc) {
        const uint32_t sa0 = sbyte + (uint32_t)(st * STAGE_WORDS) * 4u;
        const uint32_t sb0 = sa0 + STG_WORDS * 4u;
        const int kk = cc << 5;
#pragma unroll
        for (int i = 0; i < 8; ++i) {
            int r = lr + i * 16;
            uint32_t so = (uint32_t)(r * 32 + chsw * 4) * 4u;
            CP_ASYNC_CG(sa0 + so, Ablk + (size_t)r * lda + kk + ch * 4);
            CP_ASYNC_CG(sb0 + so, Bblk + (size_t)r * ldb + kk + ch * 4);
        }
    };

    issue(0, 0); CP_COMMIT();
    issue(1, 1); CP_COMMIT();

    for (int c = 0; c < nch; ++c) {
        CP_WAIT1();
        __syncthreads();
        if (c + 2 < nch) issue((c + 2) % 3, c + 2);
        CP_COMMIT();

        const uint32_t* sA = s + (c % 3) * STAGE_WORDS;
        const uint32_t* sB = sA + STG_WORDS;
#pragma unroll
        for (int ks = 0; ks < 4; ++ks) {
            const int e1 = (((2 * ks) ^ g) << 2) + t;
            const int e2 = (((2 * ks) ^ g ^ 1) << 2) + t;
            uint32_t af[4][4], bf[8][2];
#pragma unroll
            for (int mt = 0; mt < 4; ++mt) {
                int mr = m0 + mt * 16 + g;
                af[mt][0] = sA[mr * 32 + e1];
                af[mt][1] = sA[(mr + 8) * 32 + e1];
                af[mt][2] = sA[mr * 32 + e2];
                af[mt][3] = sA[(mr + 8) * 32 + e2];
            }
#pragma unroll
            for (int nt = 0; nt < 8; ++nt) {
                int nr = n0 + nt * 8 + g;
                bf[nt][0] = sB[nr * 32 + e1];
                bf[nt][1] = sB[nr * 32 + e2];
            }
#pragma unroll
            for (int mt = 0; mt < 4; ++mt)
#pragma unroll
                for (int nt = 0; nt < 8; ++nt)
                    mma_tf32(acc[mt][nt], af[mt], bf[nt]);
        }
    }

#pragma unroll
    for (int mt = 0; mt < 4; ++mt) {
        int r0 = m0 + mt * 16 + g;
#pragma unroll
        for (int nt = 0; nt < 8; ++nt) {
            int cc = n0 + nt * 8 + 2 * t;
            if (TRANSV) {
                CtF[(size_t)(col0g + cc)     * SEQ + row0g + r0]     = acc[mt][nt][0];
                CtF[(size_t)(col0g + cc + 1) * SEQ + row0g + r0]     = acc[mt][nt][1];
                CtF[(size_t)(col0g + cc)     * SEQ + row0g + r0 + 8] = acc[mt][nt][2];
                CtF[(size_t)(col0g + cc + 1) * SEQ + row0g + r0 + 8] = acc[mt][nt][3];
            } else {
                *(float2*)(Cblk + (size_t)r0 * ldc + cc)       = make_float2(acc[mt][nt][0], acc[mt][nt][1]);
                *(float2*)(Cblk + (size_t)(r0 + 8) * ldc + cc) = make_float2(acc[mt][nt][2], acc[mt][nt][3]);
            }
        }
    }
}

// Fused QKV, split-K by mu-decomposition: grid (48, 16), 128 threads.
__global__ __launch_bounds__(128, 2) void qkv_mma(
    const uint32_t* __restrict__ xmu,
    const uint32_t* __restrict__ wqc, const uint32_t* __restrict__ wkc,
    const uint32_t* __restrict__ wvc,
    float* __restrict__ pq0, float* __restrict__ pq1,
    float* __restrict__ pk0, float* __restrict__ pk1,
    float* __restrict__ pv0, float* __restrict__ pv1)
{
    extern __shared__ uint32_t smem[];
    const int cb = blockIdx.x >> 1;
    const int half = blockIdx.x & 1;
    const int row0 = blockIdx.y * 128;
    const int koff = half * HID;

    const uint32_t* A = xmu + (size_t)row0 * (2 * HID) + koff;

    if (cb < 20) {
        const uint32_t* B; float* C; int ldc, ccol;
        if (cb < 16) { B = wqc; C = half ? pq1 : pq0; ldc = QD;  ccol = cb * 128; }
        else         { B = wkc; C = half ? pk1 : pk0; ldc = KVD; ccol = (cb - 16) * 128; }
        gemm_core_async<false>(A, B + (size_t)ccol * (2 * HID) + koff,
                               C + (size_t)row0 * ldc + ccol, ldc,
                               nullptr, 0, 0, HID, 2 * HID, 2 * HID, smem);
    } else {
        const int ccol = (cb - 20) * 128;
        gemm_core_async<true>(A, wvc + (size_t)ccol * (2 * HID) + koff,
                              nullptr, 0, half ? pv1 : pv0, row0, ccol,
                              HID, 2 * HID, 2 * HID, smem);
    }
}

// Output projection: grid = (16, 16), 128 threads
__global__ __launch_bounds__(128, 2) void oproj_mma(
    const uint32_t* __restrict__ A, const uint32_t* __restrict__ B, float* __restrict__ C)
{
    extern __shared__ uint32_t smem[];
    const int row0 = blockIdx.y * 128;
    const int ccol = blockIdx.x * 128;
    gemm_core_async<false>(A + (size_t)row0 * QD, B + (size_t)ccol * QD,
                           C + (size_t)row0 * QD + ccol, QD,
                           nullptr, 0, 0, QD, QD, QD, smem);
}

// ---------------------------------------------------------------------------
// Per-head RMSNorm + RoPE (table-based), summing the two split-K halves.
// ---------------------------------------------------------------------------
__global__ __launch_bounds__(128) void normrope_kernel(
    float* __restrict__ qb0, const float* __restrict__ qb1,
    const float* __restrict__ kb0, const float* __restrict__ kb1,
    uint32_t* __restrict__ kt,
    const float* __restrict__ qw, const float* __restrict__ kw,
    const float2* __restrict__ rope)
{
    const int pos = blockIdx.x;
    const int hh = blockIdx.y;
    const int d = threadIdx.x;

    const bool isq = (hh < NH);
    int stride = isq ? QD : KVD;
    int col0 = isq ? hh * HD : (hh - NH) * HD;
    const float* w = isq ? qw : kw;
    const size_t idx = (size_t)pos * stride + col0 + d;

    float x = isq ? (qb0[idx] + qb1[idx]) : (kb0[idx] + kb1[idx]);

    float ss = x * x;
#pragma unroll
    for (int off = 16; off; off >>= 1) ss += __shfl_xor_sync(0xffffffffu, ss, off);

    __shared__ float red[4];
    __shared__ float xs[128];
    if ((d & 31) == 0) red[d >> 5] = ss;
    __syncthreads();
    ss = red[0] + red[1] + red[2] + red[3];

    float xn = x * rsqrtf(ss * (1.0f / 128.0f) + 1e-6f) * w[d];
    xs[d] = xn;
    __syncthreads();
    float rot = (d < 64) ? -xs[d + 64] : xs[d - 64];

    float2 cs = rope[pos * 64 + (d & 63)];
    float r = xn * cs.x + rot * cs.y;
    if (isq) qb0[idx] = r;
    else     kt[idx] = f2tf32(r);
}

// ---------------------------------------------------------------------------
// Tensor-core causal flash attention (tf32 mma), cp.async double-buffered K/V.
// (unchanged from R8/R10 best)
// ---------------------------------------------------------------------------
#define ATTN_SMEM_WORDS 41984

__global__ __launch_bounds__(256, 1) void attn_mma(
    const float* __restrict__ q, const uint32_t* __restrict__ kt,
    const uint32_t* __restrict__ vt, uint32_t* __restrict__ o)
{
    extern __shared__ uint32_t sw[];
    uint32_t* sP = sw + 32768;    // [128][72]
    uint32_t* sQ = sw + 16384;    // staging [128][136]
    const uint32_t sbyte = smem_u32(sw);

    const int qt = gridDim.x - 1 - blockIdx.x;   // heavy tiles first
    const int h = blockIdx.y;
    const int kvh = h >> 2;
    const int qrow0 = qt * 128;
    const int tid = threadIdx.x;
    const int w = tid >> 5, lane = tid & 31;
    const int gg = lane >> 2, t = lane & 3;
    const int m0 = w * 16;
    const int jmax = 2 * qt + 2;
    const int rmax = qrow0 + m0 + 15;

    auto issueKV = [&](int b, int jt) {
        const uint32_t kb0 = sbyte + (uint32_t)(b ? 16384 : 0) * 4u;
        const uint32_t vb0 = kb0 + 8192u * 4u;
#pragma unroll
        for (int i = 0; i < 8; ++i) {
            int id = tid + i * 256;
            int r = id >> 5, c = id & 31;
            int cs = (c & 24) | ((c & 7) ^ (r & 7));
            CP_ASYNC_CG(kb0 + (uint32_t)(r * 128 + cs * 4) * 4u,
                        kt + (size_t)(jt * 64 + r) * KVD + kvh * HD + c * 4);
        }
#pragma unroll
        for (int i = 0; i < 8; ++i) {
            int id = tid + i * 256;
            int r = id >> 4, c = id & 15;
            int cs = (c & 8) | ((c & 7) ^ (r & 7));
            CP_ASYNC_CG(vb0 + (uint32_t)(r * 64 + cs * 4) * 4u,
                        vt + (size_t)(kvh * HD + r) * SEQ + jt * 64 + c * 4);
        }
    };

    issueKV(0, 0); CP_COMMIT();

#pragma unroll
    for (int i = 0; i < 16; ++i) {
        int id = tid + i * 256;
        int r = id >> 5, c4 = id & 31, c = c4 * 4;
        float4 val = *(const float4*)(q + (size_t)(qrow0 + r) * QD + h * HD + c);
        uint32_t base = (uint32_t)(r * 136 + (c >> 3) * 8 + ((c >> 2) & 1));
        sQ[base + 0] = f2tf32(val.x);
        sQ[base + 2] = f2tf32(val.y);
        sQ[base + 4] = f2tf32(val.z);
        sQ[base + 6] = f2tf32(val.w);
    }
    __syncthreads();

    uint32_t qf[16][4];
#pragma unroll
    for (int ks = 0; ks < 16; ++ks) {
        uint2 q0 = *(const uint2*)&sQ[(m0 + gg) * 136 + ks * 8 + 2 * t];
        uint2 q1 = *(const uint2*)&sQ[(m0 + gg + 8) * 136 + ks * 8 + 2 * t];
        qf[ks][0] = q0.x; qf[ks][1] = q1.x; qf[ks][2] = q0.y; qf[ks][3] = q1.y;
    }

    float oacc[16][4];
#pragma unroll
    for (int i = 0; i < 16; ++i)
#pragma unroll
        for (int j = 0; j < 4; ++j) oacc[i][j] = 0.0f;
    float mrow0 = -1e30f, mrow1 = -1e30f, lrow0 = 0.0f, lrow1 = 0.0f;

    const float scale = 0.08838834764831845f;

    for (int jt = 0; jt < jmax; ++jt) {
        CP_WAIT0();
        __syncthreads();
        if (jt + 1 < jmax) { issueKV((jt + 1) & 1, jt + 1); CP_COMMIT(); }

        const uint32_t* sK = sw + ((jt & 1) ? 16384 : 0);
        const uint32_t* sV = sK + 8192;

        const bool edge = (jt >= 2 * qt);
        const bool active = (jt * 64 <= rmax);
        if (active) {
            float sacc[8][4];
#pragma unroll
            for (int i = 0; i < 8; ++i)
#pragma unroll
                for (int j = 0; j < 4; ++j) sacc[i][j] = 0.0f;

            if (!edge) {
#pragma unroll
                for (int ks = 0; ks < 16; ++ks) {
                    const int c0 = ((2 * ks) & 24) | (((2 * ks) & 7) ^ gg);
                    const int c1 = ((2 * ks) & 24) | ((((2 * ks) & 7) ^ 1) ^ gg);
#pragma unroll
                    for (int nt = 0; nt < 8; ++nt) {
                        int nr = nt * 8 + gg;
                        mma_tf32_2(sacc[nt], qf[ks],
                                   sK[nr * 128 + c0 * 4 + t], sK[nr * 128 + c1 * 4 + t]);
                    }
                }
            } else {
#pragma unroll
                for (int nt = 0; nt < 8; ++nt) {
                    if (jt * 64 + nt * 8 <= rmax) {
                        const int nr = nt * 8 + gg;
#pragma unroll
                        for (int ks = 0; ks < 16; ++ks) {
                            const int c0 = ((2 * ks) & 24) | (((2 * ks) & 7) ^ gg);
                            const int c1 = ((2 * ks) & 24) | ((((2 * ks) & 7) ^ 1) ^ gg);
                            mma_tf32_2(sacc[nt], qf[ks],
                                       sK[nr * 128 + c0 * 4 + t], sK[nr * 128 + c1 * 4 + t]);
                        }
                    }
                }
            }

            const int r0 = qrow0 + m0 + gg;
            const int r1 = r0 + 8;
            float rm0 = -1e30f, rm1 = -1e30f;
#pragma unroll
            for (int nt = 0; nt < 8; ++nt) {
                float c0 = sacc[nt][0] * scale, c1 = sacc[nt][1] * scale;
                float c2 = sacc[nt][2] * scale, c3 = sacc[nt][3] * scale;
                if (edge) {
                    int colb = jt * 64 + nt * 8 + 2 * t;
                    if (colb     > r0) c0 = -1e30f;
                    if (colb + 1 > r0) c1 = -1e30f;
                    if (colb     > r1) c2 = -1e30f;
                    if (colb + 1 > r1) c3 = -1e30f;
                }
                sacc[nt][0] = c0; sacc[nt][1] = c1; sacc[nt][2] = c2; sacc[nt][3] = c3;
                rm0 = fmaxf(rm0, fmaxf(c0, c1));
                rm1 = fmaxf(rm1, fmaxf(c2, c3));
            }
            rm0 = fmaxf(rm0, __shfl_xor_sync(0xffffffffu, rm0, 1));
            rm0 = fmaxf(rm0, __shfl_xor_sync(0xffffffffu, rm0, 2));
            rm1 = fmaxf(rm1, __shfl_xor_sync(0xffffffffu, rm1, 1));
            rm1 = fmaxf(rm1, __shfl_xor_sync(0xffffffffu, rm1, 2));

            float mn0 = fmaxf(mrow0, rm0), mn1 = fmaxf(mrow1, rm1);
            float al0 = __expf(mrow0 - mn0), al1 = __expf(mrow1 - mn1);
            mrow0 = mn0; mrow1 = mn1;

            const uint32_t pA = (uint32_t)(((2 * t) & 3) * 2 + ((t >> 1) & 1));
            const uint32_t pb0 = (uint32_t)((m0 + gg) * 72) + pA;
            const uint32_t pb1 = pb0 + 8 * 72;
            float rs0 = 0.0f, rs1 = 0.0f;
#pragma unroll
            for (int nt = 0; nt < 8; ++nt) {
                float p0 = __expf(sacc[nt][0] - mn0);
                float p1 = __expf(sacc[nt][1] - mn0);
                float p2 = __expf(sacc[nt][2] - mn1);
                float p3 = __expf(sacc[nt][3] - mn1);
                rs0 += p0 + p1; rs1 += p2 + p3;
                sP[pb0 + nt * 8]     = f2tf32(p0);
                sP[pb0 + nt * 8 + 2] = f2tf32(p1);
                sP[pb1 + nt * 8]     = f2tf32(p2);
                sP[pb1 + nt * 8 + 2] = f2tf32(p3);
            }
            rs0 += __shfl_xor_sync(0xffffffffu, rs0, 1);
            rs0 += __shfl_xor_sync(0xffffffffu, rs0, 2);
            rs1 += __shfl_xor_sync(0xffffffffu, rs1, 1);
            rs1 += __shfl_xor_sync(0xffffffffu, rs1, 2);
            lrow0 = lrow0 * al0 + rs0;
            lrow1 = lrow1 * al1 + rs1;

#pragma unroll
            for (int nt = 0; nt < 16; ++nt) {
                oacc[nt][0] *= al0; oacc[nt][1] *= al0;
                oacc[nt][2] *= al1; oacc[nt][3] *= al1;
            }
            __syncwarp();

            if (!edge) {
#pragma unroll
                for (int ks = 0; ks < 8; ++ks) {
                    const int c0 = ((2 * ks) & 8) | (((2 * ks) & 7) ^ gg);
                    const int c1 = ((2 * ks) & 8) | ((((2 * ks) & 7) ^ 1) ^ gg);
                    uint2 pa0 = *(const uint2*)&sP[(m0 + gg) * 72 + ks * 8 + 2 * t];
                    uint2 pa1 = *(const uint2*)&sP[(m0 + gg + 8) * 72 + ks * 8 + 2 * t];
                    uint32_t a[4] = {pa0.x, pa1.x, pa0.y, pa1.y};
#pragma unroll
                    for (int nt = 0; nt < 16; ++nt) {
                        int nr = nt * 8 + gg;
                        mma_tf32_2(oacc[nt], a,
                                   sV[nr * 64 + c0 * 4 + t], sV[nr * 64 + c1 * 4 + t]);
                    }
                }
            } else {
#pragma unroll
                for (int ks = 0; ks < 8; ++ks) {
                    if (jt * 64 + ks * 8 <= rmax) {
                        const int c0 = ((2 * ks) & 8) | (((2 * ks) & 7) ^ gg);
                        const int c1 = ((2 * ks) & 8) | ((((2 * ks) & 7) ^ 1) ^ gg);
                        uint2 pa0 = *(const uint2*)&sP[(m0 + gg) * 72 + ks * 8 + 2 * t];
                        uint2 pa1 = *(const uint2*)&sP[(m0 + gg + 8) * 72 + ks * 8 + 2 * t];
                        uint32_t a[4] = {pa0.x, pa1.x, pa0.y, pa1.y};
#pragma unroll
                        for (int nt = 0; nt < 16; ++nt) {
                            int nr = nt * 8 + gg;
                            mma_tf32_2(oacc[nt], a,
                                       sV[nr * 64 + c0 * 4 + t], sV[nr * 64 + c1 * 4 + t]);
                        }
                    }
                }
            }
        }
    }

    const float inv0 = 1.0f / lrow0, inv1 = 1.0f / lrow1;
    const int r0 = qrow0 + m0 + gg;
#pragma unroll
    for (int nt = 0; nt < 16; ++nt) {
        int cc = h * HD + nt * 8 + 2 * t;
        *(uint2*)(o + (size_t)r0 * QD + cc) =
            make_uint2(f2tf32(oacc[nt][0] * inv0), f2tf32(oacc[nt][1] * inv0));
        *(uint2*)(o + (size_t)(r0 + 8) * QD + cc) =
            make_uint2(f2tf32(oacc[nt][2] * inv1), f2tf32(oacc[nt][3] * inv1));
    }
}

// ---------------------------------------------------------------------------
extern "C" void kernel_launch(void* const* d_in, const int* in_sizes, int n_in,
                              void* d_out, int out_size)
{
    (void)in_sizes; (void)n_in; (void)out_size;
    const float* x   = (const float*)d_in[0];
    const float* mu  = (const float*)d_in[1];
    const float* wq  = (const float*)d_in[2];
    const float* wk  = (const float*)d_in[3];
    const float* wv  = (const float*)d_in[4];
    const float* wo  = (const float*)d_in[5];
    const float* wmq = (const float*)d_in[6];
    const float* wmk = (const float*)d_in[7];
    const float* wmv = (const float*)d_in[8];
    const float* qw  = (const float*)d_in[9];
    const float* kw  = (const float*)d_in[10];
    float* out = (float*)d_out;

    float *pq0, *pq1, *pk0, *pk1, *pv0, *pv1;
    uint32_t *pkt, *pvt, *po;
    uint32_t *pxmu, *pwqc, *pwkc, *pwvc, *pwot;
    float2 *prope;
    cudaGetSymbolAddress((void**)&pq0, g_q);
    cudaGetSymbolAddress((void**)&pq1, g_q1);
    cudaGetSymbolAddress((void**)&pk0, g_k);
    cudaGetSymbolAddress((void**)&pk1, g_k1);
    cudaGetSymbolAddress((void**)&pv0, g_v0);
    cudaGetSymbolAddress((void**)&pv1, g_v1);
    cudaGetSymbolAddress((void**)&pkt, g_kt);
    cudaGetSymbolAddress((void**)&pvt, g_vt);
    cudaGetSymbolAddress((void**)&po, g_o);
    cudaGetSymbolAddress((void**)&pxmu, g_xmu);
    cudaGetSymbolAddress((void**)&pwqc, g_wqc);
    cudaGetSymbolAddress((void**)&pwkc, g_wkc);
    cudaGetSymbolAddress((void**)&pwvc, g_wvc);
    cudaGetSymbolAddress((void**)&pwot, g_wot);
    cudaGetSymbolAddress((void**)&prope, g_rope);

    // ---- fused prepass ----
    rope_table<<<SEQ, 64>>>(prope);
    cvt_all<<<24576, 256>>>(pxmu, pwqc, pwkc, pwvc, pwot,
                            x, mu, wq, wmq, wk, wmk, wv, wmv, wo);

    const int gemm_smem = 3 * STAGE_WORDS * 4;  // 98304 bytes
    cudaFuncSetAttribute(qkv_mma,   cudaFuncAttributeMaxDynamicSharedMemorySize, gemm_smem);
    cudaFuncSetAttribute(oproj_mma, cudaFuncAttributeMaxDynamicSharedMemorySize, gemm_smem);

    // Fused QKV projections, split-K (x/mu halves), 64x64 warp tiles
    qkv_mma<<<dim3(48, 16), 128, gemm_smem>>>(pxmu, pwqc, pwkc, pwvc,
                                              pq0, pq1, pk0, pk1, pv0, pv1);

    // V halves -> tf32 transposed
    vsum<<<(KVD * SEQ) / 1024, 256>>>(pvt, pv0, pv1);

    // per-head RMSNorm + RoPE (table), summing Q/K halves; K emitted as tf32
    normrope_kernel<<<dim3(SEQ, NH + NKV), 128>>>(pq0, pq1, pk0, pk1, pkt, qw, kw, prope);

    // causal GQA attention (tf32, cp.async double-buffered K/V)
    const int attn_smem = ATTN_SMEM_WORDS * 4;  // 167936 bytes
    cudaFuncSetAttribute(attn_mma, cudaFuncAttributeMaxDynamicSharedMemorySize, attn_smem);
    attn_mma<<<dim3(SEQ / 128, NH), 256, attn_smem>>>(pq0, pkt, pvt, po);

    // output projection (tf32, 64x64 warp tiles)
    oproj_mma<<<dim3(16, 16), 128, gemm_smem>>>(po, pwot, out);
}

// round 13
// speedup vs baseline: 1.9632x; 1.7604x over previous
#include <cuda_runtime.h>
#include <cuda_fp16.h>
#include <math.h>
#include <stdint.h>

#define SEQ 2048
#define HID 2048
#define NH 16
#define NKV 4
#define HD 128
#define QD (NH*HD)    /* 2048 */
#define KVD (NKV*HD)  /* 512  */

// Scratch (device globals: no allocations allowed)
__device__ float    g_q[SEQ*QD];             // Q half0 (x@Wq) fp32
__device__ float    g_q1[SEQ*QD];            // Q half1 (mu@Wmq) fp32
__device__ float    g_k[SEQ*KVD];            // K half0
__device__ float    g_k1[SEQ*KVD];           // K half1
__device__ float    g_v0[KVD*SEQ];           // V half0, fp32 transposed
__device__ float    g_v1[KVD*SEQ];           // V half1, fp32 transposed
__device__ uint32_t g_qt[SEQ*QD/2];          // fp16x2 Q (post-normrope)
__device__ uint32_t g_kt[SEQ*KVD/2];         // fp16x2 K (post-normrope)
__device__ uint32_t g_vt[KVD*SEQ/2];         // fp16x2 V, transposed [kvd][seq]
__device__ uint32_t g_o[SEQ*QD/2];           // attention output fp16x2
__device__ float2   g_rope[SEQ*64];
// Pre-converted fp16x2 operands (prepass); word = 2 k-consecutive elements
__device__ uint32_t g_xmu[SEQ*2*HID/2];      // [x | mu]  2048 x 2048 words
__device__ uint32_t g_wqc[QD*2*HID/2];
__device__ uint32_t g_wkc[KVD*2*HID/2];
__device__ uint32_t g_wvc[KVD*2*HID/2];
__device__ uint32_t g_wot[HID*QD/2];

// ---------------------------------------------------------------------------
// helpers
// ---------------------------------------------------------------------------
__device__ __forceinline__ uint32_t pack2h(float a, float b) {
    __half2 h = __floats2half2_rn(a, b);
    return *reinterpret_cast<uint32_t*>(&h);
}

__device__ __forceinline__ void mma_f16(float d[4], const uint32_t a[4],
                                        uint32_t b0, uint32_t b1) {
    asm volatile(
        "mma.sync.aligned.m16n8k16.row.col.f32.f16.f16.f32 "
        "{%0,%1,%2,%3}, {%4,%5,%6,%7}, {%8,%9}, {%0,%1,%2,%3};"
        : "+f"(d[0]), "+f"(d[1]), "+f"(d[2]), "+f"(d[3])
        : "r"(a[0]), "r"(a[1]), "r"(a[2]), "r"(a[3]), "r"(b0), "r"(b1));
}

#define CP_ASYNC_CG(dst_u32, src_ptr) \
    asm volatile("cp.async.cg.shared.global [%0], [%1], 16;" :: "r"(dst_u32), "l"(src_ptr) : "memory")
#define CP_COMMIT() asm volatile("cp.async.commit_group;" ::: "memory")
#define CP_WAIT1()  asm volatile("cp.async.wait_group 1;"  ::: "memory")
#define CP_WAIT0()  asm volatile("cp.async.wait_group 0;"  ::: "memory")

__device__ __forceinline__ uint32_t smem_u32(const void* p) {
    uint32_t a;
    asm("{ .reg .u64 t; cvta.to.shared.u64 t, %1; cvt.u32.u64 %0, t; }" : "=r"(a) : "l"(p));
    return a;
}

// ---------------------------------------------------------------------------
// Fused prepass: fp32 -> fp16x2 (+K-concat). 8 elements -> 4 words per thread.
// Element segments: xmu[0,8388608) wqc[..,16777216) wkc[..,18874368)
// wvc[..,20971520) wot[..,25165824)
// ---------------------------------------------------------------------------
__global__ __launch_bounds__(256) void cvt_all(
    uint32_t* __restrict__ xmu, uint32_t* __restrict__ wqc,
    uint32_t* __restrict__ wkc, uint32_t* __restrict__ wvc,
    uint32_t* __restrict__ wot,
    const float* __restrict__ x,  const float* __restrict__ mu,
    const float* __restrict__ wq, const float* __restrict__ wmq,
    const float* __restrict__ wk, const float* __restrict__ wmk,
    const float* __restrict__ wv, const float* __restrict__ wmv,
    const float* __restrict__ wo)
{
    long e = ((long)blockIdx.x * 256 + threadIdx.x) * 8;
    const float *A, *B; uint32_t* D; long off; bool cat = true;
    if (e < 8388608L)       { D = xmu; A = x;  B = mu;  off = e; }
    else if (e < 16777216L) { D = wqc; A = wq; B = wmq; off = e - 8388608L; }
    else if (e < 18874368L) { D = wkc; A = wk; B = wmk; off = e - 16777216L; }
    else if (e < 20971520L) { D = wvc; A = wv; B = wmv; off = e - 18874368L; }
    else                    { D = wot; A = wo; B = wo;  off = e - 20971520L; cat = false; }

    const float* src;
    if (cat) {
        int r = (int)(off >> 12);
        int c = (int)(off & 4095);
        src = (c < 2048) ? (A + (size_t)r * 2048 + c) : (B + (size_t)r * 2048 + (c - 2048));
    } else {
        src = A + off;
    }
    float4 v0 = *(const float4*)src;
    float4 v1 = *(const float4*)(src + 4);
    *(uint4*)(D + (off >> 1)) = make_uint4(pack2h(v0.x, v0.y), pack2h(v0.z, v0.w),
                                           pack2h(v1.x, v1.y), pack2h(v1.z, v1.w));
}

// RoPE (cos,sin) table
__global__ __launch_bounds__(64) void rope_table(float2* __restrict__ tab)
{
    const int pos = blockIdx.x;
    const int f = threadIdx.x;
    float ang = (float)pos * powf(10000.0f, -(float)f * (1.0f / 64.0f));
    float sn, cs;
    sincosf(ang, &sn, &cs);
    tab[pos * 64 + f] = make_float2(cs, sn);
}

// V half-sum: g_vt = fp16x2(v0 + v1)
__global__ __launch_bounds__(256) void vsum(
    uint32_t* __restrict__ vt, const float* __restrict__ v0, const float* __restrict__ v1)
{
    long e = ((long)blockIdx.x * 256 + threadIdx.x) * 4;
    float4 a = *(const float4*)(v0 + e);
    float4 b = *(const float4*)(v1 + e);
    *(uint2*)(vt + (e >> 1)) = make_uint2(pack2h(a.x + b.x, a.y + b.y),
                                          pack2h(a.z + b.z, a.w + b.w));
}

// ---------------------------------------------------------------------------
// cp.async 3-stage fp16 GEMM core. Words = fp16x2, rows 32 words = 64 elems.
// XOR-chunk swizzle; 128 threads, warp tile 64x64, m16n8k16.
// Chunk = 64 K-elements = 4 k16 steps. Same word indexing as tf32 version.
// ---------------------------------------------------------------------------
#define STG_WORDS 4096            /* 128*32 */
#define STAGE_WORDS (2*STG_WORDS)

template<bool TRANSV>
__device__ __forceinline__ void gemm_core_async(
    const uint32_t* __restrict__ Ablk, const uint32_t* __restrict__ Bblk,
    float* __restrict__ Cblk, int ldc,
    float* __restrict__ CtF, int row0g, int col0g,
    int Kelem, int ldaW, int ldbW, uint32_t* s)
{
    const uint32_t sbyte = smem_u32(s);
    const int tid = threadIdx.x;
    const int wid = tid >> 5, lane = tid & 31;
    const int g = lane >> 2, t = lane & 3;
    const int m0 = (wid >> 1) * 64;
    const int n0 = (wid & 1) * 64;

    const int lr = tid >> 3;
    const int ch = tid & 7;

    float acc[4][8][4];
#pragma unroll
    for (int i = 0; i < 4; ++i)
#pragma unroll
        for (int j = 0; j < 8; ++j)
#pragma unroll
            for (int q = 0; q < 4; ++q) acc[i][j][q] = 0.0f;

    const int nch = Kelem >> 6;
    const int chsw = ch ^ (lr & 7);

    auto issue = [&](int st, int cc) {
        const uint32_t sa0 = sbyte + (uint32_t)(st * STAGE_WORDS) * 4u;
        const uint32_t sb0 = sa0 + STG_WORDS * 4u;
        const int kkw = cc << 5;   // chunk offset in words
#pragma unroll
        for (int i = 0; i < 8; ++i) {
            int r = lr + i * 16;
            uint32_t so = (uint32_t)(r * 32 + chsw * 4) * 4u;
            CP_ASYNC_CG(sa0 + so, Ablk + (size_t)r * ldaW + kkw + ch * 4);
            CP_ASYNC_CG(sb0 + so, Bblk + (size_t)r * ldbW + kkw + ch * 4);
        }
    };

    issue(0, 0); CP_COMMIT();
    issue(1, 1); CP_COMMIT();

    for (int c = 0; c < nch; ++c) {
        CP_WAIT1();
        __syncthreads();
        if (c + 2 < nch) issue((c + 2) % 3, c + 2);
        CP_COMMIT();

        const uint32_t* sA = s + (c % 3) * STAGE_WORDS;
        const uint32_t* sB = sA + STG_WORDS;
#pragma unroll
        for (int ks = 0; ks < 4; ++ks) {   // 4 x k16 per 64-elem chunk
            const int e1 = (((2 * ks) ^ g) << 2) + t;
            const int e2 = (((2 * ks) ^ g ^ 1) << 2) + t;
            uint32_t af[4][4], bf[8][2];
#pragma unroll
            for (int mt = 0; mt < 4; ++mt) {
                int mr = m0 + mt * 16 + g;
                af[mt][0] = sA[mr * 32 + e1];
                af[mt][1] = sA[(mr + 8) * 32 + e1];
                af[mt][2] = sA[mr * 32 + e2];
                af[mt][3] = sA[(mr + 8) * 32 + e2];
            }
#pragma unroll
            for (int nt = 0; nt < 8; ++nt) {
                int nr = n0 + nt * 8 + g;
                bf[nt][0] = sB[nr * 32 + e1];
                bf[nt][1] = sB[nr * 32 + e2];
            }
#pragma unroll
            for (int mt = 0; mt < 4; ++mt)
#pragma unroll
                for (int nt = 0; nt < 8; ++nt)
                    mma_f16(acc[mt][nt], af[mt], bf[nt][0], bf[nt][1]);
        }
    }

#pragma unroll
    for (int mt = 0; mt < 4; ++mt) {
        int r0 = m0 + mt * 16 + g;
#pragma unroll
        for (int nt = 0; nt < 8; ++nt) {
            int cc = n0 + nt * 8 + 2 * t;
            if (TRANSV) {
                CtF[(size_t)(col0g + cc)     * SEQ + row0g + r0]     = acc[mt][nt][0];
                CtF[(size_t)(col0g + cc + 1) * SEQ + row0g + r0]     = acc[mt][nt][1];
                CtF[(size_t)(col0g + cc)     * SEQ + row0g + r0 + 8] = acc[mt][nt][2];
                CtF[(size_t)(col0g + cc + 1) * SEQ + row0g + r0 + 8] = acc[mt][nt][3];
            } else {
                *(float2*)(Cblk + (size_t)r0 * ldc + cc)       = make_float2(acc[mt][nt][0], acc[mt][nt][1]);
                *(float2*)(Cblk + (size_t)(r0 + 8) * ldc + cc) = make_float2(acc[mt][nt][2], acc[mt][nt][3]);
            }
        }
    }
}

// Fused QKV, split-K by mu-decomposition: grid (48, 16), 128 threads.
__global__ __launch_bounds__(128, 2) void qkv_mma(
    const uint32_t* __restrict__ xmu,
    const uint32_t* __restrict__ wqc, const uint32_t* __restrict__ wkc,
    const uint32_t* __restrict__ wvc,
    float* __restrict__ pq0, float* __restrict__ pq1,
    float* __restrict__ pk0, float* __restrict__ pk1,
    float* __restrict__ pv0, float* __restrict__ pv1)
{
    extern __shared__ uint32_t smem[];
    const int cb = blockIdx.x >> 1;
    const int half = blockIdx.x & 1;
    const int row0 = blockIdx.y * 128;
    const int koffW = half * (HID / 2);   // word offset into concatenated K range

    const uint32_t* A = xmu + (size_t)row0 * HID + koffW;   // row = 2*HID/2 = HID words

    if (cb < 20) {
        const uint32_t* B; float* C; int ldc, ccol;
        if (cb < 16) { B = wqc; C = half ? pq1 : pq0; ldc = QD;  ccol = cb * 128; }
        else         { B = wkc; C = half ? pk1 : pk0; ldc = KVD; ccol = (cb - 16) * 128; }
        gemm_core_async<false>(A, B + (size_t)ccol * HID + koffW,
                               C + (size_t)row0 * ldc + ccol, ldc,
                               nullptr, 0, 0, HID, HID, HID, smem);
    } else {
        const int ccol = (cb - 20) * 128;
        gemm_core_async<true>(A, wvc + (size_t)ccol * HID + koffW,
                              nullptr, 0, half ? pv1 : pv0, row0, ccol,
                              HID, HID, HID, smem);
    }
}

// Output projection: grid = (16, 16), 128 threads
__global__ __launch_bounds__(128, 2) void oproj_mma(
    const uint32_t* __restrict__ A, const uint32_t* __restrict__ B, float* __restrict__ C)
{
    extern __shared__ uint32_t smem[];
    const int row0 = blockIdx.y * 128;
    const int ccol = blockIdx.x * 128;
    gemm_core_async<false>(A + (size_t)row0 * (QD / 2), B + (size_t)ccol * (QD / 2),
                           C + (size_t)row0 * QD + ccol, QD,
                           nullptr, 0, 0, QD, QD / 2, QD / 2, smem);
}

// ---------------------------------------------------------------------------
// Per-head RMSNorm + RoPE, summing split-K halves. Q and K both emitted as
// packed fp16x2 (even lanes pack with odd neighbor via shfl).
// ---------------------------------------------------------------------------
__global__ __launch_bounds__(128) void normrope_kernel(
    const float* __restrict__ qb0, const float* __restrict__ qb1,
    const float* __restrict__ kb0, const float* __restrict__ kb1,
    uint32_t* __restrict__ qt, uint32_t* __restrict__ kt,
    const float* __restrict__ qw, const float* __restrict__ kw,
    const float2* __restrict__ rope)
{
    const int pos = blockIdx.x;
    const int hh = blockIdx.y;
    const int d = threadIdx.x;

    const bool isq = (hh < NH);
    int stride = isq ? QD : KVD;
    int col0 = isq ? hh * HD : (hh - NH) * HD;
    const float* w = isq ? qw : kw;
    const size_t idx = (size_t)pos * stride + col0 + d;

    float x = isq ? (qb0[idx] + qb1[idx]) : (kb0[idx] + kb1[idx]);

    float ss = x * x;
#pragma unroll
    for (int off = 16; off; off >>= 1) ss += __shfl_xor_sync(0xffffffffu, ss, off);

    __shared__ float red[4];
    __shared__ float xs[128];
    if ((d & 31) == 0) red[d >> 5] = ss;
    __syncthreads();
    ss = red[0] + red[1] + red[2] + red[3];

    float xn = x * rsqrtf(ss * (1.0f / 128.0f) + 1e-6f) * w[d];
    xs[d] = xn;
    __syncthreads();
    float rot = (d < 64) ? -xs[d + 64] : xs[d - 64];

    float2 cs = rope[pos * 64 + (d & 63)];
    float r = xn * cs.x + rot * cs.y;

    float rhi = __shfl_down_sync(0xffffffffu, r, 1);
    if (!(d & 1)) {
        uint32_t word = pack2h(r, rhi);
        if (isq) qt[idx >> 1] = word;
        else     kt[idx >> 1] = word;
    }
}

// ---------------------------------------------------------------------------
// fp16 causal flash attention, cp.async double-buffered K/V, P in registers
// (fp16 C-frag == A-frag identity). Q-tile 128, KV-tile 64, 8 warps.
// SMEM words: KV buf0 [K 64x64w | V 128x32w] @0 (8192), buf1 @8192,
//             sQ [128][68] @16384 (8704). Total 25088 words = 100352 B.
// ---------------------------------------------------------------------------
#define ATTN_SMEM_WORDS 25088

__global__ __launch_bounds__(256, 1) void attn_mma(
    const uint32_t* __restrict__ qt, const uint32_t* __restrict__ kt,
    const uint32_t* __restrict__ vt, uint32_t* __restrict__ o)
{
    extern __shared__ uint32_t sw[];
    uint32_t* sQ = sw + 16384;    // [128][68]
    const uint32_t sbyte = smem_u32(sw);

    const int qt_i = gridDim.x - 1 - blockIdx.x;   // heavy tiles first
    const int h = blockIdx.y;
    const int kvh = h >> 2;
    const int qrow0 = qt_i * 128;
    const int tid = threadIdx.x;
    const int w = tid >> 5, lane = tid & 31;
    const int gg = lane >> 2, t = lane & 3;
    const int m0 = w * 16;
    const int jmax = 2 * qt_i + 2;
    const int rmax = qrow0 + m0 + 15;

    auto issueKV = [&](int b, int jt) {
        const uint32_t kb0 = sbyte + (uint32_t)(b ? 8192 : 0) * 4u;
        const uint32_t vb0 = kb0 + 4096u * 4u;
#pragma unroll
        for (int i = 0; i < 4; ++i) {      // K: 64 rows x 16 chunks16
            int id = tid + i * 256;
            int r = id >> 4, c = id & 15;
            int cs = (c & 8) | ((c & 7) ^ (r & 7));
            CP_ASYNC_CG(kb0 + (uint32_t)(r * 64 + cs * 4) * 4u,
                        kt + (size_t)(jt * 64 + r) * (KVD / 2) + kvh * (HD / 2) + c * 4);
        }
#pragma unroll
        for (int i = 0; i < 4; ++i) {      // V: 128 rows x 8 chunks16
            int id = tid + i * 256;
            int r = id >> 3, c = id & 7;
            int cs = c ^ (r & 7);
            CP_ASYNC_CG(vb0 + (uint32_t)(r * 32 + cs * 4) * 4u,
                        vt + (size_t)(kvh * HD + r) * (SEQ / 2) + jt * 32 + c * 4);
        }
    };

    issueKV(0, 0); CP_COMMIT();

    // ---- stage Q (fp16 words) ----
#pragma unroll
    for (int i = 0; i < 8; ++i) {
        int id = tid + i * 256;            // 0..2047 over 128 rows x 16 uint4
        int r = id >> 4, w4 = (id & 15) << 2;
        uint4 v = *(const uint4*)(qt + (size_t)(qrow0 + r) * (QD / 2) + h * (HD / 2) + w4);
        sQ[r * 68 + w4 + 0] = v.x;
        sQ[r * 68 + w4 + 1] = v.y;
        sQ[r * 68 + w4 + 2] = v.z;
        sQ[r * 68 + w4 + 3] = v.w;
    }
    __syncthreads();

    // ---- Q fragments (8 k16 steps over HD=128) ----
    uint32_t qf[8][4];
#pragma unroll
    for (int ks = 0; ks < 8; ++ks) {
        qf[ks][0] = sQ[(m0 + gg) * 68 + ks * 8 + t];
        qf[ks][1] = sQ[(m0 + gg + 8) * 68 + ks * 8 + t];
        qf[ks][2] = sQ[(m0 + gg) * 68 + ks * 8 + 4 + t];
        qf[ks][3] = sQ[(m0 + gg + 8) * 68 + ks * 8 + 4 + t];
    }

    float oacc[16][4];
#pragma unroll
    for (int i = 0; i < 16; ++i)
#pragma unroll
        for (int j = 0; j < 4; ++j) oacc[i][j] = 0.0f;
    float mrow0 = -1e30f, mrow1 = -1e30f, lrow0 = 0.0f, lrow1 = 0.0f;

    const float scale = 0.08838834764831845f;

    for (int jt = 0; jt < jmax; ++jt) {
        CP_WAIT0();
        __syncthreads();
        if (jt + 1 < jmax) { issueKV((jt + 1) & 1, jt + 1); CP_COMMIT(); }

        const uint32_t* sK = sw + ((jt & 1) ? 8192 : 0);
        const uint32_t* sV = sK + 4096;

        const bool edge = (jt >= 2 * qt_i);
        const bool active = (jt * 64 <= rmax);
        if (active) {
            // ---- S = Q @ K^T ----
            float sacc[8][4];
#pragma unroll
            for (int i = 0; i < 8; ++i)
#pragma unroll
                for (int j = 0; j < 4; ++j) sacc[i][j] = 0.0f;

            if (!edge) {
#pragma unroll
                for (int ks = 0; ks < 8; ++ks) {
                    const int c0 = (((2 * ks) & 8) | (((2 * ks) & 7) ^ gg)) * 4 + t;
                    const int c1 = (((2 * ks + 1) & 8) | (((2 * ks + 1) & 7) ^ gg)) * 4 + t;
#pragma unroll
                    for (int nt = 0; nt < 8; ++nt) {
                        int nr = nt * 8 + gg;
                        mma_f16(sacc[nt], qf[ks], sK[nr * 64 + c0], sK[nr * 64 + c1]);
                    }
                }
            } else {
#pragma unroll
                for (int nt = 0; nt < 8; ++nt) {
                    if (jt * 64 + nt * 8 <= rmax) {
                        const int nr = nt * 8 + gg;
#pragma unroll
                        for (int ks = 0; ks < 8; ++ks) {
                            const int c0 = (((2 * ks) & 8) | (((2 * ks) & 7) ^ gg)) * 4 + t;
                            const int c1 = (((2 * ks + 1) & 8) | (((2 * ks + 1) & 7) ^ gg)) * 4 + t;
                            mma_f16(sacc[nt], qf[ks], sK[nr * 64 + c0], sK[nr * 64 + c1]);
                        }
                    }
                }
            }

            // ---- scale + mask + online softmax ----
            const int r0 = qrow0 + m0 + gg;
            const int r1 = r0 + 8;
            float rm0 = -1e30f, rm1 = -1e30f;
#pragma unroll
            for (int nt = 0; nt < 8; ++nt) {
                float c0 = sacc[nt][0] * scale, c1 = sacc[nt][1] * scale;
                float c2 = sacc[nt][2] * scale, c3 = sacc[nt][3] * scale;
                if (edge) {
                    int colb = jt * 64 + nt * 8 + 2 * t;
                    if (colb     > r0) c0 = -1e30f;
                    if (colb + 1 > r0) c1 = -1e30f;
                    if (colb     > r1) c2 = -1e30f;
                    if (colb + 1 > r1) c3 = -1e30f;
                }
                sacc[nt][0] = c0; sacc[nt][1] = c1; sacc[nt][2] = c2; sacc[nt][3] = c3;
                rm0 = fmaxf(rm0, fmaxf(c0, c1));
                rm1 = fmaxf(rm1, fmaxf(c2, c3));
            }
            rm0 = fmaxf(rm0, __shfl_xor_sync(0xffffffffu, rm0, 1));
            rm0 = fmaxf(rm0, __shfl_xor_sync(0xffffffffu, rm0, 2));
            rm1 = fmaxf(rm1, __shfl_xor_sync(0xffffffffu, rm1, 1));
            rm1 = fmaxf(rm1, __shfl_xor_sync(0xffffffffu, rm1, 2));

            float mn0 = fmaxf(mrow0, rm0), mn1 = fmaxf(mrow1, rm1);
            float al0 = __expf(mrow0 - mn0), al1 = __expf(mrow1 - mn1);
            mrow0 = mn0; mrow1 = mn1;

            // ---- P: exp in fp32, pack to fp16x2 A-frags in registers ----
            uint32_t pu[8][2];
            float rs0 = 0.0f, rs1 = 0.0f;
#pragma unroll
            for (int nt = 0; nt < 8; ++nt) {
                float p0 = __expf(sacc[nt][0] - mn0);
                float p1 = __expf(sacc[nt][1] - mn0);
                float p2 = __expf(sacc[nt][2] - mn1);
                float p3 = __expf(sacc[nt][3] - mn1);
                rs0 += p0 + p1; rs1 += p2 + p3;
                pu[nt][0] = pack2h(p0, p1);
                pu[nt][1] = pack2h(p2, p3);
            }
            rs0 += __shfl_xor_sync(0xffffffffu, rs0, 1);
            rs0 += __shfl_xor_sync(0xffffffffu, rs0, 2);
            rs1 += __shfl_xor_sync(0xffffffffu, rs1, 1);
            rs1 += __shfl_xor_sync(0xffffffffu, rs1, 2);
            lrow0 = lrow0 * al0 + rs0;
            lrow1 = lrow1 * al1 + rs1;

#pragma unroll
            for (int nt = 0; nt < 16; ++nt) {
                oacc[nt][0] *= al0; oacc[nt][1] *= al0;
                oacc[nt][2] *= al1; oacc[nt][3] *= al1;
            }

            // ---- O += P @ V (P A-frags direct from C-frags) ----
#pragma unroll
            for (int ks = 0; ks < 4; ++ks) {   // k16 over 64 seq cols
                if (edge && (jt * 64 + ks * 16 > rmax)) continue;
                uint32_t a[4] = {pu[2 * ks][0], pu[2 * ks][1],
                                 pu[2 * ks + 1][0], pu[2 * ks + 1][1]};
                const int c0 = (((2 * ks) ^ gg) & 7) * 4 + t;
                const int c1 = (((2 * ks + 1) ^ gg) & 7) * 4 + t;
#pragma unroll
                for (int nt = 0; nt < 16; ++nt) {
                    int nr = nt * 8 + gg;
                    mma_f16(oacc[nt], a, sV[nr * 32 + c0], sV[nr * 32 + c1]);
                }
            }
        }
    }

    // ---- normalize + write fp16x2 ----
    const float inv0 = 1.0f / lrow0, inv1 = 1.0f / lrow1;
    const int r0 = qrow0 + m0 + gg;
#pragma unroll
    for (int nt = 0; nt < 16; ++nt) {
        int wi = h * (HD / 2) + nt * 4 + t;    // word of cols (nt*8+2t, +1)
        o[(size_t)r0 * (QD / 2) + wi]       = pack2h(oacc[nt][0] * inv0, oacc[nt][1] * inv0);
        o[(size_t)(r0 + 8) * (QD / 2) + wi] = pack2h(oacc[nt][2] * inv1, oacc[nt][3] * inv1);
    }
}

// ---------------------------------------------------------------------------
extern "C" void kernel_launch(void* const* d_in, const int* in_sizes, int n_in,
                              void* d_out, int out_size)
{
    (void)in_sizes; (void)n_in; (void)out_size;
    const float* x   = (const float*)d_in[0];
    const float* mu  = (const float*)d_in[1];
    const float* wq  = (const float*)d_in[2];
    const float* wk  = (const float*)d_in[3];
    const float* wv  = (const float*)d_in[4];
    const float* wo  = (const float*)d_in[5];
    const float* wmq = (const float*)d_in[6];
    const float* wmk = (const float*)d_in[7];
    const float* wmv = (const float*)d_in[8];
    const float* qw  = (const float*)d_in[9];
    const float* kw  = (const float*)d_in[10];
    float* out = (float*)d_out;

    float *pq0, *pq1, *pk0, *pk1, *pv0, *pv1;
    uint32_t *pqt, *pkt, *pvt, *po;
    uint32_t *pxmu, *pwqc, *pwkc, *pwvc, *pwot;
    float2 *prope;
    cudaGetSymbolAddress((void**)&pq0, g_q);
    cudaGetSymbolAddress((void**)&pq1, g_q1);
    cudaGetSymbolAddress((void**)&pk0, g_k);
    cudaGetSymbolAddress((void**)&pk1, g_k1);
    cudaGetSymbolAddress((void**)&pv0, g_v0);
    cudaGetSymbolAddress((void**)&pv1, g_v1);
    cudaGetSymbolAddress((void**)&pqt, g_qt);
    cudaGetSymbolAddress((void**)&pkt, g_kt);
    cudaGetSymbolAddress((void**)&pvt, g_vt);
    cudaGetSymbolAddress((void**)&po, g_o);
    cudaGetSymbolAddress((void**)&pxmu, g_xmu);
    cudaGetSymbolAddress((void**)&pwqc, g_wqc);
    cudaGetSymbolAddress((void**)&pwkc, g_wkc);
    cudaGetSymbolAddress((void**)&pwvc, g_wvc);
    cudaGetSymbolAddress((void**)&pwot, g_wot);
    cudaGetSymbolAddress((void**)&prope, g_rope);

    // ---- fused prepass ----
    rope_table<<<SEQ, 64>>>(prope);
    cvt_all<<<12288, 256>>>(pxmu, pwqc, pwkc, pwvc, pwot,
                            x, mu, wq, wmq, wk, wmk, wv, wmv, wo);

    const int gemm_smem = 3 * STAGE_WORDS * 4;  // 98304 bytes
    cudaFuncSetAttribute(qkv_mma,   cudaFuncAttributeMaxDynamicSharedMemorySize, gemm_smem);
    cudaFuncSetAttribute(oproj_mma, cudaFuncAttributeMaxDynamicSharedMemorySize, gemm_smem);

    // Fused QKV projections (fp16 mma, split-K halves)
    qkv_mma<<<dim3(48, 16), 128, gemm_smem>>>(pxmu, pwqc, pwkc, pwvc,
                                              pq0, pq1, pk0, pk1, pv0, pv1);

    // V halves -> fp16x2 transposed
    vsum<<<(KVD * SEQ) / 1024, 256>>>(pvt, pv0, pv1);

    // RMSNorm + RoPE; Q and K emitted as fp16x2
    normrope_kernel<<<dim3(SEQ, NH + NKV), 128>>>(pq0, pq1, pk0, pk1, pqt, pkt, qw, kw, prope);

    // causal GQA attention (fp16 mma, P in registers)
    const int attn_smem = ATTN_SMEM_WORDS * 4;  // 100352 bytes
    cudaFuncSetAttribute(attn_mma, cudaFuncAttributeMaxDynamicSharedMemorySize, attn_smem);
    attn_mma<<<dim3(SEQ / 128, NH), 256, attn_smem>>>(pqt, pkt, pvt, po);

    // output projection (fp16 mma)
    oproj_mma<<<dim3(16, 16), 128, gemm_smem>>>(po, pwot, out);
}

// round 14
// speedup vs baseline: 1.9664x; 1.0017x over previous
#include <cuda_runtime.h>
#include <cuda_fp16.h>
#include <math.h>
#include <stdint.h>

#define SEQ 2048
#define HID 2048
#define NH 16
#define NKV 4
#define HD 128
#define QD (NH*HD)    /* 2048 */
#define KVD (NKV*HD)  /* 512  */

// Scratch (device globals: no allocations allowed)
__device__ float    g_q[SEQ*QD];             // Q half0 (x@Wq) fp32
__device__ float    g_q1[SEQ*QD];            // Q half1 (mu@Wmq) fp32
__device__ float    g_k[SEQ*KVD];            // K half0
__device__ float    g_k1[SEQ*KVD];           // K half1
__device__ uint32_t g_qt[SEQ*QD/2];          // fp16x2 Q (post-normrope)
__device__ uint32_t g_kt[SEQ*KVD/2];         // fp16x2 K (post-normrope)
__device__ uint32_t g_vt[KVD*SEQ/2];         // fp16x2 V, transposed [kvd][seq]
__device__ uint32_t g_o[SEQ*QD/2];           // attention output fp16x2
__device__ float2   g_rope[SEQ*64];
// Pre-converted fp16x2 operands (prepass); word = 2 k-consecutive elements
__device__ uint32_t g_xmu[SEQ*2*HID/2];      // [x | mu]  2048 x 2048 words
__device__ uint32_t g_wqc[QD*2*HID/2];
__device__ uint32_t g_wkc[KVD*2*HID/2];
__device__ uint32_t g_wvc[KVD*2*HID/2];
__device__ uint32_t g_wot[HID*QD/2];

// ---------------------------------------------------------------------------
// helpers
// ---------------------------------------------------------------------------
__device__ __forceinline__ uint32_t pack2h(float a, float b) {
    __half2 h = __floats2half2_rn(a, b);
    return *reinterpret_cast<uint32_t*>(&h);
}

__device__ __forceinline__ uint32_t ex2_h2(uint32_t a) {
    uint32_t r;
    asm("ex2.approx.f16x2 %0, %1;" : "=r"(r) : "r"(a));
    return r;
}

__device__ __forceinline__ void mma_f16(float d[4], const uint32_t a[4],
                                        uint32_t b0, uint32_t b1) {
    asm volatile(
        "mma.sync.aligned.m16n8k16.row.col.f32.f16.f16.f32 "
        "{%0,%1,%2,%3}, {%4,%5,%6,%7}, {%8,%9}, {%0,%1,%2,%3};"
        : "+f"(d[0]), "+f"(d[1]), "+f"(d[2]), "+f"(d[3])
        : "r"(a[0]), "r"(a[1]), "r"(a[2]), "r"(a[3]), "r"(b0), "r"(b1));
}

#define CP_ASYNC_CG(dst_u32, src_ptr) \
    asm volatile("cp.async.cg.shared.global [%0], [%1], 16;" :: "r"(dst_u32), "l"(src_ptr) : "memory")
#define CP_COMMIT() asm volatile("cp.async.commit_group;" ::: "memory")
#define CP_WAIT1()  asm volatile("cp.async.wait_group 1;"  ::: "memory")
#define CP_WAIT0()  asm volatile("cp.async.wait_group 0;"  ::: "memory")

__device__ __forceinline__ uint32_t smem_u32(const void* p) {
    uint32_t a;
    asm("{ .reg .u64 t; cvta.to.shared.u64 t, %1; cvt.u32.u64 %0, t; }" : "=r"(a) : "l"(p));
    return a;
}

// ---------------------------------------------------------------------------
// Fused prepass: fp32 -> fp16x2 (+K-concat). 8 elements -> 4 words per thread.
// ---------------------------------------------------------------------------
__global__ __launch_bounds__(256) void cvt_all(
    uint32_t* __restrict__ xmu, uint32_t* __restrict__ wqc,
    uint32_t* __restrict__ wkc, uint32_t* __restrict__ wvc,
    uint32_t* __restrict__ wot,
    const float* __restrict__ x,  const float* __restrict__ mu,
    const float* __restrict__ wq, const float* __restrict__ wmq,
    const float* __restrict__ wk, const float* __restrict__ wmk,
    const float* __restrict__ wv, const float* __restrict__ wmv,
    const float* __restrict__ wo)
{
    long e = ((long)blockIdx.x * 256 + threadIdx.x) * 8;
    const float *A, *B; uint32_t* D; long off; bool cat = true;
    if (e < 8388608L)       { D = xmu; A = x;  B = mu;  off = e; }
    else if (e < 16777216L) { D = wqc; A = wq; B = wmq; off = e - 8388608L; }
    else if (e < 18874368L) { D = wkc; A = wk; B = wmk; off = e - 16777216L; }
    else if (e < 20971520L) { D = wvc; A = wv; B = wmv; off = e - 18874368L; }
    else                    { D = wot; A = wo; B = wo;  off = e - 20971520L; cat = false; }

    const float* src;
    if (cat) {
        int r = (int)(off >> 12);
        int c = (int)(off & 4095);
        src = (c < 2048) ? (A + (size_t)r * 2048 + c) : (B + (size_t)r * 2048 + (c - 2048));
    } else {
        src = A + off;
    }
    float4 v0 = *(const float4*)src;
    float4 v1 = *(const float4*)(src + 4);
    *(uint4*)(D + (off >> 1)) = make_uint4(pack2h(v0.x, v0.y), pack2h(v0.z, v0.w),
                                           pack2h(v1.x, v1.y), pack2h(v1.z, v1.w));
}

// RoPE (cos,sin) table
__global__ __launch_bounds__(64) void rope_table(float2* __restrict__ tab)
{
    const int pos = blockIdx.x;
    const int f = threadIdx.x;
    float ang = (float)pos * powf(10000.0f, -(float)f * (1.0f / 64.0f));
    float sn, cs;
    sincosf(ang, &sn, &cs);
    tab[pos * 64 + f] = make_float2(cs, sn);
}

// ---------------------------------------------------------------------------
// cp.async 3-stage fp16 GEMM core. Words = fp16x2, rows 32 words = 64 elems.
// XOR-chunk swizzle; 128 threads, warp tile 64x64, m16n8k16.
// TRANSV: packs fp16 pairs along the row (seq) dim via shfl_xor(4) and writes
// transposed fp16x2 words directly (used for V).
// ---------------------------------------------------------------------------
#define STG_WORDS 4096            /* 128*32 */
#define STAGE_WORDS (2*STG_WORDS)

template<bool TRANSV>
__device__ __forceinline__ void gemm_core_async(
    const uint32_t* __restrict__ Ablk, const uint32_t* __restrict__ Bblk,
    float* __restrict__ Cblk, int ldc,
    uint32_t* __restrict__ Cth, int row0g, int col0g,
    int Kelem, int ldaW, int ldbW, uint32_t* s)
{
    const uint32_t sbyte = smem_u32(s);
    const int tid = threadIdx.x;
    const int wid = tid >> 5, lane = tid & 31;
    const int g = lane >> 2, t = lane & 3;
    const int m0 = (wid >> 1) * 64;
    const int n0 = (wid & 1) * 64;

    const int lr = tid >> 3;
    const int ch = tid & 7;

    float acc[4][8][4];
#pragma unroll
    for (int i = 0; i < 4; ++i)
#pragma unroll
        for (int j = 0; j < 8; ++j)
#pragma unroll
            for (int q = 0; q < 4; ++q) acc[i][j][q] = 0.0f;

    const int nch = Kelem >> 6;
    const int chsw = ch ^ (lr & 7);

    auto issue = [&](int st, int cc) {
        const uint32_t sa0 = sbyte + (uint32_t)(st * STAGE_WORDS) * 4u;
        const uint32_t sb0 = sa0 + STG_WORDS * 4u;
        const int kkw = cc << 5;
#pragma unroll
        for (int i = 0; i < 8; ++i) {
            int r = lr + i * 16;
            uint32_t so = (uint32_t)(r * 32 + chsw * 4) * 4u;
            CP_ASYNC_CG(sa0 + so, Ablk + (size_t)r * ldaW + kkw + ch * 4);
            CP_ASYNC_CG(sb0 + so, Bblk + (size_t)r * ldbW + kkw + ch * 4);
        }
    };

    issue(0, 0); CP_COMMIT();
    issue(1, 1); CP_COMMIT();

    for (int c = 0; c < nch; ++c) {
        CP_WAIT1();
        __syncthreads();
        if (c + 2 < nch) issue((c + 2) % 3, c + 2);
        CP_COMMIT();

        const uint32_t* sA = s + (c % 3) * STAGE_WORDS;
        const uint32_t* sB = sA + STG_WORDS;
#pragma unroll
        for (int ks = 0; ks < 4; ++ks) {
            const int e1 = (((2 * ks) ^ g) << 2) + t;
            const int e2 = (((2 * ks) ^ g ^ 1) << 2) + t;
            uint32_t af[4][4], bf[8][2];
#pragma unroll
            for (int mt = 0; mt < 4; ++mt) {
                int mr = m0 + mt * 16 + g;
                af[mt][0] = sA[mr * 32 + e1];
                af[mt][1] = sA[(mr + 8) * 32 + e1];
                af[mt][2] = sA[mr * 32 + e2];
                af[mt][3] = sA[(mr + 8) * 32 + e2];
            }
#pragma unroll
            for (int nt = 0; nt < 8; ++nt) {
                int nr = n0 + nt * 8 + g;
                bf[nt][0] = sB[nr * 32 + e1];
                bf[nt][1] = sB[nr * 32 + e2];
            }
#pragma unroll
            for (int mt = 0; mt < 4; ++mt)
#pragma unroll
                for (int nt = 0; nt < 8; ++nt)
                    mma_f16(acc[mt][nt], af[mt], bf[nt][0], bf[nt][1]);
        }
    }

#pragma unroll
    for (int mt = 0; mt < 4; ++mt) {
        int r0 = m0 + mt * 16 + g;
#pragma unroll
        for (int nt = 0; nt < 8; ++nt) {
            int cc = n0 + nt * 8 + 2 * t;
            if (TRANSV) {
                // pack (row, row^1) pairs: row parity == g parity; partner in lane^4
                float p0 = acc[mt][nt][0], q0 = __shfl_xor_sync(0xffffffffu, p0, 4);
                float p1 = acc[mt][nt][1], q1 = __shfl_xor_sync(0xffffffffu, p1, 4);
                float p2 = acc[mt][nt][2], q2 = __shfl_xor_sync(0xffffffffu, p2, 4);
                float p3 = acc[mt][nt][3], q3 = __shfl_xor_sync(0xffffffffu, p3, 4);
                if (!(g & 1)) {
                    size_t w0 = (size_t)(col0g + cc)     * (SEQ / 2);
                    size_t w1 = (size_t)(col0g + cc + 1) * (SEQ / 2);
                    int rw0 = (row0g + r0) >> 1;
                    int rw1 = (row0g + r0 + 8) >> 1;
                    Cth[w0 + rw0] = pack2h(p0, q0);
                    Cth[w1 + rw0] = pack2h(p1, q1);
                    Cth[w0 + rw1] = pack2h(p2, q2);
                    Cth[w1 + rw1] = pack2h(p3, q3);
                }
            } else {
                *(float2*)(Cblk + (size_t)r0 * ldc + cc)       = make_float2(acc[mt][nt][0], acc[mt][nt][1]);
                *(float2*)(Cblk + (size_t)(r0 + 8) * ldc + cc) = make_float2(acc[mt][nt][2], acc[mt][nt][3]);
            }
        }
    }
}

// Fused QKV: grid (44, 16), 128 threads.
// x 0..3   -> V col blocks, FULL K=4096, fp16 transposed direct (2-unit work, first)
// x 4..35  -> Q halves (cb=(x-4)>>1, half=(x-4)&1), K=2048 each
// x 36..43 -> K halves
__global__ __launch_bounds__(128, 2) void qkv_mma(
    const uint32_t* __restrict__ xmu,
    const uint32_t* __restrict__ wqc, const uint32_t* __restrict__ wkc,
    const uint32_t* __restrict__ wvc,
    float* __restrict__ pq0, float* __restrict__ pq1,
    float* __restrict__ pk0, float* __restrict__ pk1,
    uint32_t* __restrict__ pvt)
{
    extern __shared__ uint32_t smem[];
    const int xb = blockIdx.x;
    const int row0 = blockIdx.y * 128;

    if (xb < 4) {
        const int ccol = xb * 128;
        gemm_core_async<true>(xmu + (size_t)row0 * HID, wvc + (size_t)ccol * HID,
                              nullptr, 0, pvt, row0, ccol,
                              2 * HID, HID, HID, smem);
    } else {
        int q = xb - 4;
        const uint32_t* B; float* C; int ldc, cb, half;
        if (q < 32) { cb = q >> 1; half = q & 1; B = wqc; C = half ? pq1 : pq0; ldc = QD; }
        else        { q -= 32; cb = q >> 1; half = q & 1; B = wkc; C = half ? pk1 : pk0; ldc = KVD; }
        const int ccol = cb * 128;
        const int koffW = half * (HID / 2);
        gemm_core_async<false>(xmu + (size_t)row0 * HID + koffW,
                               B + (size_t)ccol * HID + koffW,
                               C + (size_t)row0 * ldc + ccol, ldc,
                               nullptr, 0, 0, HID, HID, HID, smem);
    }
}

// Output projection: grid = (16, 16), 128 threads
__global__ __launch_bounds__(128, 2) void oproj_mma(
    const uint32_t* __restrict__ A, const uint32_t* __restrict__ B, float* __restrict__ C)
{
    extern __shared__ uint32_t smem[];
    const int row0 = blockIdx.y * 128;
    const int ccol = blockIdx.x * 128;
    gemm_core_async<false>(A + (size_t)row0 * (QD / 2), B + (size_t)ccol * (QD / 2),
                           C + (size_t)row0 * QD + ccol, QD,
                           nullptr, 0, 0, QD, QD / 2, QD / 2, smem);
}

// ---------------------------------------------------------------------------
// Per-head RMSNorm + RoPE, summing split-K halves; Q/K emitted as fp16x2.
// ---------------------------------------------------------------------------
__global__ __launch_bounds__(128) void normrope_kernel(
    const float* __restrict__ qb0, const float* __restrict__ qb1,
    const float* __restrict__ kb0, const float* __restrict__ kb1,
    uint32_t* __restrict__ qt, uint32_t* __restrict__ kt,
    const float* __restrict__ qw, const float* __restrict__ kw,
    const float2* __restrict__ rope)
{
    const int pos = blockIdx.x;
    const int hh = blockIdx.y;
    const int d = threadIdx.x;

    const bool isq = (hh < NH);
    int stride = isq ? QD : KVD;
    int col0 = isq ? hh * HD : (hh - NH) * HD;
    const float* w = isq ? qw : kw;
    const size_t idx = (size_t)pos * stride + col0 + d;

    float x = isq ? (qb0[idx] + qb1[idx]) : (kb0[idx] + kb1[idx]);

    float ss = x * x;
#pragma unroll
    for (int off = 16; off; off >>= 1) ss += __shfl_xor_sync(0xffffffffu, ss, off);

    __shared__ float red[4];
    __shared__ float xs[128];
    if ((d & 31) == 0) red[d >> 5] = ss;
    __syncthreads();
    ss = red[0] + red[1] + red[2] + red[3];

    float xn = x * rsqrtf(ss * (1.0f / 128.0f) + 1e-6f) * w[d];
    xs[d] = xn;
    __syncthreads();
    float rot = (d < 64) ? -xs[d + 64] : xs[d - 64];

    float2 cs = rope[pos * 64 + (d & 63)];
    float r = xn * cs.x + rot * cs.y;

    float rhi = __shfl_down_sync(0xffffffffu, r, 1);
    if (!(d & 1)) {
        uint32_t word = pack2h(r, rhi);
        if (isq) qt[idx >> 1] = word;
        else     kt[idx >> 1] = word;
    }
}

// ---------------------------------------------------------------------------
// fp16 causal flash attention, cp.async double-buffered K/V, P in registers,
// softmax via ex2.approx.f16x2 (one MUFU per two probs; result IS the P word).
// ---------------------------------------------------------------------------
#define ATTN_SMEM_WORDS 25088

__global__ __launch_bounds__(256, 1) void attn_mma(
    const uint32_t* __restrict__ qt, const uint32_t* __restrict__ kt,
    const uint32_t* __restrict__ vt, uint32_t* __restrict__ o)
{
    extern __shared__ uint32_t sw[];
    uint32_t* sQ = sw + 16384;    // [128][68]
    const uint32_t sbyte = smem_u32(sw);

    const int qt_i = gridDim.x - 1 - blockIdx.x;   // heavy tiles first
    const int h = blockIdx.y;
    const int kvh = h >> 2;
    const int qrow0 = qt_i * 128;
    const int tid = threadIdx.x;
    const int w = tid >> 5, lane = tid & 31;
    const int gg = lane >> 2, t = lane & 3;
    const int m0 = w * 16;
    const int jmax = 2 * qt_i + 2;
    const int rmax = qrow0 + m0 + 15;

    auto issueKV = [&](int b, int jt) {
        const uint32_t kb0 = sbyte + (uint32_t)(b ? 8192 : 0) * 4u;
        const uint32_t vb0 = kb0 + 4096u * 4u;
#pragma unroll
        for (int i = 0; i < 4; ++i) {
            int id = tid + i * 256;
            int r = id >> 4, c = id & 15;
            int cs = (c & 8) | ((c & 7) ^ (r & 7));
            CP_ASYNC_CG(kb0 + (uint32_t)(r * 64 + cs * 4) * 4u,
                        kt + (size_t)(jt * 64 + r) * (KVD / 2) + kvh * (HD / 2) + c * 4);
        }
#pragma unroll
        for (int i = 0; i < 4; ++i) {
            int id = tid + i * 256;
            int r = id >> 3, c = id & 7;
            int cs = c ^ (r & 7);
            CP_ASYNC_CG(vb0 + (uint32_t)(r * 32 + cs * 4) * 4u,
                        vt + (size_t)(kvh * HD + r) * (SEQ / 2) + jt * 32 + c * 4);
        }
    };

    issueKV(0, 0); CP_COMMIT();

#pragma unroll
    for (int i = 0; i < 8; ++i) {
        int id = tid + i * 256;
        int r = id >> 4, w4 = (id & 15) << 2;
        uint4 v = *(const uint4*)(qt + (size_t)(qrow0 + r) * (QD / 2) + h * (HD / 2) + w4);
        sQ[r * 68 + w4 + 0] = v.x;
        sQ[r * 68 + w4 + 1] = v.y;
        sQ[r * 68 + w4 + 2] = v.z;
        sQ[r * 68 + w4 + 3] = v.w;
    }
    __syncthreads();

    uint32_t qf[8][4];
#pragma unroll
    for (int ks = 0; ks < 8; ++ks) {
        qf[ks][0] = sQ[(m0 + gg) * 68 + ks * 8 + t];
        qf[ks][1] = sQ[(m0 + gg + 8) * 68 + ks * 8 + t];
        qf[ks][2] = sQ[(m0 + gg) * 68 + ks * 8 + 4 + t];
        qf[ks][3] = sQ[(m0 + gg + 8) * 68 + ks * 8 + 4 + t];
    }

    float oacc[16][4];
#pragma unroll
    for (int i = 0; i < 16; ++i)
#pragma unroll
        for (int j = 0; j < 4; ++j) oacc[i][j] = 0.0f;
    float mrow0 = -1e30f, mrow1 = -1e30f, lrow0 = 0.0f, lrow1 = 0.0f;

    const float scale = 0.08838834764831845f;
    const float L2E = 1.4426950408889634f;

    for (int jt = 0; jt < jmax; ++jt) {
        CP_WAIT0();
        __syncthreads();
        if (jt + 1 < jmax) { issueKV((jt + 1) & 1, jt + 1); CP_COMMIT(); }

        const uint32_t* sK = sw + ((jt & 1) ? 8192 : 0);
        const uint32_t* sV = sK + 4096;

        const bool edge = (jt >= 2 * qt_i);
        const bool active = (jt * 64 <= rmax);
        if (active) {
            float sacc[8][4];
#pragma unroll
            for (int i = 0; i < 8; ++i)
#pragma unroll
                for (int j = 0; j < 4; ++j) sacc[i][j] = 0.0f;

            if (!edge) {
#pragma unroll
                for (int ks = 0; ks < 8; ++ks) {
                    const int c0 = (((2 * ks) & 8) | (((2 * ks) & 7) ^ gg)) * 4 + t;
                    const int c1 = (((2 * ks + 1) & 8) | (((2 * ks + 1) & 7) ^ gg)) * 4 + t;
#pragma unroll
                    for (int nt = 0; nt < 8; ++nt) {
                        int nr = nt * 8 + gg;
                        mma_f16(sacc[nt], qf[ks], sK[nr * 64 + c0], sK[nr * 64 + c1]);
                    }
                }
            } else {
#pragma unroll
                for (int nt = 0; nt < 8; ++nt) {
                    if (jt * 64 + nt * 8 <= rmax) {
                        const int nr = nt * 8 + gg;
#pragma unroll
                        for (int ks = 0; ks < 8; ++ks) {
                            const int c0 = (((2 * ks) & 8) | (((2 * ks) & 7) ^ gg)) * 4 + t;
                            const int c1 = (((2 * ks + 1) & 8) | (((2 * ks + 1) & 7) ^ gg)) * 4 + t;
                            mma_f16(sacc[nt], qf[ks], sK[nr * 64 + c0], sK[nr * 64 + c1]);
                        }
                    }
                }
            }

            const int r0 = qrow0 + m0 + gg;
            const int r1 = r0 + 8;
            float rm0 = -1e30f, rm1 = -1e30f;
#pragma unroll
            for (int nt = 0; nt < 8; ++nt) {
                float c0 = sacc[nt][0] * scale, c1 = sacc[nt][1] * scale;
                float c2 = sacc[nt][2] * scale, c3 = sacc[nt][3] * scale;
                if (edge) {
                    int colb = jt * 64 + nt * 8 + 2 * t;
                    if (colb     > r0) c0 = -1e30f;
                    if (colb + 1 > r0) c1 = -1e30f;
                    if (colb     > r1) c2 = -1e30f;
                    if (colb + 1 > r1) c3 = -1e30f;
                }
                sacc[nt][0] = c0; sacc[nt][1] = c1; sacc[nt][2] = c2; sacc[nt][3] = c3;
                rm0 = fmaxf(rm0, fmaxf(c0, c1));
                rm1 = fmaxf(rm1, fmaxf(c2, c3));
            }
            rm0 = fmaxf(rm0, __shfl_xor_sync(0xffffffffu, rm0, 1));
            rm0 = fmaxf(rm0, __shfl_xor_sync(0xffffffffu, rm0, 2));
            rm1 = fmaxf(rm1, __shfl_xor_sync(0xffffffffu, rm1, 1));
            rm1 = fmaxf(rm1, __shfl_xor_sync(0xffffffffu, rm1, 2));

            float mn0 = fmaxf(mrow0, rm0), mn1 = fmaxf(mrow1, rm1);
            float al0 = __expf(mrow0 - mn0), al1 = __expf(mrow1 - mn1);
            mrow0 = mn0; mrow1 = mn1;

            // ---- P = 2^((s-m)*log2e) via ex2.f16x2; result is the P word ----
            const float mn0L = mn0 * L2E, mn1L = mn1 * L2E;
            uint32_t pu[8][2];
            float rs0 = 0.0f, rs1 = 0.0f;
#pragma unroll
            for (int nt = 0; nt < 8; ++nt) {
                uint32_t a0 = pack2h(fmaf(sacc[nt][0], L2E, -mn0L),
                                     fmaf(sacc[nt][1], L2E, -mn0L));
                uint32_t a1 = pack2h(fmaf(sacc[nt][2], L2E, -mn1L),
                                     fmaf(sacc[nt][3], L2E, -mn1L));
                pu[nt][0] = ex2_h2(a0);
                pu[nt][1] = ex2_h2(a1);
                float2 f0 = __half22float2(*reinterpret_cast<__half2*>(&pu[nt][0]));
                float2 f1 = __half22float2(*reinterpret_cast<__half2*>(&pu[nt][1]));
                rs0 += f0.x + f0.y;
                rs1 += f1.x + f1.y;
            }
            rs0 += __shfl_xor_sync(0xffffffffu, rs0, 1);
            rs0 += __shfl_xor_sync(0xffffffffu, rs0, 2);
            rs1 += __shfl_xor_sync(0xffffffffu, rs1, 1);
            rs1 += __shfl_xor_sync(0xffffffffu, rs1, 2);
            lrow0 = lrow0 * al0 + rs0;
            lrow1 = lrow1 * al1 + rs1;

#pragma unroll
            for (int nt = 0; nt < 16; ++nt) {
                oacc[nt][0] *= al0; oacc[nt][1] *= al0;
                oacc[nt][2] *= al1; oacc[nt][3] *= al1;
            }

#pragma unroll
            for (int ks = 0; ks < 4; ++ks) {
                if (edge && (jt * 64 + ks * 16 > rmax)) continue;
                uint32_t a[4] = {pu[2 * ks][0], pu[2 * ks][1],
                                 pu[2 * ks + 1][0], pu[2 * ks + 1][1]};
                const int c0 = (((2 * ks) ^ gg) & 7) * 4 + t;
                const int c1 = (((2 * ks + 1) ^ gg) & 7) * 4 + t;
#pragma unroll
                for (int nt = 0; nt < 16; ++nt) {
                    int nr = nt * 8 + gg;
                    mma_f16(oacc[nt], a, sV[nr * 32 + c0], sV[nr * 32 + c1]);
                }
            }
        }
    }

    const float inv0 = 1.0f / lrow0, inv1 = 1.0f / lrow1;
    const int r0 = qrow0 + m0 + gg;
#pragma unroll
    for (int nt = 0; nt < 16; ++nt) {
        int wi = h * (HD / 2) + nt * 4 + t;
        o[(size_t)r0 * (QD / 2) + wi]       = pack2h(oacc[nt][0] * inv0, oacc[nt][1] * inv0);
        o[(size_t)(r0 + 8) * (QD / 2) + wi] = pack2h(oacc[nt][2] * inv1, oacc[nt][3] * inv1);
    }
}

// ---------------------------------------------------------------------------
extern "C" void kernel_launch(void* const* d_in, const int* in_sizes, int n_in,
                              void* d_out, int out_size)
{
    (void)in_sizes; (void)n_in; (void)out_size;
    const float* x   = (const float*)d_in[0];
    const float* mu  = (const float*)d_in[1];
    const float* wq  = (const float*)d_in[2];
    const float* wk  = (const float*)d_in[3];
    const float* wv  = (const float*)d_in[4];
    const float* wo  = (const float*)d_in[5];
    const float* wmq = (const float*)d_in[6];
    const float* wmk = (const float*)d_in[7];
    const float* wmv = (const float*)d_in[8];
    const float* qw  = (const float*)d_in[9];
    const float* kw  = (const float*)d_in[10];
    float* out = (float*)d_out;

    float *pq0, *pq1, *pk0, *pk1;
    uint32_t *pqt, *pkt, *pvt, *po;
    uint32_t *pxmu, *pwqc, *pwkc, *pwvc, *pwot;
    float2 *prope;
    cudaGetSymbolAddress((void**)&pq0, g_q);
    cudaGetSymbolAddress((void**)&pq1, g_q1);
    cudaGetSymbolAddress((void**)&pk0, g_k);
    cudaGetSymbolAddress((void**)&pk1, g_k1);
    cudaGetSymbolAddress((void**)&pqt, g_qt);
    cudaGetSymbolAddress((void**)&pkt, g_kt);
    cudaGetSymbolAddress((void**)&pvt, g_vt);
    cudaGetSymbolAddress((void**)&po, g_o);
    cudaGetSymbolAddress((void**)&pxmu, g_xmu);
    cudaGetSymbolAddress((void**)&pwqc, g_wqc);
    cudaGetSymbolAddress((void**)&pwkc, g_wkc);
    cudaGetSymbolAddress((void**)&pwvc, g_wvc);
    cudaGetSymbolAddress((void**)&pwot, g_wot);
    cudaGetSymbolAddress((void**)&prope, g_rope);

    // ---- fused prepass ----
    rope_table<<<SEQ, 64>>>(prope);
    cvt_all<<<12288, 256>>>(pxmu, pwqc, pwkc, pwvc, pwot,
                            x, mu, wq, wmq, wk, wmk, wv, wmv, wo);

    const int gemm_smem = 3 * STAGE_WORDS * 4;  // 98304 bytes
    cudaFuncSetAttribute(qkv_mma,   cudaFuncAttributeMaxDynamicSharedMemorySize, gemm_smem);
    cudaFuncSetAttribute(oproj_mma, cudaFuncAttributeMaxDynamicSharedMemorySize, gemm_smem);

    // Fused QKV projections (fp16 mma, Q/K split-K halves, V full direct-fp16)
    qkv_mma<<<dim3(44, 16), 128, gemm_smem>>>(pxmu, pwqc, pwkc, pwvc,
                                              pq0, pq1, pk0, pk1, pvt);

    // RMSNorm + RoPE; Q and K emitted as fp16x2
    normrope_kernel<<<dim3(SEQ, NH + NKV), 128>>>(pq0, pq1, pk0, pk1, pqt, pkt, qw, kw, prope);

    // causal GQA attention (fp16 mma, P in registers, h2 exp)
    const int attn_smem = ATTN_SMEM_WORDS * 4;  // 100352 bytes
    cudaFuncSetAttribute(attn_mma, cudaFuncAttributeMaxDynamicSharedMemorySize, attn_smem);
    attn_mma<<<dim3(SEQ / 128, NH), 256, attn_smem>>>(pqt, pkt, pvt, po);

    // output projection (fp16 mma)
    oproj_mma<<<dim3(16, 16), 128, gemm_smem>>>(po, pwot, out);
}

// round 15
// speedup vs baseline: 2.0744x; 1.0549x over previous
#include <cuda_runtime.h>
#include <cuda_fp16.h>
#include <math.h>
#include <stdint.h>

#define SEQ 2048
#define HID 2048
#define NH 16
#define NKV 4
#define HD 128
#define QD (NH*HD)    /* 2048 */
#define KVD (NKV*HD)  /* 512  */

// Scratch (device globals: no allocations allowed)
__device__ uint32_t g_qt[SEQ*QD/2];          // fp16x2 Q (post-norm+rope)
__device__ uint32_t g_kt[SEQ*KVD/2];         // fp16x2 K (post-norm+rope)
__device__ uint32_t g_vt[KVD*SEQ/2];         // fp16x2 V, transposed [kvd][seq]
__device__ uint32_t g_o[SEQ*QD/2];           // attention output fp16x2
__device__ float2   g_rope[SEQ*64];
// Pre-converted fp16x2 operands (prepass); word = 2 k-consecutive elements
__device__ uint32_t g_xmu[SEQ*2*HID/2];      // [x | mu]  2048 x 2048 words
__device__ uint32_t g_wqc[QD*2*HID/2];
__device__ uint32_t g_wkc[KVD*2*HID/2];
__device__ uint32_t g_wvc[KVD*2*HID/2];
__device__ uint32_t g_wot[HID*QD/2];

// ---------------------------------------------------------------------------
// helpers
// ---------------------------------------------------------------------------
__device__ __forceinline__ uint32_t pack2h(float a, float b) {
    __half2 h = __floats2half2_rn(a, b);
    return *reinterpret_cast<uint32_t*>(&h);
}

__device__ __forceinline__ uint32_t ex2_h2(uint32_t a) {
    uint32_t r;
    asm("ex2.approx.f16x2 %0, %1;" : "=r"(r) : "r"(a));
    return r;
}

__device__ __forceinline__ void mma_f16(float d[4], const uint32_t a[4],
                                        uint32_t b0, uint32_t b1) {
    asm volatile(
        "mma.sync.aligned.m16n8k16.row.col.f32.f16.f16.f32 "
        "{%0,%1,%2,%3}, {%4,%5,%6,%7}, {%8,%9}, {%0,%1,%2,%3};"
        : "+f"(d[0]), "+f"(d[1]), "+f"(d[2]), "+f"(d[3])
        : "r"(a[0]), "r"(a[1]), "r"(a[2]), "r"(a[3]), "r"(b0), "r"(b1));
}

#define CP_ASYNC_CG(dst_u32, src_ptr) \
    asm volatile("cp.async.cg.shared.global [%0], [%1], 16;" :: "r"(dst_u32), "l"(src_ptr) : "memory")
#define CP_COMMIT() asm volatile("cp.async.commit_group;" ::: "memory")
#define CP_WAIT1()  asm volatile("cp.async.wait_group 1;"  ::: "memory")
#define CP_WAIT0()  asm volatile("cp.async.wait_group 0;"  ::: "memory")

__device__ __forceinline__ uint32_t smem_u32(const void* p) {
    uint32_t a;
    asm("{ .reg .u64 t; cvta.to.shared.u64 t, %1; cvt.u32.u64 %0, t; }" : "=r"(a) : "l"(p));
    return a;
}

// ---------------------------------------------------------------------------
// Fused prepass: fp32 -> fp16x2 (+K-concat). 8 elements -> 4 words per thread.
// ---------------------------------------------------------------------------
__global__ __launch_bounds__(256) void cvt_all(
    uint32_t* __restrict__ xmu, uint32_t* __restrict__ wqc,
    uint32_t* __restrict__ wkc, uint32_t* __restrict__ wvc,
    uint32_t* __restrict__ wot,
    const float* __restrict__ x,  const float* __restrict__ mu,
    const float* __restrict__ wq, const float* __restrict__ wmq,
    const float* __restrict__ wk, const float* __restrict__ wmk,
    const float* __restrict__ wv, const float* __restrict__ wmv,
    const float* __restrict__ wo)
{
    long e = ((long)blockIdx.x * 256 + threadIdx.x) * 8;
    const float *A, *B; uint32_t* D; long off; bool cat = true;
    if (e < 8388608L)       { D = xmu; A = x;  B = mu;  off = e; }
    else if (e < 16777216L) { D = wqc; A = wq; B = wmq; off = e - 8388608L; }
    else if (e < 18874368L) { D = wkc; A = wk; B = wmk; off = e - 16777216L; }
    else if (e < 20971520L) { D = wvc; A = wv; B = wmv; off = e - 18874368L; }
    else                    { D = wot; A = wo; B = wo;  off = e - 20971520L; cat = false; }

    const float* src;
    if (cat) {
        int r = (int)(off >> 12);
        int c = (int)(off & 4095);
        src = (c < 2048) ? (A + (size_t)r * 2048 + c) : (B + (size_t)r * 2048 + (c - 2048));
    } else {
        src = A + off;
    }
    float4 v0 = *(const float4*)src;
    float4 v1 = *(const float4*)(src + 4);
    *(uint4*)(D + (off >> 1)) = make_uint4(pack2h(v0.x, v0.y), pack2h(v0.z, v0.w),
                                           pack2h(v1.x, v1.y), pack2h(v1.z, v1.w));
}

// RoPE (cos,sin) table
__global__ __launch_bounds__(64) void rope_table(float2* __restrict__ tab)
{
    const int pos = blockIdx.x;
    const int f = threadIdx.x;
    float ang = (float)pos * powf(10000.0f, -(float)f * (1.0f / 64.0f));
    float sn, cs;
    sincosf(ang, &sn, &cs);
    tab[pos * 64 + f] = make_float2(cs, sn);
}

// ---------------------------------------------------------------------------
// cp.async 3-stage fp16 GEMM core. Words = fp16x2, rows 32 words = 64 elems.
// XOR-chunk swizzle; 128 threads, warp tile 64x64, m16n8k16.
// MODE 0: plain fp32 C. MODE 1: TRANSV fp16x2 transposed write (V).
// MODE 2: fused RMSNorm+RoPE epilogue -> fp16x2 (Q/K; col block == one head).
// ---------------------------------------------------------------------------
#define STG_WORDS 4096            /* 128*32 */
#define STAGE_WORDS (2*STG_WORDS)

template<int MODE>
__device__ __forceinline__ void gemm_core_async(
    const uint32_t* __restrict__ Ablk, const uint32_t* __restrict__ Bblk,
    float* __restrict__ Cblk, int ldc,
    uint32_t* __restrict__ Cth, int row0g, int col0g, int dstStrideW,
    const float* __restrict__ nw, const float2* __restrict__ rope,
    int Kelem, int ldaW, int ldbW, uint32_t* s)
{
    const uint32_t sbyte = smem_u32(s);
    const int tid = threadIdx.x;
    const int wid = tid >> 5, lane = tid & 31;
    const int g = lane >> 2, t = lane & 3;
    const int m0 = (wid >> 1) * 64;
    const int n0 = (wid & 1) * 64;

    const int lr = tid >> 3;
    const int ch = tid & 7;

    float acc[4][8][4];
#pragma unroll
    for (int i = 0; i < 4; ++i)
#pragma unroll
        for (int j = 0; j < 8; ++j)
#pragma unroll
            for (int q = 0; q < 4; ++q) acc[i][j][q] = 0.0f;

    const int nch = Kelem >> 6;
    const int chsw = ch ^ (lr & 7);

    auto issue = [&](int st, int cc) {
        const uint32_t sa0 = sbyte + (uint32_t)(st * STAGE_WORDS) * 4u;
        const uint32_t sb0 = sa0 + STG_WORDS * 4u;
        const int kkw = cc << 5;
#pragma unroll
        for (int i = 0; i < 8; ++i) {
            int r = lr + i * 16;
            uint32_t so = (uint32_t)(r * 32 + chsw * 4) * 4u;
            CP_ASYNC_CG(sa0 + so, Ablk + (size_t)r * ldaW + kkw + ch * 4);
            CP_ASYNC_CG(sb0 + so, Bblk + (size_t)r * ldbW + kkw + ch * 4);
        }
    };

    issue(0, 0); CP_COMMIT();
    issue(1, 1); CP_COMMIT();

    for (int c = 0; c < nch; ++c) {
        CP_WAIT1();
        __syncthreads();
        if (c + 2 < nch) issue((c + 2) % 3, c + 2);
        CP_COMMIT();

        const uint32_t* sA = s + (c % 3) * STAGE_WORDS;
        const uint32_t* sB = sA + STG_WORDS;
#pragma unroll
        for (int ks = 0; ks < 4; ++ks) {
            const int e1 = (((2 * ks) ^ g) << 2) + t;
            const int e2 = (((2 * ks) ^ g ^ 1) << 2) + t;
            uint32_t af[4][4], bf[8][2];
#pragma unroll
            for (int mt = 0; mt < 4; ++mt) {
                int mr = m0 + mt * 16 + g;
                af[mt][0] = sA[mr * 32 + e1];
                af[mt][1] = sA[(mr + 8) * 32 + e1];
                af[mt][2] = sA[mr * 32 + e2];
                af[mt][3] = sA[(mr + 8) * 32 + e2];
            }
#pragma unroll
            for (int nt = 0; nt < 8; ++nt) {
                int nr = n0 + nt * 8 + g;
                bf[nt][0] = sB[nr * 32 + e1];
                bf[nt][1] = sB[nr * 32 + e2];
            }
#pragma unroll
            for (int mt = 0; mt < 4; ++mt)
#pragma unroll
                for (int nt = 0; nt < 8; ++nt)
                    mma_f16(acc[mt][nt], af[mt], bf[nt][0], bf[nt][1]);
        }
    }

    if (MODE == 2) {
        // ---- fused RMSNorm + RoPE epilogue (col block == one head) ----
        __syncthreads();                      // pipeline smem free now
        float* st = (float*)s;                // [128][132] raw acc staging
        float* ssb = (float*)s + 128 * 132;   // [128][2] per-N-half row ss

        // 1) partial row sum-of-squares (quad reduce) + stage raw acc
#pragma unroll
        for (int mt = 0; mt < 4; ++mt) {
            float s0 = 0.0f, s1 = 0.0f;
            int r0 = m0 + mt * 16 + g;
#pragma unroll
            for (int nt = 0; nt < 8; ++nt) {
                float a0 = acc[mt][nt][0], a1 = acc[mt][nt][1];
                float a2 = acc[mt][nt][2], a3 = acc[mt][nt][3];
                s0 += a0 * a0 + a1 * a1;
                s1 += a2 * a2 + a3 * a3;
                int cc = n0 + nt * 8 + 2 * t;
                *(float2*)&st[r0 * 132 + cc]       = make_float2(a0, a1);
                *(float2*)&st[(r0 + 8) * 132 + cc] = make_float2(a2, a3);
            }
            s0 += __shfl_xor_sync(0xffffffffu, s0, 1);
            s0 += __shfl_xor_sync(0xffffffffu, s0, 2);
            s1 += __shfl_xor_sync(0xffffffffu, s1, 1);
            s1 += __shfl_xor_sync(0xffffffffu, s1, 2);
            if (t == 0) {
                ssb[r0 * 2 + (wid & 1)]       = s0;
                ssb[(r0 + 8) * 2 + (wid & 1)] = s1;
            }
        }
        __syncthreads();

        // 2) normalize + rope + pack fp16x2 + write
        const float sgn = (wid & 1) ? 1.0f : -1.0f;   // n0=64: +sin; n0=0: -sin
#pragma unroll
        for (int mt = 0; mt < 4; ++mt) {
            int r0 = m0 + mt * 16 + g;
            int r1 = r0 + 8;
            float inv0 = rsqrtf((ssb[r0 * 2] + ssb[r0 * 2 + 1]) * (1.0f / 128.0f) + 1e-6f);
            float inv1 = rsqrtf((ssb[r1 * 2] + ssb[r1 * 2 + 1]) * (1.0f / 128.0f) + 1e-6f);
#pragma unroll
            for (int nt = 0; nt < 8; ++nt) {
                int cc = n0 + nt * 8 + 2 * t;        // even col
                int f = cc & 63;
                float w0 = nw[cc], w1 = nw[cc + 1];
                float wp0 = nw[cc ^ 64], wp1 = nw[(cc ^ 64) + 1];
                float2 cs0 = rope[(size_t)(row0g + r0) * 64 + f];
                float2 cs0b = rope[(size_t)(row0g + r0) * 64 + f + 1];
                float2 cs1 = rope[(size_t)(row0g + r1) * 64 + f];
                float2 cs1b = rope[(size_t)(row0g + r1) * 64 + f + 1];
                float2 p0 = *(const float2*)&st[r0 * 132 + (cc ^ 64)];
                float2 p1 = *(const float2*)&st[r1 * 132 + (cc ^ 64)];
                float o00 = acc[mt][nt][0] * inv0 * w0 * cs0.x  + sgn * p0.x * inv0 * wp0 * cs0.y;
                float o01 = acc[mt][nt][1] * inv0 * w1 * cs0b.x + sgn * p0.y * inv0 * wp1 * cs0b.y;
                float o10 = acc[mt][nt][2] * inv1 * w0 * cs1.x  + sgn * p1.x * inv1 * wp0 * cs1.y;
                float o11 = acc[mt][nt][3] * inv1 * w1 * cs1b.x + sgn * p1.y * inv1 * wp1 * cs1b.y;
                Cth[(size_t)(row0g + r0) * dstStrideW + (cc >> 1)] = pack2h(o00, o01);
                Cth[(size_t)(row0g + r1) * dstStrideW + (cc >> 1)] = pack2h(o10, o11);
            }
        }
        return;
    }

#pragma unroll
    for (int mt = 0; mt < 4; ++mt) {
        int r0 = m0 + mt * 16 + g;
#pragma unroll
        for (int nt = 0; nt < 8; ++nt) {
            int cc = n0 + nt * 8 + 2 * t;
            if (MODE == 1) {
                float p0 = acc[mt][nt][0], q0 = __shfl_xor_sync(0xffffffffu, p0, 4);
                float p1 = acc[mt][nt][1], q1 = __shfl_xor_sync(0xffffffffu, p1, 4);
                float p2 = acc[mt][nt][2], q2 = __shfl_xor_sync(0xffffffffu, p2, 4);
                float p3 = acc[mt][nt][3], q3 = __shfl_xor_sync(0xffffffffu, p3, 4);
                if (!(g & 1)) {
                    size_t w0 = (size_t)(col0g + cc)     * (SEQ / 2);
                    size_t w1 = (size_t)(col0g + cc + 1) * (SEQ / 2);
                    int rw0 = (row0g + r0) >> 1;
                    int rw1 = (row0g + r0 + 8) >> 1;
                    Cth[w0 + rw0] = pack2h(p0, q0);
                    Cth[w1 + rw0] = pack2h(p1, q1);
                    Cth[w0 + rw1] = pack2h(p2, q2);
                    Cth[w1 + rw1] = pack2h(p3, q3);
                }
            } else {
                *(float2*)(Cblk + (size_t)r0 * ldc + cc)       = make_float2(acc[mt][nt][0], acc[mt][nt][1]);
                *(float2*)(Cblk + (size_t)(r0 + 8) * ldc + cc) = make_float2(acc[mt][nt][2], acc[mt][nt][3]);
            }
        }
    }
}

// Fused QKV: grid (24, 16), 128 threads, all full K=4096.
// x 0..3 -> V (TRANSV fp16 direct), 4..19 -> Q (fused norm+rope), 20..23 -> K.
__global__ __launch_bounds__(128, 2) void qkv_mma(
    const uint32_t* __restrict__ xmu,
    const uint32_t* __restrict__ wqc, const uint32_t* __restrict__ wkc,
    const uint32_t* __restrict__ wvc,
    uint32_t* __restrict__ pqt, uint32_t* __restrict__ pkt,
    uint32_t* __restrict__ pvt,
    const float* __restrict__ qw, const float* __restrict__ kw,
    const float2* __restrict__ rope)
{
    extern __shared__ uint32_t smem[];
    const int xb = blockIdx.x;
    const int row0 = blockIdx.y * 128;
    const uint32_t* A = xmu + (size_t)row0 * HID;

    if (xb < 4) {
        const int ccol = xb * 128;
        gemm_core_async<1>(A, wvc + (size_t)ccol * HID,
                           nullptr, 0, pvt, row0, ccol, 0, nullptr, nullptr,
                           2 * HID, HID, HID, smem);
    } else if (xb < 20) {
        const int head = xb - 4;
        gemm_core_async<2>(A, wqc + (size_t)(head * 128) * HID,
                           nullptr, 0, pqt + head * (HD / 2), row0, 0, QD / 2,
                           qw, rope, 2 * HID, HID, HID, smem);
    } else {
        const int head = xb - 20;
        gemm_core_async<2>(A, wkc + (size_t)(head * 128) * HID,
                           nullptr, 0, pkt + head * (HD / 2), row0, 0, KVD / 2,
                           kw, rope, 2 * HID, HID, HID, smem);
    }
}

// Output projection: grid = (16, 16), 128 threads
__global__ __launch_bounds__(128, 2) void oproj_mma(
    const uint32_t* __restrict__ A, const uint32_t* __restrict__ B, float* __restrict__ C)
{
    extern __shared__ uint32_t smem[];
    const int row0 = blockIdx.y * 128;
    const int ccol = blockIdx.x * 128;
    gemm_core_async<0>(A + (size_t)row0 * (QD / 2), B + (size_t)ccol * (QD / 2),
                       C + (size_t)row0 * QD + ccol, QD,
                       nullptr, 0, 0, 0, nullptr, nullptr,
                       QD, QD / 2, QD / 2, smem);
}

// ---------------------------------------------------------------------------
// fp16 causal flash attention (unchanged from R14 best)
// ---------------------------------------------------------------------------
#define ATTN_SMEM_WORDS 25088

__global__ __launch_bounds__(256, 1) void attn_mma(
    const uint32_t* __restrict__ qt, const uint32_t* __restrict__ kt,
    const uint32_t* __restrict__ vt, uint32_t* __restrict__ o)
{
    extern __shared__ uint32_t sw[];
    uint32_t* sQ = sw + 16384;    // [128][68]
    const uint32_t sbyte = smem_u32(sw);

    const int qt_i = gridDim.x - 1 - blockIdx.x;
    const int h = blockIdx.y;
    const int kvh = h >> 2;
    const int qrow0 = qt_i * 128;
    const int tid = threadIdx.x;
    const int w = tid >> 5, lane = tid & 31;
    const int gg = lane >> 2, t = lane & 3;
    const int m0 = w * 16;
    const int jmax = 2 * qt_i + 2;
    const int rmax = qrow0 + m0 + 15;

    auto issueKV = [&](int b, int jt) {
        const uint32_t kb0 = sbyte + (uint32_t)(b ? 8192 : 0) * 4u;
        const uint32_t vb0 = kb0 + 4096u * 4u;
#pragma unroll
        for (int i = 0; i < 4; ++i) {
            int id = tid + i * 256;
            int r = id >> 4, c = id & 15;
            int cs = (c & 8) | ((c & 7) ^ (r & 7));
            CP_ASYNC_CG(kb0 + (uint32_t)(r * 64 + cs * 4) * 4u,
                        kt + (size_t)(jt * 64 + r) * (KVD / 2) + kvh * (HD / 2) + c * 4);
        }
#pragma unroll
        for (int i = 0; i < 4; ++i) {
            int id = tid + i * 256;
            int r = id >> 3, c = id & 7;
            int cs = c ^ (r & 7);
            CP_ASYNC_CG(vb0 + (uint32_t)(r * 32 + cs * 4) * 4u,
                        vt + (size_t)(kvh * HD + r) * (SEQ / 2) + jt * 32 + c * 4);
        }
    };

    issueKV(0, 0); CP_COMMIT();

#pragma unroll
    for (int i = 0; i < 8; ++i) {
        int id = tid + i * 256;
        int r = id >> 4, w4 = (id & 15) << 2;
        uint4 v = *(const uint4*)(qt + (size_t)(qrow0 + r) * (QD / 2) + h * (HD / 2) + w4);
        sQ[r * 68 + w4 + 0] = v.x;
        sQ[r * 68 + w4 + 1] = v.y;
        sQ[r * 68 + w4 + 2] = v.z;
        sQ[r * 68 + w4 + 3] = v.w;
    }
    __syncthreads();

    uint32_t qf[8][4];
#pragma unroll
    for (int ks = 0; ks < 8; ++ks) {
        qf[ks][0] = sQ[(m0 + gg) * 68 + ks * 8 + t];
        qf[ks][1] = sQ[(m0 + gg + 8) * 68 + ks * 8 + t];
        qf[ks][2] = sQ[(m0 + gg) * 68 + ks * 8 + 4 + t];
        qf[ks][3] = sQ[(m0 + gg + 8) * 68 + ks * 8 + 4 + t];
    }

    float oacc[16][4];
#pragma unroll
    for (int i = 0; i < 16; ++i)
#pragma unroll
        for (int j = 0; j < 4; ++j) oacc[i][j] = 0.0f;
    float mrow0 = -1e30f, mrow1 = -1e30f, lrow0 = 0.0f, lrow1 = 0.0f;

    const float scale = 0.08838834764831845f;
    const float L2E = 1.4426950408889634f;

    for (int jt = 0; jt < jmax; ++jt) {
        CP_WAIT0();
        __syncthreads();
        if (jt + 1 < jmax) { issueKV((jt + 1) & 1, jt + 1); CP_COMMIT(); }

        const uint32_t* sK = sw + ((jt & 1) ? 8192 : 0);
        const uint32_t* sV = sK + 4096;

        const bool edge = (jt >= 2 * qt_i);
        const bool active = (jt * 64 <= rmax);
        if (active) {
            float sacc[8][4];
#pragma unroll
            for (int i = 0; i < 8; ++i)
#pragma unroll
                for (int j = 0; j < 4; ++j) sacc[i][j] = 0.0f;

            if (!edge) {
#pragma unroll
                for (int ks = 0; ks < 8; ++ks) {
                    const int c0 = (((2 * ks) & 8) | (((2 * ks) & 7) ^ gg)) * 4 + t;
                    const int c1 = (((2 * ks + 1) & 8) | (((2 * ks + 1) & 7) ^ gg)) * 4 + t;
#pragma unroll
                    for (int nt = 0; nt < 8; ++nt) {
                        int nr = nt * 8 + gg;
                        mma_f16(sacc[nt], qf[ks], sK[nr * 64 + c0], sK[nr * 64 + c1]);
                    }
                }
            } else {
#pragma unroll
                for (int nt = 0; nt < 8; ++nt) {
                    if (jt * 64 + nt * 8 <= rmax) {
                        const int nr = nt * 8 + gg;
#pragma unroll
                        for (int ks = 0; ks < 8; ++ks) {
                            const int c0 = (((2 * ks) & 8) | (((2 * ks) & 7) ^ gg)) * 4 + t;
                            const int c1 = (((2 * ks + 1) & 8) | (((2 * ks + 1) & 7) ^ gg)) * 4 + t;
                            mma_f16(sacc[nt], qf[ks], sK[nr * 64 + c0], sK[nr * 64 + c1]);
                        }
                    }
                }
            }

            const int r0 = qrow0 + m0 + gg;
            const int r1 = r0 + 8;
            float rm0 = -1e30f, rm1 = -1e30f;
#pragma unroll
            for (int nt = 0; nt < 8; ++nt) {
                float c0 = sacc[nt][0] * scale, c1 = sacc[nt][1] * scale;
                float c2 = sacc[nt][2] * scale, c3 = sacc[nt][3] * scale;
                if (edge) {
                    int colb = jt * 64 + nt * 8 + 2 * t;
                    if (colb     > r0) c0 = -1e30f;
                    if (colb + 1 > r0) c1 = -1e30f;
                    if (colb     > r1) c2 = -1e30f;
                    if (colb + 1 > r1) c3 = -1e30f;
                }
                sacc[nt][0] = c0; sacc[nt][1] = c1; sacc[nt][2] = c2; sacc[nt][3] = c3;
                rm0 = fmaxf(rm0, fmaxf(c0, c1));
                rm1 = fmaxf(rm1, fmaxf(c2, c3));
            }
            rm0 = fmaxf(rm0, __shfl_xor_sync(0xffffffffu, rm0, 1));
            rm0 = fmaxf(rm0, __shfl_xor_sync(0xffffffffu, rm0, 2));
            rm1 = fmaxf(rm1, __shfl_xor_sync(0xffffffffu, rm1, 1));
            rm1 = fmaxf(rm1, __shfl_xor_sync(0xffffffffu, rm1, 2));

            float mn0 = fmaxf(mrow0, rm0), mn1 = fmaxf(mrow1, rm1);
            float al0 = __expf(mrow0 - mn0), al1 = __expf(mrow1 - mn1);
            mrow0 = mn0; mrow1 = mn1;

            const float mn0L = mn0 * L2E, mn1L = mn1 * L2E;
            uint32_t pu[8][2];
            float rs0 = 0.0f, rs1 = 0.0f;
#pragma unroll
            for (int nt = 0; nt < 8; ++nt) {
                uint32_t a0 = pack2h(fmaf(sacc[nt][0], L2E, -mn0L),
                                     fmaf(sacc[nt][1], L2E, -mn0L));
                uint32_t a1 = pack2h(fmaf(sacc[nt][2], L2E, -mn1L),
                                     fmaf(sacc[nt][3], L2E, -mn1L));
                pu[nt][0] = ex2_h2(a0);
                pu[nt][1] = ex2_h2(a1);
                float2 f0 = __half22float2(*reinterpret_cast<__half2*>(&pu[nt][0]));
                float2 f1 = __half22float2(*reinterpret_cast<__half2*>(&pu[nt][1]));
                rs0 += f0.x + f0.y;
                rs1 += f1.x + f1.y;
            }
            rs0 += __shfl_xor_sync(0xffffffffu, rs0, 1);
            rs0 += __shfl_xor_sync(0xffffffffu, rs0, 2);
            rs1 += __shfl_xor_sync(0xffffffffu, rs1, 1);
            rs1 += __shfl_xor_sync(0xffffffffu, rs1, 2);
            lrow0 = lrow0 * al0 + rs0;
            lrow1 = lrow1 * al1 + rs1;

#pragma unroll
            for (int nt = 0; nt < 16; ++nt) {
                oacc[nt][0] *= al0; oacc[nt][1] *= al0;
                oacc[nt][2] *= al1; oacc[nt][3] *= al1;
            }

#pragma unroll
            for (int ks = 0; ks < 4; ++ks) {
                if (edge && (jt * 64 + ks * 16 > rmax)) continue;
                uint32_t a[4] = {pu[2 * ks][0], pu[2 * ks][1],
                                 pu[2 * ks + 1][0], pu[2 * ks + 1][1]};
                const int c0 = (((2 * ks) ^ gg) & 7) * 4 + t;
                const int c1 = (((2 * ks + 1) ^ gg) & 7) * 4 + t;
#pragma unroll
                for (int nt = 0; nt < 16; ++nt) {
                    int nr = nt * 8 + gg;
                    mma_f16(oacc[nt], a, sV[nr * 32 + c0], sV[nr * 32 + c1]);
                }
            }
        }
    }

    const float inv0 = 1.0f / lrow0, inv1 = 1.0f / lrow1;
    const int r0 = qrow0 + m0 + gg;
#pragma unroll
    for (int nt = 0; nt < 16; ++nt) {
        int wi = h * (HD / 2) + nt * 4 + t;
        o[(size_t)r0 * (QD / 2) + wi]       = pack2h(oacc[nt][0] * inv0, oacc[nt][1] * inv0);
        o[(size_t)(r0 + 8) * (QD / 2) + wi] = pack2h(oacc[nt][2] * inv1, oacc[nt][3] * inv1);
    }
}

// ---------------------------------------------------------------------------
extern "C" void kernel_launch(void* const* d_in, const int* in_sizes, int n_in,
                              void* d_out, int out_size)
{
    (void)in_sizes; (void)n_in; (void)out_size;
    const float* x   = (const float*)d_in[0];
    const float* mu  = (const float*)d_in[1];
    const float* wq  = (const float*)d_in[2];
    const float* wk  = (const float*)d_in[3];
    const float* wv  = (const float*)d_in[4];
    const float* wo  = (const float*)d_in[5];
    const float* wmq = (const float*)d_in[6];
    const float* wmk = (const float*)d_in[7];
    const float* wmv = (const float*)d_in[8];
    const float* qw  = (const float*)d_in[9];
    const float* kw  = (const float*)d_in[10];
    float* out = (float*)d_out;

    uint32_t *pqt, *pkt, *pvt, *po;
    uint32_t *pxmu, *pwqc, *pwkc, *pwvc, *pwot;
    float2 *prope;
    cudaGetSymbolAddress((void**)&pqt, g_qt);
    cudaGetSymbolAddress((void**)&pkt, g_kt);
    cudaGetSymbolAddress((void**)&pvt, g_vt);
    cudaGetSymbolAddress((void**)&po, g_o);
    cudaGetSymbolAddress((void**)&pxmu, g_xmu);
    cudaGetSymbolAddress((void**)&pwqc, g_wqc);
    cudaGetSymbolAddress((void**)&pwkc, g_wkc);
    cudaGetSymbolAddress((void**)&pwvc, g_wvc);
    cudaGetSymbolAddress((void**)&pwot, g_wot);
    cudaGetSymbolAddress((void**)&prope, g_rope);

    // ---- fused prepass ----
    rope_table<<<SEQ, 64>>>(prope);
    cvt_all<<<12288, 256>>>(pxmu, pwqc, pwkc, pwvc, pwot,
                            x, mu, wq, wmq, wk, wmk, wv, wmv, wo);

    const int gemm_smem = 3 * STAGE_WORDS * 4;  // 98304 bytes
    cudaFuncSetAttribute(qkv_mma,   cudaFuncAttributeMaxDynamicSharedMemorySize, gemm_smem);
    cudaFuncSetAttribute(oproj_mma, cudaFuncAttributeMaxDynamicSharedMemorySize, gemm_smem);

    // Fused QKV + RMSNorm + RoPE (Q/K) + V transpose, all fp16 outputs
    qkv_mma<<<dim3(24, 16), 128, gemm_smem>>>(pxmu, pwqc, pwkc, pwvc,
                                              pqt, pkt, pvt, qw, kw, prope);

    // causal GQA attention (fp16 mma, P in registers, h2 exp)
    const int attn_smem = ATTN_SMEM_WORDS * 4;  // 100352 bytes
    cudaFuncSetAttribute(attn_mma, cudaFuncAttributeMaxDynamicSharedMemorySize, attn_smem);
    attn_mma<<<dim3(SEQ / 128, NH), 256, attn_smem>>>(pqt, pkt, pvt, po);

    // output projection (fp16 mma)
    oproj_mma<<<dim3(16, 16), 128, gemm_smem>>>(po, pwot, out);
}

// round 16
// speedup vs baseline: 2.1454x; 1.0343x over previous
#include <cuda_runtime.h>
#include <cuda_fp16.h>
#include <math.h>
#include <stdint.h>

#define SEQ 2048
#define HID 2048
#define NH 16
#define NKV 4
#define HD 128
#define QD (NH*HD)    /* 2048 */
#define KVD (NKV*HD)  /* 512  */

// Scratch (device globals: no allocations allowed)
__device__ uint32_t g_qt[SEQ*QD/2];          // fp16x2 Q (post-norm+rope)
__device__ uint32_t g_kt[SEQ*KVD/2];         // fp16x2 K (post-norm+rope)
__device__ uint32_t g_vt[KVD*SEQ/2];         // fp16x2 V, transposed [kvd][seq]
__device__ uint32_t g_o[SEQ*QD/2];           // attention output fp16x2
__device__ float2   g_rope[SEQ*64];
// Pre-converted fp16x2 operands (prepass); word = 2 k-consecutive elements
__device__ uint32_t g_xmu[SEQ*2*HID/2];      // [x | mu]  2048 x 2048 words
__device__ uint32_t g_wqc[QD*2*HID/2];
__device__ uint32_t g_wkc[KVD*2*HID/2];
__device__ uint32_t g_wvc[KVD*2*HID/2];
__device__ uint32_t g_wot[HID*QD/2];

// ---------------------------------------------------------------------------
// helpers
// ---------------------------------------------------------------------------
__device__ __forceinline__ uint32_t pack2h(float a, float b) {
    __half2 h = __floats2half2_rn(a, b);
    return *reinterpret_cast<uint32_t*>(&h);
}

__device__ __forceinline__ uint32_t ex2_h2(uint32_t a) {
    uint32_t r;
    asm("ex2.approx.f16x2 %0, %1;" : "=r"(r) : "r"(a));
    return r;
}

__device__ __forceinline__ void mma_f16(float d[4], const uint32_t a[4],
                                        uint32_t b0, uint32_t b1) {
    asm volatile(
        "mma.sync.aligned.m16n8k16.row.col.f32.f16.f16.f32 "
        "{%0,%1,%2,%3}, {%4,%5,%6,%7}, {%8,%9}, {%0,%1,%2,%3};"
        : "+f"(d[0]), "+f"(d[1]), "+f"(d[2]), "+f"(d[3])
        : "r"(a[0]), "r"(a[1]), "r"(a[2]), "r"(a[3]), "r"(b0), "r"(b1));
}

#define CP_ASYNC_CG(dst_u32, src_ptr) \
    asm volatile("cp.async.cg.shared.global [%0], [%1], 16;" :: "r"(dst_u32), "l"(src_ptr) : "memory")
#define CP_COMMIT() asm volatile("cp.async.commit_group;" ::: "memory")
#define CP_WAIT1()  asm volatile("cp.async.wait_group 1;"  ::: "memory")
#define CP_WAIT0()  asm volatile("cp.async.wait_group 0;"  ::: "memory")

__device__ __forceinline__ uint32_t smem_u32(const void* p) {
    uint32_t a;
    asm("{ .reg .u64 t; cvta.to.shared.u64 t, %1; cvt.u32.u64 %0, t; }" : "=r"(a) : "l"(p));
    return a;
}

// ---------------------------------------------------------------------------
// Fused prepass: fp32 -> fp16x2 (+K-concat). 8 elements -> 4 words per thread.
// ---------------------------------------------------------------------------
__global__ __launch_bounds__(256) void cvt_all(
    uint32_t* __restrict__ xmu, uint32_t* __restrict__ wqc,
    uint32_t* __restrict__ wkc, uint32_t* __restrict__ wvc,
    uint32_t* __restrict__ wot,
    const float* __restrict__ x,  const float* __restrict__ mu,
    const float* __restrict__ wq, const float* __restrict__ wmq,
    const float* __restrict__ wk, const float* __restrict__ wmk,
    const float* __restrict__ wv, const float* __restrict__ wmv,
    const float* __restrict__ wo)
{
    long e = ((long)blockIdx.x * 256 + threadIdx.x) * 8;
    const float *A, *B; uint32_t* D; long off; bool cat = true;
    if (e < 8388608L)       { D = xmu; A = x;  B = mu;  off = e; }
    else if (e < 16777216L) { D = wqc; A = wq; B = wmq; off = e - 8388608L; }
    else if (e < 18874368L) { D = wkc; A = wk; B = wmk; off = e - 16777216L; }
    else if (e < 20971520L) { D = wvc; A = wv; B = wmv; off = e - 18874368L; }
    else                    { D = wot; A = wo; B = wo;  off = e - 20971520L; cat = false; }

    const float* src;
    if (cat) {
        int r = (int)(off >> 12);
        int c = (int)(off & 4095);
        src = (c < 2048) ? (A + (size_t)r * 2048 + c) : (B + (size_t)r * 2048 + (c - 2048));
    } else {
        src = A + off;
    }
    float4 v0 = *(const float4*)src;
    float4 v1 = *(const float4*)(src + 4);
    *(uint4*)(D + (off >> 1)) = make_uint4(pack2h(v0.x, v0.y), pack2h(v0.z, v0.w),
                                           pack2h(v1.x, v1.y), pack2h(v1.z, v1.w));
}

// RoPE (cos,sin) table
__global__ __launch_bounds__(64) void rope_table(float2* __restrict__ tab)
{
    const int pos = blockIdx.x;
    const int f = threadIdx.x;
    float ang = (float)pos * powf(10000.0f, -(float)f * (1.0f / 64.0f));
    float sn, cs;
    sincosf(ang, &sn, &cs);
    tab[pos * 64 + f] = make_float2(cs, sn);
}

// ---------------------------------------------------------------------------
// cp.async 3-stage fp16 GEMM core (unchanged from R15).
// MODE 0: plain fp32 C. MODE 1: TRANSV fp16x2 transposed write (V).
// MODE 2: fused RMSNorm+RoPE epilogue -> fp16x2 (Q/K; col block == one head).
// ---------------------------------------------------------------------------
#define STG_WORDS 4096            /* 128*32 */
#define STAGE_WORDS (2*STG_WORDS)

template<int MODE>
__device__ __forceinline__ void gemm_core_async(
    const uint32_t* __restrict__ Ablk, const uint32_t* __restrict__ Bblk,
    float* __restrict__ Cblk, int ldc,
    uint32_t* __restrict__ Cth, int row0g, int col0g, int dstStrideW,
    const float* __restrict__ nw, const float2* __restrict__ rope,
    int Kelem, int ldaW, int ldbW, uint32_t* s)
{
    const uint32_t sbyte = smem_u32(s);
    const int tid = threadIdx.x;
    const int wid = tid >> 5, lane = tid & 31;
    const int g = lane >> 2, t = lane & 3;
    const int m0 = (wid >> 1) * 64;
    const int n0 = (wid & 1) * 64;

    const int lr = tid >> 3;
    const int ch = tid & 7;

    float acc[4][8][4];
#pragma unroll
    for (int i = 0; i < 4; ++i)
#pragma unroll
        for (int j = 0; j < 8; ++j)
#pragma unroll
            for (int q = 0; q < 4; ++q) acc[i][j][q] = 0.0f;

    const int nch = Kelem >> 6;
    const int chsw = ch ^ (lr & 7);

    auto issue = [&](int st, int cc) {
        const uint32_t sa0 = sbyte + (uint32_t)(st * STAGE_WORDS) * 4u;
        const uint32_t sb0 = sa0 + STG_WORDS * 4u;
        const int kkw = cc << 5;
#pragma unroll
        for (int i = 0; i < 8; ++i) {
            int r = lr + i * 16;
            uint32_t so = (uint32_t)(r * 32 + chsw * 4) * 4u;
            CP_ASYNC_CG(sa0 + so, Ablk + (size_t)r * ldaW + kkw + ch * 4);
            CP_ASYNC_CG(sb0 + so, Bblk + (size_t)r * ldbW + kkw + ch * 4);
        }
    };

    issue(0, 0); CP_COMMIT();
    issue(1, 1); CP_COMMIT();

    for (int c = 0; c < nch; ++c) {
        CP_WAIT1();
        __syncthreads();
        if (c + 2 < nch) issue((c + 2) % 3, c + 2);
        CP_COMMIT();

        const uint32_t* sA = s + (c % 3) * STAGE_WORDS;
        const uint32_t* sB = sA + STG_WORDS;
#pragma unroll
        for (int ks = 0; ks < 4; ++ks) {
            const int e1 = (((2 * ks) ^ g) << 2) + t;
            const int e2 = (((2 * ks) ^ g ^ 1) << 2) + t;
            uint32_t af[4][4], bf[8][2];
#pragma unroll
            for (int mt = 0; mt < 4; ++mt) {
                int mr = m0 + mt * 16 + g;
                af[mt][0] = sA[mr * 32 + e1];
                af[mt][1] = sA[(mr + 8) * 32 + e1];
                af[mt][2] = sA[mr * 32 + e2];
                af[mt][3] = sA[(mr + 8) * 32 + e2];
            }
#pragma unroll
            for (int nt = 0; nt < 8; ++nt) {
                int nr = n0 + nt * 8 + g;
                bf[nt][0] = sB[nr * 32 + e1];
                bf[nt][1] = sB[nr * 32 + e2];
            }
#pragma unroll
            for (int mt = 0; mt < 4; ++mt)
#pragma unroll
                for (int nt = 0; nt < 8; ++nt)
                    mma_f16(acc[mt][nt], af[mt], bf[nt][0], bf[nt][1]);
        }
    }

    if (MODE == 2) {
        __syncthreads();
        float* st = (float*)s;
        float* ssb = (float*)s + 128 * 132;

#pragma unroll
        for (int mt = 0; mt < 4; ++mt) {
            float s0 = 0.0f, s1 = 0.0f;
            int r0 = m0 + mt * 16 + g;
#pragma unroll
            for (int nt = 0; nt < 8; ++nt) {
                float a0 = acc[mt][nt][0], a1 = acc[mt][nt][1];
                float a2 = acc[mt][nt][2], a3 = acc[mt][nt][3];
                s0 += a0 * a0 + a1 * a1;
                s1 += a2 * a2 + a3 * a3;
                int cc = n0 + nt * 8 + 2 * t;
                *(float2*)&st[r0 * 132 + cc]       = make_float2(a0, a1);
                *(float2*)&st[(r0 + 8) * 132 + cc] = make_float2(a2, a3);
            }
            s0 += __shfl_xor_sync(0xffffffffu, s0, 1);
            s0 += __shfl_xor_sync(0xffffffffu, s0, 2);
            s1 += __shfl_xor_sync(0xffffffffu, s1, 1);
            s1 += __shfl_xor_sync(0xffffffffu, s1, 2);
            if (t == 0) {
                ssb[r0 * 2 + (wid & 1)]       = s0;
                ssb[(r0 + 8) * 2 + (wid & 1)] = s1;
            }
        }
        __syncthreads();

        const float sgn = (wid & 1) ? 1.0f : -1.0f;
#pragma unroll
        for (int mt = 0; mt < 4; ++mt) {
            int r0 = m0 + mt * 16 + g;
            int r1 = r0 + 8;
            float inv0 = rsqrtf((ssb[r0 * 2] + ssb[r0 * 2 + 1]) * (1.0f / 128.0f) + 1e-6f);
            float inv1 = rsqrtf((ssb[r1 * 2] + ssb[r1 * 2 + 1]) * (1.0f / 128.0f) + 1e-6f);
#pragma unroll
            for (int nt = 0; nt < 8; ++nt) {
                int cc = n0 + nt * 8 + 2 * t;
                int f = cc & 63;
                float w0 = nw[cc], w1 = nw[cc + 1];
                float wp0 = nw[cc ^ 64], wp1 = nw[(cc ^ 64) + 1];
                float2 cs0 = rope[(size_t)(row0g + r0) * 64 + f];
                float2 cs0b = rope[(size_t)(row0g + r0) * 64 + f + 1];
                float2 cs1 = rope[(size_t)(row0g + r1) * 64 + f];
                float2 cs1b = rope[(size_t)(row0g + r1) * 64 + f + 1];
                float2 p0 = *(const float2*)&st[r0 * 132 + (cc ^ 64)];
                float2 p1 = *(const float2*)&st[r1 * 132 + (cc ^ 64)];
                float o00 = acc[mt][nt][0] * inv0 * w0 * cs0.x  + sgn * p0.x * inv0 * wp0 * cs0.y;
                float o01 = acc[mt][nt][1] * inv0 * w1 * cs0b.x + sgn * p0.y * inv0 * wp1 * cs0b.y;
                float o10 = acc[mt][nt][2] * inv1 * w0 * cs1.x  + sgn * p1.x * inv1 * wp0 * cs1.y;
                float o11 = acc[mt][nt][3] * inv1 * w1 * cs1b.x + sgn * p1.y * inv1 * wp1 * cs1b.y;
                Cth[(size_t)(row0g + r0) * dstStrideW + (cc >> 1)] = pack2h(o00, o01);
                Cth[(size_t)(row0g + r1) * dstStrideW + (cc >> 1)] = pack2h(o10, o11);
            }
        }
        return;
    }

#pragma unroll
    for (int mt = 0; mt < 4; ++mt) {
        int r0 = m0 + mt * 16 + g;
#pragma unroll
        for (int nt = 0; nt < 8; ++nt) {
            int cc = n0 + nt * 8 + 2 * t;
            if (MODE == 1) {
                float p0 = acc[mt][nt][0], q0 = __shfl_xor_sync(0xffffffffu, p0, 4);
                float p1 = acc[mt][nt][1], q1 = __shfl_xor_sync(0xffffffffu, p1, 4);
                float p2 = acc[mt][nt][2], q2 = __shfl_xor_sync(0xffffffffu, p2, 4);
                float p3 = acc[mt][nt][3], q3 = __shfl_xor_sync(0xffffffffu, p3, 4);
                if (!(g & 1)) {
                    size_t w0 = (size_t)(col0g + cc)     * (SEQ / 2);
                    size_t w1 = (size_t)(col0g + cc + 1) * (SEQ / 2);
                    int rw0 = (row0g + r0) >> 1;
                    int rw1 = (row0g + r0 + 8) >> 1;
                    Cth[w0 + rw0] = pack2h(p0, q0);
                    Cth[w1 + rw0] = pack2h(p1, q1);
                    Cth[w0 + rw1] = pack2h(p2, q2);
                    Cth[w1 + rw1] = pack2h(p3, q3);
                }
            } else {
                *(float2*)(Cblk + (size_t)r0 * ldc + cc)       = make_float2(acc[mt][nt][0], acc[mt][nt][1]);
                *(float2*)(Cblk + (size_t)(r0 + 8) * ldc + cc) = make_float2(acc[mt][nt][2], acc[mt][nt][3]);
            }
        }
    }
}

// Fused QKV: grid (24, 16), 128 threads, all full K=4096.
__global__ __launch_bounds__(128, 2) void qkv_mma(
    const uint32_t* __restrict__ xmu,
    const uint32_t* __restrict__ wqc, const uint32_t* __restrict__ wkc,
    const uint32_t* __restrict__ wvc,
    uint32_t* __restrict__ pqt, uint32_t* __restrict__ pkt,
    uint32_t* __restrict__ pvt,
    const float* __restrict__ qw, const float* __restrict__ kw,
    const float2* __restrict__ rope)
{
    extern __shared__ uint32_t smem[];
    const int xb = blockIdx.x;
    const int row0 = blockIdx.y * 128;
    const uint32_t* A = xmu + (size_t)row0 * HID;

    if (xb < 4) {
        const int ccol = xb * 128;
        gemm_core_async<1>(A, wvc + (size_t)ccol * HID,
                           nullptr, 0, pvt, row0, ccol, 0, nullptr, nullptr,
                           2 * HID, HID, HID, smem);
    } else if (xb < 20) {
        const int head = xb - 4;
        gemm_core_async<2>(A, wqc + (size_t)(head * 128) * HID,
                           nullptr, 0, pqt + head * (HD / 2), row0, 0, QD / 2,
                           qw, rope, 2 * HID, HID, HID, smem);
    } else {
        const int head = xb - 20;
        gemm_core_async<2>(A, wkc + (size_t)(head * 128) * HID,
                           nullptr, 0, pkt + head * (HD / 2), row0, 0, KVD / 2,
                           kw, rope, 2 * HID, HID, HID, smem);
    }
}

// Output projection: grid = (16, 16), 128 threads
__global__ __launch_bounds__(128, 2) void oproj_mma(
    const uint32_t* __restrict__ A, const uint32_t* __restrict__ B, float* __restrict__ C)
{
    extern __shared__ uint32_t smem[];
    const int row0 = blockIdx.y * 128;
    const int ccol = blockIdx.x * 128;
    gemm_core_async<0>(A + (size_t)row0 * (QD / 2), B + (size_t)ccol * (QD / 2),
                       C + (size_t)row0 * QD + ccol, QD,
                       nullptr, 0, 0, 0, nullptr, nullptr,
                       QD, QD / 2, QD / 2, smem);
}

// ---------------------------------------------------------------------------
// fp16 causal flash attention. Q-tile 64 rows, 4 warps (128 thr), 2 CTAs/SM.
// grid = (SEQ/64, NH), reversed x (heavy first). P in registers, h2 exp.
// SMEM words: KV buf0 [K 64x64w | V 128x32w] @0 (8192), buf1 @8192,
//             sQ [64][68] @16384 (4352). Total 20736 words = 82944 B.
// ---------------------------------------------------------------------------
#define ATTN_SMEM_WORDS 20736

__global__ __launch_bounds__(128, 2) void attn_mma(
    const uint32_t* __restrict__ qt, const uint32_t* __restrict__ kt,
    const uint32_t* __restrict__ vt, uint32_t* __restrict__ o)
{
    extern __shared__ uint32_t sw[];
    uint32_t* sQ = sw + 16384;    // [64][68]
    const uint32_t sbyte = smem_u32(sw);

    const int qt_i = gridDim.x - 1 - blockIdx.x;   // heavy tiles first
    const int h = blockIdx.y;
    const int kvh = h >> 2;
    const int qrow0 = qt_i * 64;
    const int tid = threadIdx.x;
    const int w = tid >> 5, lane = tid & 31;
    const int gg = lane >> 2, t = lane & 3;
    const int m0 = w * 16;
    const int jmax = qt_i + 1;
    const int rmax = qrow0 + m0 + 15;

    auto issueKV = [&](int b, int jt) {
        const uint32_t kb0 = sbyte + (uint32_t)(b ? 8192 : 0) * 4u;
        const uint32_t vb0 = kb0 + 4096u * 4u;
#pragma unroll
        for (int i = 0; i < 8; ++i) {      // K: 64 rows x 16 chunks16
            int id = tid + i * 128;
            int r = id >> 4, c = id & 15;
            int cs = (c & 8) | ((c & 7) ^ (r & 7));
            CP_ASYNC_CG(kb0 + (uint32_t)(r * 64 + cs * 4) * 4u,
                        kt + (size_t)(jt * 64 + r) * (KVD / 2) + kvh * (HD / 2) + c * 4);
        }
#pragma unroll
        for (int i = 0; i < 8; ++i) {      // V: 128 rows x 8 chunks16
            int id = tid + i * 128;
            int r = id >> 3, c = id & 7;
            int cs = c ^ (r & 7);
            CP_ASYNC_CG(vb0 + (uint32_t)(r * 32 + cs * 4) * 4u,
                        vt + (size_t)(kvh * HD + r) * (SEQ / 2) + jt * 32 + c * 4);
        }
    };

    issueKV(0, 0); CP_COMMIT();

    // ---- stage Q (64 rows x 16 uint4) ----
#pragma unroll
    for (int i = 0; i < 8; ++i) {
        int id = tid + i * 128;
        int r = id >> 4, w4 = (id & 15) << 2;
        uint4 v = *(const uint4*)(qt + (size_t)(qrow0 + r) * (QD / 2) + h * (HD / 2) + w4);
        sQ[r * 68 + w4 + 0] = v.x;
        sQ[r * 68 + w4 + 1] = v.y;
        sQ[r * 68 + w4 + 2] = v.z;
        sQ[r * 68 + w4 + 3] = v.w;
    }
    __syncthreads();

    uint32_t qf[8][4];
#pragma unroll
    for (int ks = 0; ks < 8; ++ks) {
        qf[ks][0] = sQ[(m0 + gg) * 68 + ks * 8 + t];
        qf[ks][1] = sQ[(m0 + gg + 8) * 68 + ks * 8 + t];
        qf[ks][2] = sQ[(m0 + gg) * 68 + ks * 8 + 4 + t];
        qf[ks][3] = sQ[(m0 + gg + 8) * 68 + ks * 8 + 4 + t];
    }

    float oacc[16][4];
#pragma unroll
    for (int i = 0; i < 16; ++i)
#pragma unroll
        for (int j = 0; j < 4; ++j) oacc[i][j] = 0.0f;
    float mrow0 = -1e30f, mrow1 = -1e30f, lrow0 = 0.0f, lrow1 = 0.0f;

    const float scale = 0.08838834764831845f;
    const float L2E = 1.4426950408889634f;

    for (int jt = 0; jt < jmax; ++jt) {
        CP_WAIT0();
        __syncthreads();
        if (jt + 1 < jmax) { issueKV((jt + 1) & 1, jt + 1); CP_COMMIT(); }

        const uint32_t* sK = sw + ((jt & 1) ? 8192 : 0);
        const uint32_t* sV = sK + 4096;

        const bool edge = (jt == qt_i);

        float sacc[8][4];
#pragma unroll
        for (int i = 0; i < 8; ++i)
#pragma unroll
            for (int j = 0; j < 4; ++j) sacc[i][j] = 0.0f;

        if (!edge) {
#pragma unroll
            for (int ks = 0; ks < 8; ++ks) {
                const int c0 = (((2 * ks) & 8) | (((2 * ks) & 7) ^ gg)) * 4 + t;
                const int c1 = (((2 * ks + 1) & 8) | (((2 * ks + 1) & 7) ^ gg)) * 4 + t;
#pragma unroll
                for (int nt = 0; nt < 8; ++nt) {
                    int nr = nt * 8 + gg;
                    mma_f16(sacc[nt], qf[ks], sK[nr * 64 + c0], sK[nr * 64 + c1]);
                }
            }
        } else {
#pragma unroll
            for (int nt = 0; nt < 8; ++nt) {
                if (jt * 64 + nt * 8 <= rmax) {
                    const int nr = nt * 8 + gg;
#pragma unroll
                    for (int ks = 0; ks < 8; ++ks) {
                        const int c0 = (((2 * ks) & 8) | (((2 * ks) & 7) ^ gg)) * 4 + t;
                        const int c1 = (((2 * ks + 1) & 8) | (((2 * ks + 1) & 7) ^ gg)) * 4 + t;
                        mma_f16(sacc[nt], qf[ks], sK[nr * 64 + c0], sK[nr * 64 + c1]);
                    }
                }
            }
        }

        const int r0 = qrow0 + m0 + gg;
        const int r1 = r0 + 8;
        float rm0 = -1e30f, rm1 = -1e30f;
#pragma unroll
        for (int nt = 0; nt < 8; ++nt) {
            float c0 = sacc[nt][0] * scale, c1 = sacc[nt][1] * scale;
            float c2 = sacc[nt][2] * scale, c3 = sacc[nt][3] * scale;
            if (edge) {
                int colb = jt * 64 + nt * 8 + 2 * t;
                if (colb     > r0) c0 = -1e30f;
                if (colb + 1 > r0) c1 = -1e30f;
                if (colb     > r1) c2 = -1e30f;
                if (colb + 1 > r1) c3 = -1e30f;
            }
            sacc[nt][0] = c0; sacc[nt][1] = c1; sacc[nt][2] = c2; sacc[nt][3] = c3;
            rm0 = fmaxf(rm0, fmaxf(c0, c1));
            rm1 = fmaxf(rm1, fmaxf(c2, c3));
        }
        rm0 = fmaxf(rm0, __shfl_xor_sync(0xffffffffu, rm0, 1));
        rm0 = fmaxf(rm0, __shfl_xor_sync(0xffffffffu, rm0, 2));
        rm1 = fmaxf(rm1, __shfl_xor_sync(0xffffffffu, rm1, 1));
        rm1 = fmaxf(rm1, __shfl_xor_sync(0xffffffffu, rm1, 2));

        float mn0 = fmaxf(mrow0, rm0), mn1 = fmaxf(mrow1, rm1);
        float al0 = __expf(mrow0 - mn0), al1 = __expf(mrow1 - mn1);
        mrow0 = mn0; mrow1 = mn1;

        const float mn0L = mn0 * L2E, mn1L = mn1 * L2E;
        uint32_t pu[8][2];
        float rs0 = 0.0f, rs1 = 0.0f;
#pragma unroll
        for (int nt = 0; nt < 8; ++nt) {
            uint32_t a0 = pack2h(fmaf(sacc[nt][0], L2E, -mn0L),
                                 fmaf(sacc[nt][1], L2E, -mn0L));
            uint32_t a1 = pack2h(fmaf(sacc[nt][2], L2E, -mn1L),
                                 fmaf(sacc[nt][3], L2E, -mn1L));
            pu[nt][0] = ex2_h2(a0);
            pu[nt][1] = ex2_h2(a1);
            float2 f0 = __half22float2(*reinterpret_cast<__half2*>(&pu[nt][0]));
            float2 f1 = __half22float2(*reinterpret_cast<__half2*>(&pu[nt][1]));
            rs0 += f0.x + f0.y;
            rs1 += f1.x + f1.y;
        }
        rs0 += __shfl_xor_sync(0xffffffffu, rs0, 1);
        rs0 += __shfl_xor_sync(0xffffffffu, rs0, 2);
        rs1 += __shfl_xor_sync(0xffffffffu, rs1, 1);
        rs1 += __shfl_xor_sync(0xffffffffu, rs1, 2);
        lrow0 = lrow0 * al0 + rs0;
        lrow1 = lrow1 * al1 + rs1;

#pragma unroll
        for (int nt = 0; nt < 16; ++nt) {
            oacc[nt][0] *= al0; oacc[nt][1] *= al0;
            oacc[nt][2] *= al1; oacc[nt][3] *= al1;
        }

#pragma unroll
        for (int ks = 0; ks < 4; ++ks) {
            if (edge && (jt * 64 + ks * 16 > rmax)) continue;
            uint32_t a[4] = {pu[2 * ks][0], pu[2 * ks][1],
                             pu[2 * ks + 1][0], pu[2 * ks + 1][1]};
            const int c0 = (((2 * ks) ^ gg) & 7) * 4 + t;
            const int c1 = (((2 * ks + 1) ^ gg) & 7) * 4 + t;
#pragma unroll
            for (int nt = 0; nt < 16; ++nt) {
                int nr = nt * 8 + gg;
                mma_f16(oacc[nt], a, sV[nr * 32 + c0], sV[nr * 32 + c1]);
            }
        }
    }

    const float inv0 = 1.0f / lrow0, inv1 = 1.0f / lrow1;
    const int r0 = qrow0 + m0 + gg;
#pragma unroll
    for (int nt = 0; nt < 16; ++nt) {
        int wi = h * (HD / 2) + nt * 4 + t;
        o[(size_t)r0 * (QD / 2) + wi]       = pack2h(oacc[nt][0] * inv0, oacc[nt][1] * inv0);
        o[(size_t)(r0 + 8) * (QD / 2) + wi] = pack2h(oacc[nt][2] * inv1, oacc[nt][3] * inv1);
    }
}

// ---------------------------------------------------------------------------
extern "C" void kernel_launch(void* const* d_in, const int* in_sizes, int n_in,
                              void* d_out, int out_size)
{
    (void)in_sizes; (void)n_in; (void)out_size;
    const float* x   = (const float*)d_in[0];
    const float* mu  = (const float*)d_in[1];
    const float* wq  = (const float*)d_in[2];
    const float* wk  = (const float*)d_in[3];
    const float* wv  = (const float*)d_in[4];
    const float* wo  = (const float*)d_in[5];
    const float* wmq = (const float*)d_in[6];
    const float* wmk = (const float*)d_in[7];
    const float* wmv = (const float*)d_in[8];
    const float* qw  = (const float*)d_in[9];
    const float* kw  = (const float*)d_in[10];
    float* out = (float*)d_out;

    uint32_t *pqt, *pkt, *pvt, *po;
    uint32_t *pxmu, *pwqc, *pwkc, *pwvc, *pwot;
    float2 *prope;
    cudaGetSymbolAddress((void**)&pqt, g_qt);
    cudaGetSymbolAddress((void**)&pkt, g_kt);
    cudaGetSymbolAddress((void**)&pvt, g_vt);
    cudaGetSymbolAddress((void**)&po, g_o);
    cudaGetSymbolAddress((void**)&pxmu, g_xmu);
    cudaGetSymbolAddress((void**)&pwqc, g_wqc);
    cudaGetSymbolAddress((void**)&pwkc, g_wkc);
    cudaGetSymbolAddress((void**)&pwvc, g_wvc);
    cudaGetSymbolAddress((void**)&pwot, g_wot);
    cudaGetSymbolAddress((void**)&prope, g_rope);

    // ---- fused prepass ----
    rope_table<<<SEQ, 64>>>(prope);
    cvt_all<<<12288, 256>>>(pxmu, pwqc, pwkc, pwvc, pwot,
                            x, mu, wq, wmq, wk, wmk, wv, wmv, wo);

    const int gemm_smem = 3 * STAGE_WORDS * 4;  // 98304 bytes
    cudaFuncSetAttribute(qkv_mma,   cudaFuncAttributeMaxDynamicSharedMemorySize, gemm_smem);
    cudaFuncSetAttribute(oproj_mma, cudaFuncAttributeMaxDynamicSharedMemorySize, gemm_smem);

    // Fused QKV + RMSNorm + RoPE (Q/K) + V transpose, all fp16 outputs
    qkv_mma<<<dim3(24, 16), 128, gemm_smem>>>(pxmu, pwqc, pwkc, pwvc,
                                              pqt, pkt, pvt, qw, kw, prope);

    // causal GQA attention (fp16 mma, 64-row Q tiles, 2 CTAs/SM)
    const int attn_smem = ATTN_SMEM_WORDS * 4;  // 82944 bytes
    cudaFuncSetAttribute(attn_mma, cudaFuncAttributeMaxDynamicSharedMemorySize, attn_smem);
    attn_mma<<<dim3(SEQ / 64, NH), 128, attn_smem>>>(pqt, pkt, pvt, po);

    // output projection (fp16 mma)
    oproj_mma<<<dim3(16, 16), 128, gemm_smem>>>(po, pwot, out);
}